// round 13
// baseline (speedup 1.0000x reference)
#include <cuda_runtime.h>
#include <cuda_fp16.h>
#include <math.h>
#include <stdint.h>

// ---------------- problem constants ----------------
#define BATCH   4
#define TLEN    2048
#define PW      256
#define P1      4
#define NPATCH  512          // TLEN/P1
#define NROWS   2048         // BATCH*NPATCH
#define DIMM    1024
#define HEADS   16
#define DH      64
#define INNERD  1024         // HEADS*DH
#define QKVD    3072
#define MLPD    4096
#define DEPTH   12
#define NCLS    41           // NCLS+1
#define RELN    399          // 2*MAXREL-1

// arch-feature gate: tcgen05 only exists on sm_100a/sm_103a-class targets
#if defined(__CUDA_ARCH_FEAT_SM103_ALL) || defined(__CUDA_ARCH_FEAT_SM100_ALL) || defined(__CUDA_ARCH_FEAT_SM101_ALL)
#define HAS_TC 1
#else
#define HAS_TC 0
#endif

// ---------------- scratch (device globals; allocation-free) ----------------
__device__ float g_x  [(size_t)NROWS*DIMM];     // fp32 residual stream
__device__ float g_qkv[(size_t)NROWS*QKVD];     // fp32 qkv + generic fp32 temp

// activation hi/lo fp16 planes
__device__ __half g_lnh[(size_t)NROWS*DIMM];
__device__ __half g_lnl[(size_t)NROWS*DIMM];
__device__ __half g_aoh[(size_t)NROWS*DIMM];
__device__ __half g_aol[(size_t)NROWS*DIMM];
__device__ __half g_fh [(size_t)NROWS*MLPD];
__device__ __half g_fl [(size_t)NROWS*MLPD];

// weight hi/lo fp16 planes
__device__ __half g_wph[(size_t)DIMM*DIMM];
__device__ __half g_wpl[(size_t)DIMM*DIMM];
__device__ __half g_wqh[(size_t)DEPTH*QKVD*DIMM];
__device__ __half g_wql[(size_t)DEPTH*QKVD*DIMM];
__device__ __half g_woh[(size_t)DEPTH*DIMM*INNERD];
__device__ __half g_wol[(size_t)DEPTH*DIMM*INNERD];
__device__ __half g_w1h[(size_t)DEPTH*MLPD*DIMM];
__device__ __half g_w1l[(size_t)DEPTH*MLPD*DIMM];
__device__ __half g_w2h[(size_t)DEPTH*DIMM*MLPD];
__device__ __half g_w2l[(size_t)DEPTH*DIMM*MLPD];

// ---------------- generic helpers ----------------
__device__ __forceinline__ void hsplit(float x, __half& h, __half& l) {
    h = __float2half_rn(x);
    l = __float2half_rn(x - __half2float(h));
}

__device__ __forceinline__ float gelu_exact(float x) {
    return 0.5f * x * (1.f + erff(x * 0.70710678118654752f));
}

__device__ __forceinline__ void cp16s(uint32_t s, const void* g) {
    asm volatile("cp.async.cg.shared.global [%0], [%1], 16;\n" :: "r"(s), "l"(g));
}

// packed f32x2 helpers (sm_100+)
__device__ __forceinline__ uint64_t pk2(float lo, float hi) {
    uint64_t d;
    asm("mov.b64 %0, {%1, %2};" : "=l"(d) : "f"(lo), "f"(hi));
    return d;
}
__device__ __forceinline__ void upk2(uint64_t v, float& lo, float& hi) {
    asm("mov.b64 {%0, %1}, %2;" : "=f"(lo), "=f"(hi) : "l"(v));
}
__device__ __forceinline__ uint64_t fma2p(uint64_t a, uint64_t b, uint64_t c) {
    uint64_t d;
    asm("fma.rn.f32x2 %0, %1, %2, %3;" : "=l"(d) : "l"(a), "l"(b), "l"(c));
    return d;
}
__device__ __forceinline__ uint64_t mul2p(uint64_t a, uint64_t b) {
    uint64_t d;
    asm("mul.rn.f32x2 %0, %1, %2;" : "=l"(d) : "l"(a), "l"(b));
    return d;
}
__device__ __forceinline__ void lds2u64(uint32_t a, uint64_t& p0, uint64_t& p1) {
    asm("ld.shared.v2.u64 {%0, %1}, [%2];" : "=l"(p0), "=l"(p1) : "r"(a));
}

// ---------------- arch probe: static smem size differs by feature ----------------
__global__ void probe_kernel(float* out) {
#if HAS_TC
    __shared__ volatile float s[2048];            // 8192 bytes static smem
    s[threadIdx.x] = 1.f;
    __syncthreads();
    if (out) out[0] = s[threadIdx.x ^ 1];
#else
    if (out) out[0] = 0.f;
#endif
}

// ---------------- tcgen05 helpers (guarded) ----------------
__device__ __forceinline__ uint32_t sw128(uint32_t off) {
    return off ^ ((off >> 3) & 0x70);
}

__device__ __forceinline__ uint64_t sdesc(uint32_t saddr) {
    return (2ull << 61) | (1ull << 46) | (64ull << 32) | (1ull << 16)
         | ((uint64_t)(saddr >> 4) & 0x3FFF);
}

__device__ __forceinline__ void mbar_init(uint32_t a, uint32_t cnt) {
    asm volatile("mbarrier.init.shared.b64 [%0], %1;" :: "r"(a), "r"(cnt) : "memory");
}

__device__ __forceinline__ void mbar_wait(uint32_t a, int phase) {
    asm volatile(
        "{\n\t.reg .pred P;\n"
        "W_%=:\n\t"
        "mbarrier.try_wait.parity.shared.b64 P, [%0], %1;\n\t"
        "@P bra D_%=;\n\t"
        "bra W_%=;\n"
        "D_%=:\n\t}"
        :: "r"(a), "r"(phase) : "memory");
}

__device__ __forceinline__ void tc_alloc(uint32_t slot, uint32_t ncols) {
#if HAS_TC
    asm volatile("tcgen05.alloc.cta_group::1.sync.aligned.shared::cta.b32 [%0], %1;"
                 :: "r"(slot), "r"(ncols) : "memory");
    asm volatile("tcgen05.relinquish_alloc_permit.cta_group::1.sync.aligned;");
#endif
}

__device__ __forceinline__ void tc_dealloc(uint32_t tmem, uint32_t ncols) {
#if HAS_TC
    asm volatile("tcgen05.dealloc.cta_group::1.sync.aligned.b32 %0, %1;"
                 :: "r"(tmem), "r"(ncols));
#endif
}

__device__ __forceinline__ void tc_mma_f16_ss(uint32_t d, uint64_t a_desc, uint64_t b_desc,
                                              uint32_t idesc, uint32_t en) {
#if HAS_TC
    asm volatile(
        "{\n\t.reg .pred p;\n\t"
        "setp.ne.u32 p, %5, 0;\n\t"
        "tcgen05.mma.cta_group::1.kind::f16 [%0], %1, %2, %3, {%4, %4, %4, %4}, p;\n\t}"
        :: "r"(d), "l"(a_desc), "l"(b_desc), "r"(idesc), "r"(0u), "r"(en) : "memory");
#endif
}

__device__ __forceinline__ void tc_commit(uint32_t mbar) {
#if HAS_TC
    asm volatile("tcgen05.commit.cta_group::1.mbarrier::arrive::one.shared::cluster.b64 [%0];"
                 :: "r"(mbar) : "memory");
#endif
}

__device__ __forceinline__ void tmem_ld32(uint32_t* r, uint32_t a) {
#if HAS_TC
    asm volatile(
        "tcgen05.ld.sync.aligned.32x32b.x32.b32 "
        "{%0, %1, %2, %3, %4, %5, %6, %7, "
        " %8, %9, %10, %11, %12, %13, %14, %15, "
        " %16, %17, %18, %19, %20, %21, %22, %23, "
        " %24, %25, %26, %27, %28, %29, %30, %31}, [%32];"
        : "=r"(r[0]),  "=r"(r[1]),  "=r"(r[2]),  "=r"(r[3]),
          "=r"(r[4]),  "=r"(r[5]),  "=r"(r[6]),  "=r"(r[7]),
          "=r"(r[8]),  "=r"(r[9]),  "=r"(r[10]), "=r"(r[11]),
          "=r"(r[12]), "=r"(r[13]), "=r"(r[14]), "=r"(r[15]),
          "=r"(r[16]), "=r"(r[17]), "=r"(r[18]), "=r"(r[19]),
          "=r"(r[20]), "=r"(r[21]), "=r"(r[22]), "=r"(r[23]),
          "=r"(r[24]), "=r"(r[25]), "=r"(r[26]), "=r"(r[27]),
          "=r"(r[28]), "=r"(r[29]), "=r"(r[30]), "=r"(r[31])
        : "r"(a));
#else
    #pragma unroll
    for (int i = 0; i < 32; i++) r[i] = 0;
    (void)a;
#endif
}

// ---------------- weight split pre-pass ----------------
__global__ void wsplit_kernel(const float4* __restrict__ in,
                              __half2* __restrict__ oh, __half2* __restrict__ ol, int n4) {
    int i = blockIdx.x * blockDim.x + threadIdx.x;
    if (i < n4) {
        float4 v = in[i];
        __half h0, l0, h1, l1, h2, l2, h3, l3;
        hsplit(v.x, h0, l0); hsplit(v.y, h1, l1);
        hsplit(v.z, h2, l2); hsplit(v.w, h3, l3);
        oh[2 * i]     = __halves2half2(h0, h1);
        oh[2 * i + 1] = __halves2half2(h2, h3);
        ol[2 * i]     = __halves2half2(l0, l1);
        ol[2 * i + 1] = __halves2half2(l2, l3);
    }
}

// ---------------- 1) gaussian conv + patchify + LN1 (planes out) ----------------
__device__ __forceinline__ float blockSum256(float v) {
    __shared__ float red[8];
    int lane = threadIdx.x & 31, w = threadIdx.x >> 5;
    __syncthreads();
    #pragma unroll
    for (int o = 16; o; o >>= 1) v += __shfl_down_sync(0xffffffffu, v, o);
    if (!lane) red[w] = v;
    __syncthreads();
    if (w == 0) {
        float r = (lane < 8) ? red[lane] : 0.f;
        #pragma unroll
        for (int o = 4; o; o >>= 1) r += __shfl_down_sync(0xffffffffu, r, o);
        if (!lane) red[0] = r;
    }
    __syncthreads();
    return red[0];
}

__global__ void patch_kernel(const float* __restrict__ in,
                             const float* __restrict__ lg,
                             const float* __restrict__ lb,
                             __half* __restrict__ oh, __half* __restrict__ ol) {
    __shared__ float gk[20];
    if (threadIdx.x == 0) {
        float tmp[20], s = 0.f;
        #pragma unroll
        for (int i = 0; i < 20; i++) {
            float z = ((float)i - 9.5f) * 0.5f;
            tmp[i] = expf(-0.5f * z * z);
            s += tmp[i];
        }
        #pragma unroll
        for (int i = 0; i < 20; i++) gk[i] = tmp[i] / s;
    }
    __syncthreads();

    int row = blockIdx.x;
    int b = row >> 9, n = row & 511;
    int f = threadIdx.x;
    const float* ib = in + (size_t)b * TLEN * PW + f;

    float vals[P1];
    #pragma unroll
    for (int p = 0; p < P1; p++) {
        int t = n * P1 + p;
        float acc = 0.f;
        #pragma unroll
        for (int k = 0; k < 20; k++) {
            int tt = t - 9 + k;
            if (tt >= 0 && tt < TLEN) acc += ib[(size_t)tt * PW] * gk[k];
        }
        vals[p] = acc;
    }
    float s = vals[0] + vals[1] + vals[2] + vals[3];
    float mean = blockSum256(s) * (1.f / 1024.f);
    float sq = 0.f;
    #pragma unroll
    for (int p = 0; p < P1; p++) { float d = vals[p] - mean; sq += d * d; }
    float var = blockSum256(sq) * (1.f / 1024.f);
    float inv = rsqrtf(var + 1e-5f);
    #pragma unroll
    for (int p = 0; p < P1; p++) {
        int e = p * PW + f;
        float o = (vals[p] - mean) * inv * lg[e] + lb[e];
        __half h, l;
        hsplit(o, h, l);
        oh[(size_t)row * DIMM + e] = h;
        ol[(size_t)row * DIMM + e] = l;
    }
}

// ---------------- 2) LayerNorm over D=1024, warp-per-row (8 rows/CTA) ----------------
template <int PACK>
__global__ __launch_bounds__(256)
void ln_kernel(const float* __restrict__ in, void* __restrict__ o1,
               void* __restrict__ o2,
               const float* __restrict__ g, const float* __restrict__ b) {
    int wid = threadIdx.x >> 5, lane = threadIdx.x & 31;
    int row = blockIdx.x * 8 + wid;
    const float* x = in + (size_t)row * DIMM;

    float4 v[8];
    float s = 0.f;
    #pragma unroll
    for (int i = 0; i < 8; i++) {
        v[i] = *(const float4*)(x + lane * 4 + i * 128);
        s += v[i].x + v[i].y + v[i].z + v[i].w;
    }
    #pragma unroll
    for (int o = 16; o; o >>= 1) s += __shfl_xor_sync(0xffffffffu, s, o);
    float mean = s * (1.f / 1024.f);

    float sq = 0.f;
    #pragma unroll
    for (int i = 0; i < 8; i++) {
        v[i].x -= mean; v[i].y -= mean; v[i].z -= mean; v[i].w -= mean;
        sq += v[i].x * v[i].x + v[i].y * v[i].y + v[i].z * v[i].z + v[i].w * v[i].w;
    }
    #pragma unroll
    for (int o = 16; o; o >>= 1) sq += __shfl_xor_sync(0xffffffffu, sq, o);
    float inv = rsqrtf(sq * (1.f / 1024.f) + 1e-5f);

    #pragma unroll
    for (int i = 0; i < 8; i++) {
        int c = lane * 4 + i * 128;
        float4 gv = *(const float4*)(g + c), bv = *(const float4*)(b + c);
        float ox = v[i].x * inv * gv.x + bv.x;
        float oy = v[i].y * inv * gv.y + bv.y;
        float oz = v[i].z * inv * gv.z + bv.z;
        float ow = v[i].w * inv * gv.w + bv.w;
        if (PACK) {
            __half h0, l0, h1, l1, h2, l2, h3, l3;
            hsplit(ox, h0, l0); hsplit(oy, h1, l1);
            hsplit(oz, h2, l2); hsplit(ow, h3, l3);
            size_t idx = ((size_t)row * DIMM + c) >> 1;
            ((__half2*)o1)[idx]     = __halves2half2(h0, h1);
            ((__half2*)o1)[idx + 1] = __halves2half2(h2, h3);
            ((__half2*)o2)[idx]     = __halves2half2(l0, l1);
            ((__half2*)o2)[idx + 1] = __halves2half2(l2, l3);
        } else {
            *(float4*)((float*)o1 + (size_t)row * DIMM + c) = make_float4(ox, oy, oz, ow);
        }
    }
}

// ---------------- 3a) tcgen05 split-FP16 GEMM ----------------
// NT=256: ST=2, lowest L2 traffic (wide GEMMs). NT=128: ST=3, bubble-free (narrow GEMMs).
// Generic pipeline: before filling chunk c+2, wait on commit of chunk c+2-ST.
#define ATILE 16384            // 128 rows * 128 B
template <int NT, int MODE>
__global__ __launch_bounds__(128)
void tgemm_tc(const __half* __restrict__ Ah, const __half* __restrict__ Al,
              const __half* __restrict__ Bh, const __half* __restrict__ Bl,
              const float* __restrict__ bias, const float* __restrict__ R,
              float* __restrict__ Cf, __half* __restrict__ Ch, __half* __restrict__ Cl,
              int M, int N, int K) {
#if HAS_TC
    constexpr int ST    = (NT == 256) ? 2 : 3;
    constexpr int BTILE = NT * 128;
    constexpr int BUF   = 2 * ATILE + 2 * BTILE;
    constexpr uint32_t IDESC = (1u << 4) | ((NT / 8) << 17) | (8u << 24);

    extern __shared__ __align__(1024) uint8_t smraw[];
    uint32_t sbase = (uint32_t)__cvta_generic_to_shared(smraw);
    uint32_t s0 = (sbase + 1023) & ~1023u;
    uint32_t tmem_slot = s0;
    uint32_t mb0 = s0 + 8;                          // mb[s] = mb0 + 8*s
    uint32_t tiles = s0 + 1024;

    int t = threadIdx.x, wid = t >> 5, lid = t & 31;
    int m0 = blockIdx.y * 128, n0 = blockIdx.x * NT;

    if (wid == 0) tc_alloc(tmem_slot, 256);
    if (t == 0) {
        #pragma unroll
        for (int s = 0; s < ST; s++) mbar_init(mb0 + 8 * s, 1);
    }
    __syncthreads();
    uint32_t tmem;
    asm volatile("ld.shared.b32 %0, [%1];" : "=r"(tmem) : "r"(tmem_slot));

    int T = K >> 6;                                 // K/64 chunks
    int ph[3] = { 0, 0, 0 };

    auto fill = [&](int c) {
        int s = c % ST;
        int k0 = c * 64;
        uint32_t bb = tiles + s * BUF;
        #pragma unroll 4
        for (int idx = t; idx < 128 * 8; idx += 128) {
            int row = idx >> 3, u = idx & 7;
            uint32_t soff = sw128(row * 128 + u * 16);
            size_t goff = (size_t)(m0 + row) * K + k0 + u * 8;
            cp16s(bb + soff, Ah + goff);
            cp16s(bb + ATILE + soff, Al + goff);
        }
        #pragma unroll 4
        for (int idx = t; idx < NT * 8; idx += 128) {
            int row = idx >> 3, u = idx & 7;
            uint32_t soff = sw128(row * 128 + u * 16);
            size_t goff = (size_t)(n0 + row) * K + k0 + u * 8;
            cp16s(bb + 2 * ATILE + soff, Bh + goff);
            cp16s(bb + 2 * ATILE + BTILE + soff, Bl + goff);
        }
        asm volatile("cp.async.commit_group;\n");
    };

    fill(0);
    if (T > 1) fill(1);

    for (int c = 0; c < T; c++) {
        int s = c % ST;
        if (c + 1 < T) asm volatile("cp.async.wait_group 1;\n");
        else           asm volatile("cp.async.wait_group 0;\n");
        __syncthreads();

        if (t == 0) {
            asm volatile("fence.proxy.async.shared::cta;" ::: "memory");
            uint32_t bb = tiles + s * BUF;
            uint64_t dAh = sdesc(bb);
            uint64_t dAl = sdesc(bb + ATILE);
            uint64_t dBh = sdesc(bb + 2 * ATILE);
            uint64_t dBl = sdesc(bb + 2 * ATILE + BTILE);
            #pragma unroll
            for (int k = 0; k < 4; k++) {
                uint32_t en0 = (c == 0 && k == 0) ? 0u : 1u;
                tc_mma_f16_ss(tmem, dAl + k * 2, dBh + k * 2, IDESC, en0);
                tc_mma_f16_ss(tmem, dAh + k * 2, dBl + k * 2, IDESC, 1u);
                tc_mma_f16_ss(tmem, dAh + k * 2, dBh + k * 2, IDESC, 1u);
            }
            tc_commit(mb0 + 8 * s);
        }

        if (c + 2 < T) {
            int w = c + 2 - ST;                     // chunk whose buffer c+2 reuses
            if (w >= 0) {
                int ws = w % ST;
                mbar_wait(mb0 + 8 * ws, ph[ws]);
                ph[ws] ^= 1;
            }
            fill(c + 2);
        }
    }

    // drain: wait the remaining commits (chunk T-1's commit implies all MMAs done)
    {
        int start = T - ST;
        if (start < 0) start = 0;
        // chunks start..T-1 not yet waited in-loop when T>=ST; for small T all T chunks
        int first = (T > ST) ? (T - ST) : 0;
        for (int j = first; j < T; j++) {
            int js = j % ST;
            mbar_wait(mb0 + 8 * js, ph[js]);
            ph[js] ^= 1;
        }
    }
    asm volatile("tcgen05.fence::after_thread_sync;" ::: "memory");

    // epilogue: each warp reads its 32-lane subpartition
    int row = m0 + wid * 32 + lid;
    #pragma unroll 1
    for (int cb = 0; cb < NT / 32; cb++) {
        uint32_t r[32];
        tmem_ld32(r, tmem + cb * 32);
        asm volatile("tcgen05.wait::ld.sync.aligned;" ::: "memory");
        int nb = n0 + cb * 32;
        float v[32];
        #pragma unroll
        for (int c = 0; c < 32; c++)
            v[c] = __uint_as_float(r[c]) + (bias ? bias[nb + c] : 0.f);
        if (MODE == 1) {
            #pragma unroll
            for (int c4 = 0; c4 < 32; c4 += 4) {
                float4 rv = *(const float4*)(R + (size_t)row * N + nb + c4);
                v[c4] += rv.x; v[c4 + 1] += rv.y; v[c4 + 2] += rv.z; v[c4 + 3] += rv.w;
            }
        }
        if (MODE <= 1) {
            #pragma unroll
            for (int c4 = 0; c4 < 32; c4 += 4)
                *(float4*)(Cf + (size_t)row * N + nb + c4) =
                    make_float4(v[c4], v[c4 + 1], v[c4 + 2], v[c4 + 3]);
        } else {
            __align__(16) __half hh[32], hl[32];
            #pragma unroll
            for (int c = 0; c < 32; c++) {
                float gx = gelu_exact(v[c]);
                hsplit(gx, hh[c], hl[c]);
            }
            #pragma unroll
            for (int q = 0; q < 4; q++) {
                *(uint4*)(Ch + (size_t)row * N + nb + q * 8) = *(uint4*)&hh[q * 8];
                *(uint4*)(Cl + (size_t)row * N + nb + q * 8) = *(uint4*)&hl[q * 8];
            }
        }
    }

    __syncthreads();
    if (wid == 0) tc_dealloc(tmem, 256);
#endif
}

// ---------------- 3b) legacy mma.sync split-FP16 GEMM (fallback) ----------------
__device__ __forceinline__ void mma_f16(float* c, const uint32_t* a, const uint32_t* b) {
    asm volatile(
        "mma.sync.aligned.m16n8k16.row.col.f32.f16.f16.f32 "
        "{%0,%1,%2,%3}, {%4,%5,%6,%7}, {%8,%9}, {%0,%1,%2,%3};"
        : "+f"(c[0]), "+f"(c[1]), "+f"(c[2]), "+f"(c[3])
        : "r"(a[0]), "r"(a[1]), "r"(a[2]), "r"(a[3]), "r"(b[0]), "r"(b[1]));
}

#define LG_PLANE 5120              // halves per plane tile (128 rows * 40)
#define LG_STAGE (4 * LG_PLANE)    // halves per stage
#define LG_SMEM  (2 * LG_STAGE * 2)  // 81920 bytes

template <int GELU, int RES, int PACK>
__global__ __launch_bounds__(256)
void tgemm_lg(const __half* __restrict__ Ah, const __half* __restrict__ Al,
              const __half* __restrict__ Bh, const __half* __restrict__ Bl,
              const float* __restrict__ bias, const float* __restrict__ R,
              float* __restrict__ Cf, __half* __restrict__ Ch, __half* __restrict__ Cl,
              int M, int N, int K) {
    extern __shared__ __half smh[];
    uint32_t sbase_u = (uint32_t)__cvta_generic_to_shared(smh);
    int m0 = blockIdx.y * 128, n0 = blockIdx.x * 128;
    int t = threadIdx.x, lane = t & 31, wid = t >> 5;
    int g = lane >> 2, tig = lane & 3;
    int warp_m = wid & 1, warp_n = wid >> 1;

    float acc[4][4][4];
    #pragma unroll
    for (int i = 0; i < 4; i++)
        #pragma unroll
        for (int j = 0; j < 4; j++)
            #pragma unroll
            for (int r = 0; r < 4; r++) acc[i][j][r] = 0.f;

    int T = K >> 5;
    const __half* gsrc[4] = { Ah, Al, Bh, Bl };

    auto fill = [&](int tt) {
        int st = tt & 1;
        int k0 = tt * 32;
        #pragma unroll
        for (int pl = 0; pl < 4; pl++) {
            int rbase = (pl < 2) ? m0 : n0;
            uint32_t dst = sbase_u + (uint32_t)(st * LG_STAGE + pl * LG_PLANE) * 2;
            const __half* src = gsrc[pl] + (size_t)rbase * K + k0;
            #pragma unroll
            for (int q = 0; q < 2; q++) {
                int cidx = t + 256 * q;
                int row = cidx >> 2, seg = cidx & 3;
                cp16s(dst + (uint32_t)(row * 40 + seg * 8) * 2,
                      src + (size_t)row * K + seg * 8);
            }
        }
        asm volatile("cp.async.commit_group;\n");
    };

    fill(0);
    for (int tt = 0; tt < T; tt++) {
        if (tt + 1 < T) { fill(tt + 1); asm volatile("cp.async.wait_group 1;\n"); }
        else            { asm volatile("cp.async.wait_group 0;\n"); }
        __syncthreads();

        const uint32_t* S   = (const uint32_t*)smh + (tt & 1) * (LG_STAGE / 2);
        const uint32_t* SAh = S;
        const uint32_t* SAl = S + LG_PLANE / 2;
        const uint32_t* SWh = S + LG_PLANE;
        const uint32_t* SWl = S + 3 * (LG_PLANE / 2);
        int am = warp_m * 64, bn = warp_n * 32;

        #pragma unroll
        for (int ks = 0; ks < 2; ks++) {
            int kw = ks * 8 + tig;
            uint32_t ah[4][4], al[4][4], bh[4][2], bl[4][2];
            #pragma unroll
            for (int i = 0; i < 4; i++) {
                int r = am + i * 16 + g;
                ah[i][0] = SAh[r * 20 + kw];       ah[i][1] = SAh[(r + 8) * 20 + kw];
                ah[i][2] = SAh[r * 20 + kw + 4];   ah[i][3] = SAh[(r + 8) * 20 + kw + 4];
                al[i][0] = SAl[r * 20 + kw];       al[i][1] = SAl[(r + 8) * 20 + kw];
                al[i][2] = SAl[r * 20 + kw + 4];   al[i][3] = SAl[(r + 8) * 20 + kw + 4];
            }
            #pragma unroll
            for (int j = 0; j < 4; j++) {
                int c = bn + j * 8 + g;
                bh[j][0] = SWh[c * 20 + kw];  bh[j][1] = SWh[c * 20 + kw + 4];
                bl[j][0] = SWl[c * 20 + kw];  bl[j][1] = SWl[c * 20 + kw + 4];
            }
            #pragma unroll
            for (int i = 0; i < 4; i++)
                #pragma unroll
                for (int j = 0; j < 4; j++) {
                    mma_f16(acc[i][j], al[i], bh[j]);
                    mma_f16(acc[i][j], ah[i], bl[j]);
                    mma_f16(acc[i][j], ah[i], bh[j]);
                }
        }
        __syncthreads();
    }

    int m_base = m0 + warp_m * 64;
    int n_base = n0 + warp_n * 32;
    #pragma unroll
    for (int i = 0; i < 4; i++) {
        int r0 = m_base + i * 16 + g;
        int r1 = r0 + 8;
        #pragma unroll
        for (int j = 0; j < 4; j++) {
            int cc = n_base + j * 8 + tig * 2;
            float b0 = bias ? bias[cc] : 0.f;
            float b1 = bias ? bias[cc + 1] : 0.f;
            float v00 = acc[i][j][0] + b0, v01 = acc[i][j][1] + b1;
            float v10 = acc[i][j][2] + b0, v11 = acc[i][j][3] + b1;
            if (GELU) {
                v00 = gelu_exact(v00); v01 = gelu_exact(v01);
                v10 = gelu_exact(v10); v11 = gelu_exact(v11);
            }
            if (RES) {
                const float2 rv0 = *(const float2*)(R + (size_t)r0 * N + cc);
                const float2 rv1 = *(const float2*)(R + (size_t)r1 * N + cc);
                v00 += rv0.x; v01 += rv0.y; v10 += rv1.x; v11 += rv1.y;
            }
            if (PACK) {
                __half h00, l00, h01, l01, h10, l10, h11, l11;
                hsplit(v00, h00, l00); hsplit(v01, h01, l01);
                hsplit(v10, h10, l10); hsplit(v11, h11, l11);
                *(__half2*)(Ch + (size_t)r0 * N + cc) = __halves2half2(h00, h01);
                *(__half2*)(Ch + (size_t)r1 * N + cc) = __halves2half2(h10, h11);
                *(__half2*)(Cl + (size_t)r0 * N + cc) = __halves2half2(l00, l01);
                *(__half2*)(Cl + (size_t)r1 * N + cc) = __halves2half2(l10, l11);
            } else {
                *(float2*)(Cf + (size_t)r0 * N + cc) = make_float2(v00, v01);
                *(float2*)(Cf + (size_t)r1 * N + cc) = make_float2(v10, v11);
            }
        }
    }
}

// ---------------- 4) fused causal attention (flash-style, f32x2 math) ----------------
// heavy causal tiles scheduled first: qt = gridDim.x-1-blockIdx.x
__global__ __launch_bounds__(128)
void attn_kernel(const float* __restrict__ qkv, const float* __restrict__ rel,
                 __half* __restrict__ oh, __half* __restrict__ ol) {
    __shared__ __align__(16) float ks[32][64];
    __shared__ __align__(16) float vs[32][64];
    __shared__ float relsm[RELN];

    int qt = gridDim.x - 1 - blockIdx.x, h = blockIdx.y, b = blockIdx.z;
    int i_glob = qt * 128 + threadIdx.x;
    const float* base = qkv + (size_t)b * NPATCH * QKVD;

    uint32_t ks_base = (uint32_t)__cvta_generic_to_shared(ks);
    uint32_t vs_base = (uint32_t)__cvta_generic_to_shared(vs);

    for (int r = threadIdx.x; r < RELN; r += 128) relsm[r] = rel[r];

    uint64_t q2[32];
    {
        const float* qp = base + (size_t)i_glob * QKVD + h * DH;
        #pragma unroll
        for (int d = 0; d < 16; d++) {
            float4 t4 = *(const float4*)(qp + 4 * d);
            q2[2 * d]     = pk2(t4.x, t4.y);
            q2[2 * d + 1] = pk2(t4.z, t4.w);
        }
    }

    uint64_t O2[32];
    #pragma unroll
    for (int d = 0; d < 32; d++) O2[d] = 0ull;
    float mrun = -1e30f, lsum = 0.f;

    int jmax = qt * 128 + 128;
    for (int j0 = 0; j0 < jmax; j0 += 32) {
        __syncthreads();
        #pragma unroll
        for (int i = 0; i < 4; i++) {
            int f = threadIdx.x + 128 * i;
            int jr = f >> 4, dc = (f & 15) * 4;
            const float* kp = base + (size_t)(j0 + jr) * QKVD + INNERD + h * DH + dc;
            const float* vp = base + (size_t)(j0 + jr) * QKVD + 2 * INNERD + h * DH + dc;
            *(float4*)&ks[jr][dc] = *(const float4*)kp;
            *(float4*)&vs[jr][dc] = *(const float4*)vp;
        }
        __syncthreads();

        if (j0 <= i_glob) {
            float s[32];
            #pragma unroll
            for (int j = 0; j < 32; j++) {
                uint64_t acc2 = 0ull;
                uint32_t a = ks_base + j * 256;
                #pragma unroll
                for (int d = 0; d < 16; d++) {
                    uint64_t p0, p1;
                    lds2u64(a + d * 16, p0, p1);
                    acc2 = fma2p(q2[2 * d], p0, acc2);
                    acc2 = fma2p(q2[2 * d + 1], p1, acc2);
                }
                float lo, hi;
                upk2(acc2, lo, hi);
                float sc = lo + hi;
                int delta = i_glob - (j0 + j);
                if (delta < 0) s[j] = -1e30f;
                else           s[j] = sc * 0.125f + relsm[min(delta, 199) + 199];
            }
            float mnew = mrun;
            #pragma unroll
            for (int j = 0; j < 32; j++) mnew = fmaxf(mnew, s[j]);
            float corr = expf(mrun - mnew);
            lsum *= corr;
            uint64_t corr2 = pk2(corr, corr);
            #pragma unroll
            for (int d = 0; d < 32; d++) O2[d] = mul2p(O2[d], corr2);
            #pragma unroll
            for (int j = 0; j < 32; j++) {
                float p = expf(s[j] - mnew);
                lsum += p;
                uint64_t pp = pk2(p, p);
                uint32_t a = vs_base + j * 256;
                #pragma unroll
                for (int d = 0; d < 16; d++) {
                    uint64_t p0, p1;
                    lds2u64(a + d * 16, p0, p1);
                    O2[2 * d]     = fma2p(pp, p0, O2[2 * d]);
                    O2[2 * d + 1] = fma2p(pp, p1, O2[2 * d + 1]);
                }
            }
            mrun = mnew;
        }
    }

    float inv = 1.f / lsum;
    size_t obase = ((size_t)b * NPATCH + i_glob) * DIMM + h * DH;
    #pragma unroll
    for (int d = 0; d < 32; d++) {
        float lo, hi;
        upk2(O2[d], lo, hi);
        float a0 = lo * inv, a1 = hi * inv;
        __half h0, l0, h1, l1;
        hsplit(a0, h0, l0); hsplit(a1, h1, l1);
        *(__half2*)(oh + obase + 2 * d) = __halves2half2(h0, h1);
        *(__half2*)(ol + obase + 2 * d) = __halves2half2(l0, l1);
    }
}

// ---------------- 5) projection head ----------------
__global__ void proj_kernel(const float* __restrict__ x, const float* __restrict__ W,
                            const float* __restrict__ bias, float* __restrict__ out) {
    __shared__ float xs[DIMM];
    int row = blockIdx.x;
    const float* xr = x + (size_t)row * DIMM;
    for (int c = threadIdx.x * 4; c < DIMM; c += 1024)
        *(float4*)&xs[c] = *(const float4*)(xr + c);
    __syncthreads();
    int w = threadIdx.x >> 5, lane = threadIdx.x & 31;
    for (int o = w; o < NCLS; o += 8) {
        const float* wr = W + (size_t)o * DIMM;
        float acc = 0.f;
        for (int d = lane * 4; d < DIMM; d += 128) {
            float4 xv = *(const float4*)&xs[d];
            float4 wv = *(const float4*)(wr + d);
            acc += xv.x * wv.x + xv.y * wv.y + xv.z * wv.z + xv.w * wv.w;
        }
        #pragma unroll
        for (int off = 16; off; off >>= 1) acc += __shfl_down_sync(0xffffffffu, acc, off);
        if (!lane) out[(size_t)row * NCLS + o] = acc + bias[o];
    }
}

// ---------------- launch ----------------
#define SMEM256 (2048 + 2 * (2 * ATILE + 2 * 256 * 128))   // 198656 (ST=2)
#define SMEM128 (2048 + 3 * (2 * ATILE + 2 * 128 * 128))   // 198656 (ST=3)

extern "C" void kernel_launch(void* const* d_in, const int* in_sizes, int n_in,
                              void* d_out, int out_size) {
    const float* neuralInput  = (const float*)d_in[0];
    const float* patch_ln1_g  = (const float*)d_in[1];
    const float* patch_ln1_b  = (const float*)d_in[2];
    const float* patch_w      = (const float*)d_in[3];
    const float* patch_b      = (const float*)d_in[4];
    const float* patch_ln2_g  = (const float*)d_in[5];
    const float* patch_ln2_b  = (const float*)d_in[6];
    const float* attn_ln_g    = (const float*)d_in[7];
    const float* attn_ln_b    = (const float*)d_in[8];
    const float* qkv_w        = (const float*)d_in[9];
    const float* out_w        = (const float*)d_in[10];
    const float* out_b        = (const float*)d_in[11];
    const float* rel_tab      = (const float*)d_in[12];
    const float* ffn_ln_g     = (const float*)d_in[13];
    const float* ffn_ln_b     = (const float*)d_in[14];
    const float* ffn_w1       = (const float*)d_in[15];
    const float* ffn_b1       = (const float*)d_in[16];
    const float* ffn_w2       = (const float*)d_in[17];
    const float* ffn_b2       = (const float*)d_in[18];
    const float* final_ln_g   = (const float*)d_in[19];
    const float* final_ln_b   = (const float*)d_in[20];
    const float* proj_w       = (const float*)d_in[21];
    const float* proj_b       = (const float*)d_in[22];

    float *px, *pqkv;
    __half *lnh, *lnl, *aoh, *aol, *fh, *fl;
    __half *wph, *wpl, *wqh, *wql, *woh, *wol, *w1h, *w1l, *w2h, *w2l;
    cudaGetSymbolAddress((void**)&px,   g_x);
    cudaGetSymbolAddress((void**)&pqkv, g_qkv);
    cudaGetSymbolAddress((void**)&lnh,  g_lnh);
    cudaGetSymbolAddress((void**)&lnl,  g_lnl);
    cudaGetSymbolAddress((void**)&aoh,  g_aoh);
    cudaGetSymbolAddress((void**)&aol,  g_aol);
    cudaGetSymbolAddress((void**)&fh,   g_fh);
    cudaGetSymbolAddress((void**)&fl,   g_fl);
    cudaGetSymbolAddress((void**)&wph,  g_wph);
    cudaGetSymbolAddress((void**)&wpl,  g_wpl);
    cudaGetSymbolAddress((void**)&wqh,  g_wqh);
    cudaGetSymbolAddress((void**)&wql,  g_wql);
    cudaGetSymbolAddress((void**)&woh,  g_woh);
    cudaGetSymbolAddress((void**)&wol,  g_wol);
    cudaGetSymbolAddress((void**)&w1h,  g_w1h);
    cudaGetSymbolAddress((void**)&w1l,  g_w1l);
    cudaGetSymbolAddress((void**)&w2h,  g_w2h);
    cudaGetSymbolAddress((void**)&w2l,  g_w2l);

    // Which binary variant got loaded? (static smem of probe differs by arch feature)
    bool use_tc = false;
    {
        cudaFuncAttributes a;
        if (cudaFuncGetAttributes(&a, probe_kernel) == cudaSuccess)
            use_tc = (a.sharedSizeBytes >= 8192);
    }

    if (use_tc) {
        cudaFuncSetAttribute(tgemm_tc<256, 0>, cudaFuncAttributeMaxDynamicSharedMemorySize, SMEM256);
        cudaFuncSetAttribute(tgemm_tc<256, 2>, cudaFuncAttributeMaxDynamicSharedMemorySize, SMEM256);
        cudaFuncSetAttribute(tgemm_tc<128, 0>, cudaFuncAttributeMaxDynamicSharedMemorySize, SMEM128);
        cudaFuncSetAttribute(tgemm_tc<128, 1>, cudaFuncAttributeMaxDynamicSharedMemorySize, SMEM128);
    } else {
        cudaFuncSetAttribute(tgemm_lg<0, 0, 0>, cudaFuncAttributeMaxDynamicSharedMemorySize, LG_SMEM);
        cudaFuncSetAttribute(tgemm_lg<0, 1, 0>, cudaFuncAttributeMaxDynamicSharedMemorySize, LG_SMEM);
        cudaFuncSetAttribute(tgemm_lg<1, 0, 1>, cudaFuncAttributeMaxDynamicSharedMemorySize, LG_SMEM);
    }

    // weight split pre-pass
    {
        int n;
        n = DIMM * DIMM / 4;
        wsplit_kernel<<<(n + 255) / 256, 256>>>((const float4*)patch_w, (__half2*)wph, (__half2*)wpl, n);
        n = DEPTH * QKVD * DIMM / 4;
        wsplit_kernel<<<(n + 255) / 256, 256>>>((const float4*)qkv_w, (__half2*)wqh, (__half2*)wql, n);
        n = DEPTH * DIMM * INNERD / 4;
        wsplit_kernel<<<(n + 255) / 256, 256>>>((const float4*)out_w, (__half2*)woh, (__half2*)wol, n);
        n = DEPTH * MLPD * DIMM / 4;
        wsplit_kernel<<<(n + 255) / 256, 256>>>((const float4*)ffn_w1, (__half2*)w1h, (__half2*)w1l, n);
        wsplit_kernel<<<(n + 255) / 256, 256>>>((const float4*)ffn_w2, (__half2*)w2h, (__half2*)w2l, n);
    }

    patch_kernel<<<NROWS, 256>>>(neuralInput, patch_ln1_g, patch_ln1_b, lnh, lnl);

    // patch linear -> fp32 temp (g_qkv), then LN2 -> fp32 residual g_x
    if (use_tc)
        tgemm_tc<128, 0><<<dim3(DIMM / 128, NROWS / 128), 128, SMEM128>>>(
            lnh, lnl, wph, wpl, patch_b, nullptr, pqkv, nullptr, nullptr, NROWS, DIMM, DIMM);
    else
        tgemm_lg<0, 0, 0><<<dim3(DIMM / 128, NROWS / 128), 256, LG_SMEM>>>(
            lnh, lnl, wph, wpl, patch_b, nullptr, pqkv, nullptr, nullptr, NROWS, DIMM, DIMM);
    ln_kernel<0><<<NROWS / 8, 256>>>(pqkv, px, nullptr, patch_ln2_g, patch_ln2_b);

    for (int l = 0; l < DEPTH; l++) {
        // attention block
        ln_kernel<1><<<NROWS / 8, 256>>>(px, lnh, lnl, attn_ln_g + l * DIMM, attn_ln_b + l * DIMM);
        if (use_tc)
            tgemm_tc<256, 0><<<dim3(QKVD / 256, NROWS / 128), 128, SMEM256>>>(
                lnh, lnl, wqh + (size_t)l * QKVD * DIMM, wql + (size_t)l * QKVD * DIMM,
                nullptr, nullptr, pqkv, nullptr, nullptr, NROWS, QKVD, DIMM);
        else
            tgemm_lg<0, 0, 0><<<dim3(QKVD / 128, NROWS / 128), 256, LG_SMEM>>>(
                lnh, lnl, wqh + (size_t)l * QKVD * DIMM, wql + (size_t)l * QKVD * DIMM,
                nullptr, nullptr, pqkv, nullptr, nullptr, NROWS, QKVD, DIMM);
        attn_kernel<<<dim3(NPATCH / 128, HEADS, BATCH), 128>>>(
            pqkv, rel_tab + (size_t)l * RELN, aoh, aol);
        if (use_tc)
            tgemm_tc<128, 1><<<dim3(DIMM / 128, NROWS / 128), 128, SMEM128>>>(
                aoh, aol, woh + (size_t)l * DIMM * INNERD, wol + (size_t)l * DIMM * INNERD,
                out_b + (size_t)l * DIMM, px, px, nullptr, nullptr, NROWS, DIMM, INNERD);
        else
            tgemm_lg<0, 1, 0><<<dim3(DIMM / 128, NROWS / 128), 256, LG_SMEM>>>(
                aoh, aol, woh + (size_t)l * DIMM * INNERD, wol + (size_t)l * DIMM * INNERD,
                out_b + (size_t)l * DIMM, px, px, nullptr, nullptr, NROWS, DIMM, INNERD);
        // ffn block
        ln_kernel<1><<<NROWS / 8, 256>>>(px, lnh, lnl, ffn_ln_g + l * DIMM, ffn_ln_b + l * DIMM);
        if (use_tc)
            tgemm_tc<256, 2><<<dim3(MLPD / 256, NROWS / 128), 128, SMEM256>>>(
                lnh, lnl, w1h + (size_t)l * MLPD * DIMM, w1l + (size_t)l * MLPD * DIMM,
                ffn_b1 + (size_t)l * MLPD, nullptr, nullptr, fh, fl, NROWS, MLPD, DIMM);
        else
            tgemm_lg<1, 0, 1><<<dim3(MLPD / 128, NROWS / 128), 256, LG_SMEM>>>(
                lnh, lnl, w1h + (size_t)l * MLPD * DIMM, w1l + (size_t)l * MLPD * DIMM,
                ffn_b1 + (size_t)l * MLPD, nullptr, nullptr, fh, fl, NROWS, MLPD, DIMM);
        if (use_tc)
            tgemm_tc<128, 1><<<dim3(DIMM / 128, NROWS / 128), 128, SMEM128>>>(
                fh, fl, w2h + (size_t)l * DIMM * MLPD, w2l + (size_t)l * DIMM * MLPD,
                ffn_b2 + (size_t)l * DIMM, px, px, nullptr, nullptr, NROWS, DIMM, MLPD);
        else
            tgemm_lg<0, 1, 0><<<dim3(DIMM / 128, NROWS / 128), 256, LG_SMEM>>>(
                fh, fl, w2h + (size_t)l * DIMM * MLPD, w2l + (size_t)l * DIMM * MLPD,
                ffn_b2 + (size_t)l * DIMM, px, px, nullptr, nullptr, NROWS, DIMM, MLPD);
    }

    // final LN (fp32 into g_qkv) + projection
    ln_kernel<0><<<NROWS / 8, 256>>>(px, pqkv, nullptr, final_ln_g, final_ln_b);
    proj_kernel<<<NROWS, 256>>>(pqkv, proj_w, proj_b, (float*)d_out);
}

// round 14
// speedup vs baseline: 1.0953x; 1.0953x over previous
#include <cuda_runtime.h>
#include <cuda_fp16.h>
#include <math.h>
#include <stdint.h>

// ---------------- problem constants ----------------
#define BATCH   4
#define TLEN    2048
#define PW      256
#define P1      4
#define NPATCH  512          // TLEN/P1
#define NROWS   2048         // BATCH*NPATCH
#define DIMM    1024
#define HEADS   16
#define DH      64
#define INNERD  1024         // HEADS*DH
#define QKVD    3072
#define MLPD    4096
#define DEPTH   12
#define NCLS    41           // NCLS+1
#define RELN    399          // 2*MAXREL-1

// arch-feature gate: tcgen05 only exists on sm_100a/sm_103a-class targets
#if defined(__CUDA_ARCH_FEAT_SM103_ALL) || defined(__CUDA_ARCH_FEAT_SM100_ALL) || defined(__CUDA_ARCH_FEAT_SM101_ALL)
#define HAS_TC 1
#else
#define HAS_TC 0
#endif

// ---------------- scratch (device globals; allocation-free) ----------------
__device__ float g_x  [(size_t)NROWS*DIMM];     // fp32 residual stream
__device__ float g_qkv[(size_t)NROWS*QKVD];     // fp32 qkv + generic fp32 temp

// activation hi/lo fp16 planes
__device__ __half g_lnh[(size_t)NROWS*DIMM];
__device__ __half g_lnl[(size_t)NROWS*DIMM];
__device__ __half g_aoh[(size_t)NROWS*DIMM];
__device__ __half g_aol[(size_t)NROWS*DIMM];
__device__ __half g_fh [(size_t)NROWS*MLPD];
__device__ __half g_fl [(size_t)NROWS*MLPD];

// weight hi/lo fp16 planes
__device__ __half g_wph[(size_t)DIMM*DIMM];
__device__ __half g_wpl[(size_t)DIMM*DIMM];
__device__ __half g_wqh[(size_t)DEPTH*QKVD*DIMM];
__device__ __half g_wql[(size_t)DEPTH*QKVD*DIMM];
__device__ __half g_woh[(size_t)DEPTH*DIMM*INNERD];
__device__ __half g_wol[(size_t)DEPTH*DIMM*INNERD];
__device__ __half g_w1h[(size_t)DEPTH*MLPD*DIMM];
__device__ __half g_w1l[(size_t)DEPTH*MLPD*DIMM];
__device__ __half g_w2h[(size_t)DEPTH*DIMM*MLPD];
__device__ __half g_w2l[(size_t)DEPTH*DIMM*MLPD];

// ---------------- generic helpers ----------------
__device__ __forceinline__ void hsplit(float x, __half& h, __half& l) {
    h = __float2half_rn(x);
    l = __float2half_rn(x - __half2float(h));
}

__device__ __forceinline__ float gelu_exact(float x) {
    return 0.5f * x * (1.f + erff(x * 0.70710678118654752f));
}

__device__ __forceinline__ void cp16s(uint32_t s, const void* g) {
    asm volatile("cp.async.cg.shared.global [%0], [%1], 16;\n" :: "r"(s), "l"(g));
}

// packed f32x2 helpers (sm_100+)
__device__ __forceinline__ uint64_t pk2(float lo, float hi) {
    uint64_t d;
    asm("mov.b64 %0, {%1, %2};" : "=l"(d) : "f"(lo), "f"(hi));
    return d;
}
__device__ __forceinline__ void upk2(uint64_t v, float& lo, float& hi) {
    asm("mov.b64 {%0, %1}, %2;" : "=f"(lo), "=f"(hi) : "l"(v));
}
__device__ __forceinline__ uint64_t fma2p(uint64_t a, uint64_t b, uint64_t c) {
    uint64_t d;
    asm("fma.rn.f32x2 %0, %1, %2, %3;" : "=l"(d) : "l"(a), "l"(b), "l"(c));
    return d;
}
__device__ __forceinline__ uint64_t mul2p(uint64_t a, uint64_t b) {
    uint64_t d;
    asm("mul.rn.f32x2 %0, %1, %2;" : "=l"(d) : "l"(a), "l"(b));
    return d;
}
__device__ __forceinline__ void lds2u64(uint32_t a, uint64_t& p0, uint64_t& p1) {
    asm("ld.shared.v2.u64 {%0, %1}, [%2];" : "=l"(p0), "=l"(p1) : "r"(a));
}

// ---------------- arch probe: static smem size differs by feature ----------------
__global__ void probe_kernel(float* out) {
#if HAS_TC
    __shared__ volatile float s[2048];            // 8192 bytes static smem
    s[threadIdx.x] = 1.f;
    __syncthreads();
    if (out) out[0] = s[threadIdx.x ^ 1];
#else
    if (out) out[0] = 0.f;
#endif
}

// ---------------- tcgen05 helpers (guarded) ----------------
__device__ __forceinline__ uint32_t sw128(uint32_t off) {
    return off ^ ((off >> 3) & 0x70);
}

__device__ __forceinline__ uint64_t sdesc(uint32_t saddr) {
    return (2ull << 61) | (1ull << 46) | (64ull << 32) | (1ull << 16)
         | ((uint64_t)(saddr >> 4) & 0x3FFF);
}

__device__ __forceinline__ void mbar_init(uint32_t a, uint32_t cnt) {
    asm volatile("mbarrier.init.shared.b64 [%0], %1;" :: "r"(a), "r"(cnt) : "memory");
}

__device__ __forceinline__ void mbar_wait(uint32_t a, int phase) {
    asm volatile(
        "{\n\t.reg .pred P;\n"
        "W_%=:\n\t"
        "mbarrier.try_wait.parity.shared.b64 P, [%0], %1;\n\t"
        "@P bra D_%=;\n\t"
        "bra W_%=;\n"
        "D_%=:\n\t}"
        :: "r"(a), "r"(phase) : "memory");
}

__device__ __forceinline__ void tc_alloc(uint32_t slot, uint32_t ncols) {
#if HAS_TC
    asm volatile("tcgen05.alloc.cta_group::1.sync.aligned.shared::cta.b32 [%0], %1;"
                 :: "r"(slot), "r"(ncols) : "memory");
    asm volatile("tcgen05.relinquish_alloc_permit.cta_group::1.sync.aligned;");
#endif
}

__device__ __forceinline__ void tc_dealloc(uint32_t tmem, uint32_t ncols) {
#if HAS_TC
    asm volatile("tcgen05.dealloc.cta_group::1.sync.aligned.b32 %0, %1;"
                 :: "r"(tmem), "r"(ncols));
#endif
}

__device__ __forceinline__ void tc_mma_f16_ss(uint32_t d, uint64_t a_desc, uint64_t b_desc,
                                              uint32_t idesc, uint32_t en) {
#if HAS_TC
    asm volatile(
        "{\n\t.reg .pred p;\n\t"
        "setp.ne.u32 p, %5, 0;\n\t"
        "tcgen05.mma.cta_group::1.kind::f16 [%0], %1, %2, %3, {%4, %4, %4, %4}, p;\n\t}"
        :: "r"(d), "l"(a_desc), "l"(b_desc), "r"(idesc), "r"(0u), "r"(en) : "memory");
#endif
}

__device__ __forceinline__ void tc_commit(uint32_t mbar) {
#if HAS_TC
    asm volatile("tcgen05.commit.cta_group::1.mbarrier::arrive::one.shared::cluster.b64 [%0];"
                 :: "r"(mbar) : "memory");
#endif
}

__device__ __forceinline__ void tmem_ld32(uint32_t* r, uint32_t a) {
#if HAS_TC
    asm volatile(
        "tcgen05.ld.sync.aligned.32x32b.x32.b32 "
        "{%0, %1, %2, %3, %4, %5, %6, %7, "
        " %8, %9, %10, %11, %12, %13, %14, %15, "
        " %16, %17, %18, %19, %20, %21, %22, %23, "
        " %24, %25, %26, %27, %28, %29, %30, %31}, [%32];"
        : "=r"(r[0]),  "=r"(r[1]),  "=r"(r[2]),  "=r"(r[3]),
          "=r"(r[4]),  "=r"(r[5]),  "=r"(r[6]),  "=r"(r[7]),
          "=r"(r[8]),  "=r"(r[9]),  "=r"(r[10]), "=r"(r[11]),
          "=r"(r[12]), "=r"(r[13]), "=r"(r[14]), "=r"(r[15]),
          "=r"(r[16]), "=r"(r[17]), "=r"(r[18]), "=r"(r[19]),
          "=r"(r[20]), "=r"(r[21]), "=r"(r[22]), "=r"(r[23]),
          "=r"(r[24]), "=r"(r[25]), "=r"(r[26]), "=r"(r[27]),
          "=r"(r[28]), "=r"(r[29]), "=r"(r[30]), "=r"(r[31])
        : "r"(a));
#else
    #pragma unroll
    for (int i = 0; i < 32; i++) r[i] = 0;
    (void)a;
#endif
}

// ---------------- weight split pre-pass ----------------
__global__ void wsplit_kernel(const float4* __restrict__ in,
                              __half2* __restrict__ oh, __half2* __restrict__ ol, int n4) {
    int i = blockIdx.x * blockDim.x + threadIdx.x;
    if (i < n4) {
        float4 v = in[i];
        __half h0, l0, h1, l1, h2, l2, h3, l3;
        hsplit(v.x, h0, l0); hsplit(v.y, h1, l1);
        hsplit(v.z, h2, l2); hsplit(v.w, h3, l3);
        oh[2 * i]     = __halves2half2(h0, h1);
        oh[2 * i + 1] = __halves2half2(h2, h3);
        ol[2 * i]     = __halves2half2(l0, l1);
        ol[2 * i + 1] = __halves2half2(l2, l3);
    }
}

// ---------------- 1) gaussian conv + patchify + LN1 (planes out) ----------------
__device__ __forceinline__ float blockSum256(float v) {
    __shared__ float red[8];
    int lane = threadIdx.x & 31, w = threadIdx.x >> 5;
    __syncthreads();
    #pragma unroll
    for (int o = 16; o; o >>= 1) v += __shfl_down_sync(0xffffffffu, v, o);
    if (!lane) red[w] = v;
    __syncthreads();
    if (w == 0) {
        float r = (lane < 8) ? red[lane] : 0.f;
        #pragma unroll
        for (int o = 4; o; o >>= 1) r += __shfl_down_sync(0xffffffffu, r, o);
        if (!lane) red[0] = r;
    }
    __syncthreads();
    return red[0];
}

__global__ void patch_kernel(const float* __restrict__ in,
                             const float* __restrict__ lg,
                             const float* __restrict__ lb,
                             __half* __restrict__ oh, __half* __restrict__ ol) {
    __shared__ float gk[20];
    if (threadIdx.x == 0) {
        float tmp[20], s = 0.f;
        #pragma unroll
        for (int i = 0; i < 20; i++) {
            float z = ((float)i - 9.5f) * 0.5f;
            tmp[i] = expf(-0.5f * z * z);
            s += tmp[i];
        }
        #pragma unroll
        for (int i = 0; i < 20; i++) gk[i] = tmp[i] / s;
    }
    __syncthreads();

    int row = blockIdx.x;
    int b = row >> 9, n = row & 511;
    int f = threadIdx.x;
    const float* ib = in + (size_t)b * TLEN * PW + f;

    float vals[P1];
    #pragma unroll
    for (int p = 0; p < P1; p++) {
        int t = n * P1 + p;
        float acc = 0.f;
        #pragma unroll
        for (int k = 0; k < 20; k++) {
            int tt = t - 9 + k;
            if (tt >= 0 && tt < TLEN) acc += ib[(size_t)tt * PW] * gk[k];
        }
        vals[p] = acc;
    }
    float s = vals[0] + vals[1] + vals[2] + vals[3];
    float mean = blockSum256(s) * (1.f / 1024.f);
    float sq = 0.f;
    #pragma unroll
    for (int p = 0; p < P1; p++) { float d = vals[p] - mean; sq += d * d; }
    float var = blockSum256(sq) * (1.f / 1024.f);
    float inv = rsqrtf(var + 1e-5f);
    #pragma unroll
    for (int p = 0; p < P1; p++) {
        int e = p * PW + f;
        float o = (vals[p] - mean) * inv * lg[e] + lb[e];
        __half h, l;
        hsplit(o, h, l);
        oh[(size_t)row * DIMM + e] = h;
        ol[(size_t)row * DIMM + e] = l;
    }
}

// ---------------- 2) LayerNorm over D=1024, warp-per-row (8 rows/CTA) ----------------
template <int PACK>
__global__ __launch_bounds__(256)
void ln_kernel(const float* __restrict__ in, void* __restrict__ o1,
               void* __restrict__ o2,
               const float* __restrict__ g, const float* __restrict__ b) {
    int wid = threadIdx.x >> 5, lane = threadIdx.x & 31;
    int row = blockIdx.x * 8 + wid;
    const float* x = in + (size_t)row * DIMM;

    float4 v[8];
    float s = 0.f;
    #pragma unroll
    for (int i = 0; i < 8; i++) {
        v[i] = *(const float4*)(x + lane * 4 + i * 128);
        s += v[i].x + v[i].y + v[i].z + v[i].w;
    }
    #pragma unroll
    for (int o = 16; o; o >>= 1) s += __shfl_xor_sync(0xffffffffu, s, o);
    float mean = s * (1.f / 1024.f);

    float sq = 0.f;
    #pragma unroll
    for (int i = 0; i < 8; i++) {
        v[i].x -= mean; v[i].y -= mean; v[i].z -= mean; v[i].w -= mean;
        sq += v[i].x * v[i].x + v[i].y * v[i].y + v[i].z * v[i].z + v[i].w * v[i].w;
    }
    #pragma unroll
    for (int o = 16; o; o >>= 1) sq += __shfl_xor_sync(0xffffffffu, sq, o);
    float inv = rsqrtf(sq * (1.f / 1024.f) + 1e-5f);

    #pragma unroll
    for (int i = 0; i < 8; i++) {
        int c = lane * 4 + i * 128;
        float4 gv = *(const float4*)(g + c), bv = *(const float4*)(b + c);
        float ox = v[i].x * inv * gv.x + bv.x;
        float oy = v[i].y * inv * gv.y + bv.y;
        float oz = v[i].z * inv * gv.z + bv.z;
        float ow = v[i].w * inv * gv.w + bv.w;
        if (PACK) {
            __half h0, l0, h1, l1, h2, l2, h3, l3;
            hsplit(ox, h0, l0); hsplit(oy, h1, l1);
            hsplit(oz, h2, l2); hsplit(ow, h3, l3);
            size_t idx = ((size_t)row * DIMM + c) >> 1;
            ((__half2*)o1)[idx]     = __halves2half2(h0, h1);
            ((__half2*)o1)[idx + 1] = __halves2half2(h2, h3);
            ((__half2*)o2)[idx]     = __halves2half2(l0, l1);
            ((__half2*)o2)[idx + 1] = __halves2half2(l2, l3);
        } else {
            *(float4*)((float*)o1 + (size_t)row * DIMM + c) = make_float4(ox, oy, oz, ow);
        }
    }
}

// ---------------- 3a) tcgen05 split-FP16 GEMM (R8 pipeline, 2-stage) ----------------
// NT=256: wide GEMMs, 1 CTA/SM. NT=64: narrow GEMMs, ~100KB smem -> 2 CTAs/SM
// so one CTA's MMAs overlap the other's loads/epilogue.
#define ATILE 16384            // 128 rows * 128 B
template <int NT, int MODE>
__global__ __launch_bounds__(128, (NT == 64) ? 2 : 1)
void tgemm_tc(const __half* __restrict__ Ah, const __half* __restrict__ Al,
              const __half* __restrict__ Bh, const __half* __restrict__ Bl,
              const float* __restrict__ bias, const float* __restrict__ R,
              float* __restrict__ Cf, __half* __restrict__ Ch, __half* __restrict__ Cl,
              int M, int N, int K) {
#if HAS_TC
    constexpr int BTILE = NT * 128;
    constexpr int BUF   = 2 * ATILE + 2 * BTILE;
    constexpr uint32_t IDESC = (1u << 4) | ((NT / 8) << 17) | (8u << 24);
    constexpr uint32_t TCOLS = (NT < 64) ? 64 : NT;   // TMEM accumulator columns

    extern __shared__ __align__(1024) uint8_t smraw[];
    uint32_t sbase = (uint32_t)__cvta_generic_to_shared(smraw);
    uint32_t s0 = (sbase + 1023) & ~1023u;
    uint32_t tmem_slot = s0, mb[2] = { s0 + 8, s0 + 16 };
    uint32_t tiles = s0 + 1024;

    int t = threadIdx.x, wid = t >> 5, lid = t & 31;
    int m0 = blockIdx.y * 128, n0 = blockIdx.x * NT;

    if (wid == 0) tc_alloc(tmem_slot, TCOLS);
    if (t == 0) { mbar_init(mb[0], 1); mbar_init(mb[1], 1); }
    __syncthreads();
    uint32_t tmem;
    asm volatile("ld.shared.b32 %0, [%1];" : "=r"(tmem) : "r"(tmem_slot));

    int T = K >> 6;                                 // K/64 chunks

    auto fill = [&](int c) {
        int b = c & 1;
        int k0 = c * 64;
        uint32_t bb = tiles + b * BUF;
        #pragma unroll 4
        for (int idx = t; idx < 128 * 8; idx += 128) {
            int row = idx >> 3, u = idx & 7;
            uint32_t soff = sw128(row * 128 + u * 16);
            size_t goff = (size_t)(m0 + row) * K + k0 + u * 8;
            cp16s(bb + soff, Ah + goff);
            cp16s(bb + ATILE + soff, Al + goff);
        }
        #pragma unroll 4
        for (int idx = t; idx < NT * 8; idx += 128) {
            int row = idx >> 3, u = idx & 7;
            uint32_t soff = sw128(row * 128 + u * 16);
            size_t goff = (size_t)(n0 + row) * K + k0 + u * 8;
            cp16s(bb + 2 * ATILE + soff, Bh + goff);
            cp16s(bb + 2 * ATILE + BTILE + soff, Bl + goff);
        }
        asm volatile("cp.async.commit_group;\n");
    };

    int ph[2] = { 0, 0 };
    fill(0);
    if (T > 1) fill(1);

    for (int c = 0; c < T; c++) {
        int b = c & 1;
        if (c + 1 < T) asm volatile("cp.async.wait_group 1;\n");
        else           asm volatile("cp.async.wait_group 0;\n");
        __syncthreads();

        if (t == 0) {
            asm volatile("fence.proxy.async.shared::cta;" ::: "memory");
            uint32_t bb = tiles + b * BUF;
            uint64_t dAh = sdesc(bb);
            uint64_t dAl = sdesc(bb + ATILE);
            uint64_t dBh = sdesc(bb + 2 * ATILE);
            uint64_t dBl = sdesc(bb + 2 * ATILE + BTILE);
            #pragma unroll
            for (int k = 0; k < 4; k++) {
                uint32_t en0 = (c == 0 && k == 0) ? 0u : 1u;
                tc_mma_f16_ss(tmem, dAl + k * 2, dBh + k * 2, IDESC, en0);
                tc_mma_f16_ss(tmem, dAh + k * 2, dBl + k * 2, IDESC, 1u);
                tc_mma_f16_ss(tmem, dAh + k * 2, dBh + k * 2, IDESC, 1u);
            }
            tc_commit(mb[b]);
        }

        if (c + 2 < T) {
            mbar_wait(mb[b], ph[b]);
            ph[b] ^= 1;
            fill(c + 2);
        }
    }

    // drain remaining two chunks' MMAs
    {
        int b2 = (T - 2) & 1, b1 = (T - 1) & 1;
        mbar_wait(mb[b2], ph[b2]); ph[b2] ^= 1;
        mbar_wait(mb[b1], ph[b1]); ph[b1] ^= 1;
    }
    asm volatile("tcgen05.fence::after_thread_sync;" ::: "memory");

    // epilogue: each warp reads its 32-lane subpartition
    int row = m0 + wid * 32 + lid;
    #pragma unroll 1
    for (int cb = 0; cb < NT / 32; cb++) {
        uint32_t r[32];
        tmem_ld32(r, tmem + cb * 32);
        asm volatile("tcgen05.wait::ld.sync.aligned;" ::: "memory");
        int nb = n0 + cb * 32;
        float v[32];
        #pragma unroll
        for (int c = 0; c < 32; c++)
            v[c] = __uint_as_float(r[c]) + (bias ? bias[nb + c] : 0.f);
        if (MODE == 1) {
            #pragma unroll
            for (int c4 = 0; c4 < 32; c4 += 4) {
                float4 rv = *(const float4*)(R + (size_t)row * N + nb + c4);
                v[c4] += rv.x; v[c4 + 1] += rv.y; v[c4 + 2] += rv.z; v[c4 + 3] += rv.w;
            }
        }
        if (MODE <= 1) {
            #pragma unroll
            for (int c4 = 0; c4 < 32; c4 += 4)
                *(float4*)(Cf + (size_t)row * N + nb + c4) =
                    make_float4(v[c4], v[c4 + 1], v[c4 + 2], v[c4 + 3]);
        } else {
            __align__(16) __half hh[32], hl[32];
            #pragma unroll
            for (int c = 0; c < 32; c++) {
                float gx = gelu_exact(v[c]);
                hsplit(gx, hh[c], hl[c]);
            }
            #pragma unroll
            for (int q = 0; q < 4; q++) {
                *(uint4*)(Ch + (size_t)row * N + nb + q * 8) = *(uint4*)&hh[q * 8];
                *(uint4*)(Cl + (size_t)row * N + nb + q * 8) = *(uint4*)&hl[q * 8];
            }
        }
    }

    __syncthreads();
    if (wid == 0) tc_dealloc(tmem, TCOLS);
#endif
}

// ---------------- 3b) legacy mma.sync split-FP16 GEMM (fallback) ----------------
__device__ __forceinline__ void mma_f16(float* c, const uint32_t* a, const uint32_t* b) {
    asm volatile(
        "mma.sync.aligned.m16n8k16.row.col.f32.f16.f16.f32 "
        "{%0,%1,%2,%3}, {%4,%5,%6,%7}, {%8,%9}, {%0,%1,%2,%3};"
        : "+f"(c[0]), "+f"(c[1]), "+f"(c[2]), "+f"(c[3])
        : "r"(a[0]), "r"(a[1]), "r"(a[2]), "r"(a[3]), "r"(b[0]), "r"(b[1]));
}

#define LG_PLANE 5120              // halves per plane tile (128 rows * 40)
#define LG_STAGE (4 * LG_PLANE)    // halves per stage
#define LG_SMEM  (2 * LG_STAGE * 2)  // 81920 bytes

template <int GELU, int RES, int PACK>
__global__ __launch_bounds__(256)
void tgemm_lg(const __half* __restrict__ Ah, const __half* __restrict__ Al,
              const __half* __restrict__ Bh, const __half* __restrict__ Bl,
              const float* __restrict__ bias, const float* __restrict__ R,
              float* __restrict__ Cf, __half* __restrict__ Ch, __half* __restrict__ Cl,
              int M, int N, int K) {
    extern __shared__ __half smh[];
    uint32_t sbase_u = (uint32_t)__cvta_generic_to_shared(smh);
    int m0 = blockIdx.y * 128, n0 = blockIdx.x * 128;
    int t = threadIdx.x, lane = t & 31, wid = t >> 5;
    int g = lane >> 2, tig = lane & 3;
    int warp_m = wid & 1, warp_n = wid >> 1;

    float acc[4][4][4];
    #pragma unroll
    for (int i = 0; i < 4; i++)
        #pragma unroll
        for (int j = 0; j < 4; j++)
            #pragma unroll
            for (int r = 0; r < 4; r++) acc[i][j][r] = 0.f;

    int T = K >> 5;
    const __half* gsrc[4] = { Ah, Al, Bh, Bl };

    auto fill = [&](int tt) {
        int st = tt & 1;
        int k0 = tt * 32;
        #pragma unroll
        for (int pl = 0; pl < 4; pl++) {
            int rbase = (pl < 2) ? m0 : n0;
            uint32_t dst = sbase_u + (uint32_t)(st * LG_STAGE + pl * LG_PLANE) * 2;
            const __half* src = gsrc[pl] + (size_t)rbase * K + k0;
            #pragma unroll
            for (int q = 0; q < 2; q++) {
                int cidx = t + 256 * q;
                int row = cidx >> 2, seg = cidx & 3;
                cp16s(dst + (uint32_t)(row * 40 + seg * 8) * 2,
                      src + (size_t)row * K + seg * 8);
            }
        }
        asm volatile("cp.async.commit_group;\n");
    };

    fill(0);
    for (int tt = 0; tt < T; tt++) {
        if (tt + 1 < T) { fill(tt + 1); asm volatile("cp.async.wait_group 1;\n"); }
        else            { asm volatile("cp.async.wait_group 0;\n"); }
        __syncthreads();

        const uint32_t* S   = (const uint32_t*)smh + (tt & 1) * (LG_STAGE / 2);
        const uint32_t* SAh = S;
        const uint32_t* SAl = S + LG_PLANE / 2;
        const uint32_t* SWh = S + LG_PLANE;
        const uint32_t* SWl = S + 3 * (LG_PLANE / 2);
        int am = warp_m * 64, bn = warp_n * 32;

        #pragma unroll
        for (int ks = 0; ks < 2; ks++) {
            int kw = ks * 8 + tig;
            uint32_t ah[4][4], al[4][4], bh[4][2], bl[4][2];
            #pragma unroll
            for (int i = 0; i < 4; i++) {
                int r = am + i * 16 + g;
                ah[i][0] = SAh[r * 20 + kw];       ah[i][1] = SAh[(r + 8) * 20 + kw];
                ah[i][2] = SAh[r * 20 + kw + 4];   ah[i][3] = SAh[(r + 8) * 20 + kw + 4];
                al[i][0] = SAl[r * 20 + kw];       al[i][1] = SAl[(r + 8) * 20 + kw];
                al[i][2] = SAl[r * 20 + kw + 4];   al[i][3] = SAl[(r + 8) * 20 + kw + 4];
            }
            #pragma unroll
            for (int j = 0; j < 4; j++) {
                int c = bn + j * 8 + g;
                bh[j][0] = SWh[c * 20 + kw];  bh[j][1] = SWh[c * 20 + kw + 4];
                bl[j][0] = SWl[c * 20 + kw];  bl[j][1] = SWl[c * 20 + kw + 4];
            }
            #pragma unroll
            for (int i = 0; i < 4; i++)
                #pragma unroll
                for (int j = 0; j < 4; j++) {
                    mma_f16(acc[i][j], al[i], bh[j]);
                    mma_f16(acc[i][j], ah[i], bl[j]);
                    mma_f16(acc[i][j], ah[i], bh[j]);
                }
        }
        __syncthreads();
    }

    int m_base = m0 + warp_m * 64;
    int n_base = n0 + warp_n * 32;
    #pragma unroll
    for (int i = 0; i < 4; i++) {
        int r0 = m_base + i * 16 + g;
        int r1 = r0 + 8;
        #pragma unroll
        for (int j = 0; j < 4; j++) {
            int cc = n_base + j * 8 + tig * 2;
            float b0 = bias ? bias[cc] : 0.f;
            float b1 = bias ? bias[cc + 1] : 0.f;
            float v00 = acc[i][j][0] + b0, v01 = acc[i][j][1] + b1;
            float v10 = acc[i][j][2] + b0, v11 = acc[i][j][3] + b1;
            if (GELU) {
                v00 = gelu_exact(v00); v01 = gelu_exact(v01);
                v10 = gelu_exact(v10); v11 = gelu_exact(v11);
            }
            if (RES) {
                const float2 rv0 = *(const float2*)(R + (size_t)r0 * N + cc);
                const float2 rv1 = *(const float2*)(R + (size_t)r1 * N + cc);
                v00 += rv0.x; v01 += rv0.y; v10 += rv1.x; v11 += rv1.y;
            }
            if (PACK) {
                __half h00, l00, h01, l01, h10, l10, h11, l11;
                hsplit(v00, h00, l00); hsplit(v01, h01, l01);
                hsplit(v10, h10, l10); hsplit(v11, h11, l11);
                *(__half2*)(Ch + (size_t)r0 * N + cc) = __halves2half2(h00, h01);
                *(__half2*)(Ch + (size_t)r1 * N + cc) = __halves2half2(h10, h11);
                *(__half2*)(Cl + (size_t)r0 * N + cc) = __halves2half2(l00, l01);
                *(__half2*)(Cl + (size_t)r1 * N + cc) = __halves2half2(l10, l11);
            } else {
                *(float2*)(Cf + (size_t)r0 * N + cc) = make_float2(v00, v01);
                *(float2*)(Cf + (size_t)r1 * N + cc) = make_float2(v10, v11);
            }
        }
    }
}

// ---------------- 4) fused causal attention (flash-style, f32x2 math) ----------------
__global__ __launch_bounds__(128)
void attn_kernel(const float* __restrict__ qkv, const float* __restrict__ rel,
                 __half* __restrict__ oh, __half* __restrict__ ol) {
    __shared__ __align__(16) float ks[32][64];
    __shared__ __align__(16) float vs[32][64];
    __shared__ float relsm[RELN];

    int qt = blockIdx.x, h = blockIdx.y, b = blockIdx.z;
    int i_glob = qt * 128 + threadIdx.x;
    const float* base = qkv + (size_t)b * NPATCH * QKVD;

    uint32_t ks_base = (uint32_t)__cvta_generic_to_shared(ks);
    uint32_t vs_base = (uint32_t)__cvta_generic_to_shared(vs);

    for (int r = threadIdx.x; r < RELN; r += 128) relsm[r] = rel[r];

    uint64_t q2[32];
    {
        const float* qp = base + (size_t)i_glob * QKVD + h * DH;
        #pragma unroll
        for (int d = 0; d < 16; d++) {
            float4 t4 = *(const float4*)(qp + 4 * d);
            q2[2 * d]     = pk2(t4.x, t4.y);
            q2[2 * d + 1] = pk2(t4.z, t4.w);
        }
    }

    uint64_t O2[32];
    #pragma unroll
    for (int d = 0; d < 32; d++) O2[d] = 0ull;
    float mrun = -1e30f, lsum = 0.f;

    int jmax = qt * 128 + 128;
    for (int j0 = 0; j0 < jmax; j0 += 32) {
        __syncthreads();
        #pragma unroll
        for (int i = 0; i < 4; i++) {
            int f = threadIdx.x + 128 * i;
            int jr = f >> 4, dc = (f & 15) * 4;
            const float* kp = base + (size_t)(j0 + jr) * QKVD + INNERD + h * DH + dc;
            const float* vp = base + (size_t)(j0 + jr) * QKVD + 2 * INNERD + h * DH + dc;
            *(float4*)&ks[jr][dc] = *(const float4*)kp;
            *(float4*)&vs[jr][dc] = *(const float4*)vp;
        }
        __syncthreads();

        if (j0 <= i_glob) {
            float s[32];
            #pragma unroll
            for (int j = 0; j < 32; j++) {
                uint64_t acc2 = 0ull;
                uint32_t a = ks_base + j * 256;
                #pragma unroll
                for (int d = 0; d < 16; d++) {
                    uint64_t p0, p1;
                    lds2u64(a + d * 16, p0, p1);
                    acc2 = fma2p(q2[2 * d], p0, acc2);
                    acc2 = fma2p(q2[2 * d + 1], p1, acc2);
                }
                float lo, hi;
                upk2(acc2, lo, hi);
                float sc = lo + hi;
                int delta = i_glob - (j0 + j);
                if (delta < 0) s[j] = -1e30f;
                else           s[j] = sc * 0.125f + relsm[min(delta, 199) + 199];
            }
            float mnew = mrun;
            #pragma unroll
            for (int j = 0; j < 32; j++) mnew = fmaxf(mnew, s[j]);
            float corr = expf(mrun - mnew);
            lsum *= corr;
            uint64_t corr2 = pk2(corr, corr);
            #pragma unroll
            for (int d = 0; d < 32; d++) O2[d] = mul2p(O2[d], corr2);
            #pragma unroll
            for (int j = 0; j < 32; j++) {
                float p = expf(s[j] - mnew);
                lsum += p;
                uint64_t pp = pk2(p, p);
                uint32_t a = vs_base + j * 256;
                #pragma unroll
                for (int d = 0; d < 16; d++) {
                    uint64_t p0, p1;
                    lds2u64(a + d * 16, p0, p1);
                    O2[2 * d]     = fma2p(pp, p0, O2[2 * d]);
                    O2[2 * d + 1] = fma2p(pp, p1, O2[2 * d + 1]);
                }
            }
            mrun = mnew;
        }
    }

    float inv = 1.f / lsum;
    size_t obase = ((size_t)b * NPATCH + i_glob) * DIMM + h * DH;
    #pragma unroll
    for (int d = 0; d < 32; d++) {
        float lo, hi;
        upk2(O2[d], lo, hi);
        float a0 = lo * inv, a1 = hi * inv;
        __half h0, l0, h1, l1;
        hsplit(a0, h0, l0); hsplit(a1, h1, l1);
        *(__half2*)(oh + obase + 2 * d) = __halves2half2(h0, h1);
        *(__half2*)(ol + obase + 2 * d) = __halves2half2(l0, l1);
    }
}

// ---------------- 5) projection head ----------------
__global__ void proj_kernel(const float* __restrict__ x, const float* __restrict__ W,
                            const float* __restrict__ bias, float* __restrict__ out) {
    __shared__ float xs[DIMM];
    int row = blockIdx.x;
    const float* xr = x + (size_t)row * DIMM;
    for (int c = threadIdx.x * 4; c < DIMM; c += 1024)
        *(float4*)&xs[c] = *(const float4*)(xr + c);
    __syncthreads();
    int w = threadIdx.x >> 5, lane = threadIdx.x & 31;
    for (int o = w; o < NCLS; o += 8) {
        const float* wr = W + (size_t)o * DIMM;
        float acc = 0.f;
        for (int d = lane * 4; d < DIMM; d += 128) {
            float4 xv = *(const float4*)&xs[d];
            float4 wv = *(const float4*)(wr + d);
            acc += xv.x * wv.x + xv.y * wv.y + xv.z * wv.z + xv.w * wv.w;
        }
        #pragma unroll
        for (int off = 16; off; off >>= 1) acc += __shfl_down_sync(0xffffffffu, acc, off);
        if (!lane) out[(size_t)row * NCLS + o] = acc + bias[o];
    }
}

// ---------------- launch ----------------
#define SMEM256 (2048 + 2 * (2 * ATILE + 2 * 256 * 128))   // 198656
#define SMEM64  (2048 + 2 * (2 * ATILE + 2 * 64 * 128))    // 100352 -> 2 CTAs/SM

extern "C" void kernel_launch(void* const* d_in, const int* in_sizes, int n_in,
                              void* d_out, int out_size) {
    const float* neuralInput  = (const float*)d_in[0];
    const float* patch_ln1_g  = (const float*)d_in[1];
    const float* patch_ln1_b  = (const float*)d_in[2];
    const float* patch_w      = (const float*)d_in[3];
    const float* patch_b      = (const float*)d_in[4];
    const float* patch_ln2_g  = (const float*)d_in[5];
    const float* patch_ln2_b  = (const float*)d_in[6];
    const float* attn_ln_g    = (const float*)d_in[7];
    const float* attn_ln_b    = (const float*)d_in[8];
    const float* qkv_w        = (const float*)d_in[9];
    const float* out_w        = (const float*)d_in[10];
    const float* out_b        = (const float*)d_in[11];
    const float* rel_tab      = (const float*)d_in[12];
    const float* ffn_ln_g     = (const float*)d_in[13];
    const float* ffn_ln_b     = (const float*)d_in[14];
    const float* ffn_w1       = (const float*)d_in[15];
    const float* ffn_b1       = (const float*)d_in[16];
    const float* ffn_w2       = (const float*)d_in[17];
    const float* ffn_b2       = (const float*)d_in[18];
    const float* final_ln_g   = (const float*)d_in[19];
    const float* final_ln_b   = (const float*)d_in[20];
    const float* proj_w       = (const float*)d_in[21];
    const float* proj_b       = (const float*)d_in[22];

    float *px, *pqkv;
    __half *lnh, *lnl, *aoh, *aol, *fh, *fl;
    __half *wph, *wpl, *wqh, *wql, *woh, *wol, *w1h, *w1l, *w2h, *w2l;
    cudaGetSymbolAddress((void**)&px,   g_x);
    cudaGetSymbolAddress((void**)&pqkv, g_qkv);
    cudaGetSymbolAddress((void**)&lnh,  g_lnh);
    cudaGetSymbolAddress((void**)&lnl,  g_lnl);
    cudaGetSymbolAddress((void**)&aoh,  g_aoh);
    cudaGetSymbolAddress((void**)&aol,  g_aol);
    cudaGetSymbolAddress((void**)&fh,   g_fh);
    cudaGetSymbolAddress((void**)&fl,   g_fl);
    cudaGetSymbolAddress((void**)&wph,  g_wph);
    cudaGetSymbolAddress((void**)&wpl,  g_wpl);
    cudaGetSymbolAddress((void**)&wqh,  g_wqh);
    cudaGetSymbolAddress((void**)&wql,  g_wql);
    cudaGetSymbolAddress((void**)&woh,  g_woh);
    cudaGetSymbolAddress((void**)&wol,  g_wol);
    cudaGetSymbolAddress((void**)&w1h,  g_w1h);
    cudaGetSymbolAddress((void**)&w1l,  g_w1l);
    cudaGetSymbolAddress((void**)&w2h,  g_w2h);
    cudaGetSymbolAddress((void**)&w2l,  g_w2l);

    // Which binary variant got loaded? (static smem of probe differs by arch feature)
    bool use_tc = false;
    {
        cudaFuncAttributes a;
        if (cudaFuncGetAttributes(&a, probe_kernel) == cudaSuccess)
            use_tc = (a.sharedSizeBytes >= 8192);
    }

    if (use_tc) {
        cudaFuncSetAttribute(tgemm_tc<256, 0>, cudaFuncAttributeMaxDynamicSharedMemorySize, SMEM256);
        cudaFuncSetAttribute(tgemm_tc<256, 2>, cudaFuncAttributeMaxDynamicSharedMemorySize, SMEM256);
        cudaFuncSetAttribute(tgemm_tc<64, 0>,  cudaFuncAttributeMaxDynamicSharedMemorySize, SMEM64);
        cudaFuncSetAttribute(tgemm_tc<64, 1>,  cudaFuncAttributeMaxDynamicSharedMemorySize, SMEM64);
    } else {
        cudaFuncSetAttribute(tgemm_lg<0, 0, 0>, cudaFuncAttributeMaxDynamicSharedMemorySize, LG_SMEM);
        cudaFuncSetAttribute(tgemm_lg<0, 1, 0>, cudaFuncAttributeMaxDynamicSharedMemorySize, LG_SMEM);
        cudaFuncSetAttribute(tgemm_lg<1, 0, 1>, cudaFuncAttributeMaxDynamicSharedMemorySize, LG_SMEM);
    }

    // weight split pre-pass
    {
        int n;
        n = DIMM * DIMM / 4;
        wsplit_kernel<<<(n + 255) / 256, 256>>>((const float4*)patch_w, (__half2*)wph, (__half2*)wpl, n);
        n = DEPTH * QKVD * DIMM / 4;
        wsplit_kernel<<<(n + 255) / 256, 256>>>((const float4*)qkv_w, (__half2*)wqh, (__half2*)wql, n);
        n = DEPTH * DIMM * INNERD / 4;
        wsplit_kernel<<<(n + 255) / 256, 256>>>((const float4*)out_w, (__half2*)woh, (__half2*)wol, n);
        n = DEPTH * MLPD * DIMM / 4;
        wsplit_kernel<<<(n + 255) / 256, 256>>>((const float4*)ffn_w1, (__half2*)w1h, (__half2*)w1l, n);
        wsplit_kernel<<<(n + 255) / 256, 256>>>((const float4*)ffn_w2, (__half2*)w2h, (__half2*)w2l, n);
    }

    patch_kernel<<<NROWS, 256>>>(neuralInput, patch_ln1_g, patch_ln1_b, lnh, lnl);

    // patch linear -> fp32 temp (g_qkv), then LN2 -> fp32 residual g_x
    if (use_tc)
        tgemm_tc<64, 0><<<dim3(DIMM / 64, NROWS / 128), 128, SMEM64>>>(
            lnh, lnl, wph, wpl, patch_b, nullptr, pqkv, nullptr, nullptr, NROWS, DIMM, DIMM);
    else
        tgemm_lg<0, 0, 0><<<dim3(DIMM / 128, NROWS / 128), 256, LG_SMEM>>>(
            lnh, lnl, wph, wpl, patch_b, nullptr, pqkv, nullptr, nullptr, NROWS, DIMM, DIMM);
    ln_kernel<0><<<NROWS / 8, 256>>>(pqkv, px, nullptr, patch_ln2_g, patch_ln2_b);

    for (int l = 0; l < DEPTH; l++) {
        // attention block
        ln_kernel<1><<<NROWS / 8, 256>>>(px, lnh, lnl, attn_ln_g + l * DIMM, attn_ln_b + l * DIMM);
        if (use_tc)
            tgemm_tc<256, 0><<<dim3(QKVD / 256, NROWS / 128), 128, SMEM256>>>(
                lnh, lnl, wqh + (size_t)l * QKVD * DIMM, wql + (size_t)l * QKVD * DIMM,
                nullptr, nullptr, pqkv, nullptr, nullptr, NROWS, QKVD, DIMM);
        else
            tgemm_lg<0, 0, 0><<<dim3(QKVD / 128, NROWS / 128), 256, LG_SMEM>>>(
                lnh, lnl, wqh + (size_t)l * QKVD * DIMM, wql + (size_t)l * QKVD * DIMM,
                nullptr, nullptr, pqkv, nullptr, nullptr, NROWS, QKVD, DIMM);
        attn_kernel<<<dim3(NPATCH / 128, HEADS, BATCH), 128>>>(
            pqkv, rel_tab + (size_t)l * RELN, aoh, aol);
        if (use_tc)
            tgemm_tc<64, 1><<<dim3(DIMM / 64, NROWS / 128), 128, SMEM64>>>(
                aoh, aol, woh + (size_t)l * DIMM * INNERD, wol + (size_t)l * DIMM * INNERD,
                out_b + (size_t)l * DIMM, px, px, nullptr, nullptr, NROWS, DIMM, INNERD);
        else
            tgemm_lg<0, 1, 0><<<dim3(DIMM / 128, NROWS / 128), 256, LG_SMEM>>>(
                aoh, aol, woh + (size_t)l * DIMM * INNERD, wol + (size_t)l * DIMM * INNERD,
                out_b + (size_t)l * DIMM, px, px, nullptr, nullptr, NROWS, DIMM, INNERD);
        // ffn block
        ln_kernel<1><<<NROWS / 8, 256>>>(px, lnh, lnl, ffn_ln_g + l * DIMM, ffn_ln_b + l * DIMM);
        if (use_tc)
            tgemm_tc<256, 2><<<dim3(MLPD / 256, NROWS / 128), 128, SMEM256>>>(
                lnh, lnl, w1h + (size_t)l * MLPD * DIMM, w1l + (size_t)l * MLPD * DIMM,
                ffn_b1 + (size_t)l * MLPD, nullptr, nullptr, fh, fl, NROWS, MLPD, DIMM);
        else
            tgemm_lg<1, 0, 1><<<dim3(MLPD / 128, NROWS / 128), 256, LG_SMEM>>>(
                lnh, lnl, w1h + (size_t)l * MLPD * DIMM, w1l + (size_t)l * MLPD * DIMM,
                ffn_b1 + (size_t)l * MLPD, nullptr, nullptr, fh, fl, NROWS, MLPD, DIMM);
        if (use_tc)
            tgemm_tc<64, 1><<<dim3(DIMM / 64, NROWS / 128), 128, SMEM64>>>(
                fh, fl, w2h + (size_t)l * DIMM * MLPD, w2l + (size_t)l * DIMM * MLPD,
                ffn_b2 + (size_t)l * DIMM, px, px, nullptr, nullptr, NROWS, DIMM, MLPD);
        else
            tgemm_lg<0, 1, 0><<<dim3(DIMM / 128, NROWS / 128), 256, LG_SMEM>>>(
                fh, fl, w2h + (size_t)l * DIMM * MLPD, w2l + (size_t)l * DIMM * MLPD,
                ffn_b2 + (size_t)l * DIMM, px, px, nullptr, nullptr, NROWS, DIMM, MLPD);
    }

    // final LN (fp32 into g_qkv) + projection
    ln_kernel<0><<<NROWS / 8, 256>>>(px, pqkv, nullptr, final_ln_g, final_ln_b);
    proj_kernel<<<NROWS, 256>>>(pqkv, proj_w, proj_b, (float*)d_out);
}

// round 15
// speedup vs baseline: 1.1155x; 1.0184x over previous
#include <cuda_runtime.h>
#include <cuda_fp16.h>
#include <math.h>
#include <stdint.h>

// ---------------- problem constants ----------------
#define BATCH   4
#define TLEN    2048
#define PW      256
#define P1      4
#define NPATCH  512          // TLEN/P1
#define NROWS   2048         // BATCH*NPATCH
#define DIMM    1024
#define HEADS   16
#define DH      64
#define INNERD  1024         // HEADS*DH
#define QKVD    3072
#define MLPD    4096
#define DEPTH   12
#define NCLS    41           // NCLS+1
#define RELN    399          // 2*MAXREL-1

// arch-feature gate: tcgen05 only exists on sm_100a/sm_103a-class targets
#if defined(__CUDA_ARCH_FEAT_SM103_ALL) || defined(__CUDA_ARCH_FEAT_SM100_ALL) || defined(__CUDA_ARCH_FEAT_SM101_ALL)
#define HAS_TC 1
#else
#define HAS_TC 0
#endif

// ---------------- scratch (device globals; allocation-free) ----------------
__device__ float g_x  [(size_t)NROWS*DIMM];     // fp32 residual stream
__device__ float g_qkv[(size_t)NROWS*QKVD];     // fp32 qkv + generic fp32 temp

// activation hi/lo fp16 planes
__device__ __half g_lnh[(size_t)NROWS*DIMM];
__device__ __half g_lnl[(size_t)NROWS*DIMM];
__device__ __half g_aoh[(size_t)NROWS*DIMM];
__device__ __half g_aol[(size_t)NROWS*DIMM];
__device__ __half g_fh [(size_t)NROWS*MLPD];
__device__ __half g_fl [(size_t)NROWS*MLPD];

// weight hi/lo fp16 planes
__device__ __half g_wph[(size_t)DIMM*DIMM];
__device__ __half g_wpl[(size_t)DIMM*DIMM];
__device__ __half g_wqh[(size_t)DEPTH*QKVD*DIMM];
__device__ __half g_wql[(size_t)DEPTH*QKVD*DIMM];
__device__ __half g_woh[(size_t)DEPTH*DIMM*INNERD];
__device__ __half g_wol[(size_t)DEPTH*DIMM*INNERD];
__device__ __half g_w1h[(size_t)DEPTH*MLPD*DIMM];
__device__ __half g_w1l[(size_t)DEPTH*MLPD*DIMM];
__device__ __half g_w2h[(size_t)DEPTH*DIMM*MLPD];
__device__ __half g_w2l[(size_t)DEPTH*DIMM*MLPD];

// ---------------- generic helpers ----------------
__device__ __forceinline__ void hsplit(float x, __half& h, __half& l) {
    h = __float2half_rn(x);
    l = __float2half_rn(x - __half2float(h));
}

__device__ __forceinline__ float gelu_exact(float x) {
    return 0.5f * x * (1.f + erff(x * 0.70710678118654752f));
}

__device__ __forceinline__ void cp16s(uint32_t s, const void* g) {
    asm volatile("cp.async.cg.shared.global [%0], [%1], 16;\n" :: "r"(s), "l"(g));
}

// packed f32x2 helpers (sm_100+)
__device__ __forceinline__ uint64_t pk2(float lo, float hi) {
    uint64_t d;
    asm("mov.b64 %0, {%1, %2};" : "=l"(d) : "f"(lo), "f"(hi));
    return d;
}
__device__ __forceinline__ void upk2(uint64_t v, float& lo, float& hi) {
    asm("mov.b64 {%0, %1}, %2;" : "=f"(lo), "=f"(hi) : "l"(v));
}
__device__ __forceinline__ uint64_t fma2p(uint64_t a, uint64_t b, uint64_t c) {
    uint64_t d;
    asm("fma.rn.f32x2 %0, %1, %2, %3;" : "=l"(d) : "l"(a), "l"(b), "l"(c));
    return d;
}
__device__ __forceinline__ uint64_t mul2p(uint64_t a, uint64_t b) {
    uint64_t d;
    asm("mul.rn.f32x2 %0, %1, %2;" : "=l"(d) : "l"(a), "l"(b));
    return d;
}
__device__ __forceinline__ void lds2u64(uint32_t a, uint64_t& p0, uint64_t& p1) {
    asm("ld.shared.v2.u64 {%0, %1}, [%2];" : "=l"(p0), "=l"(p1) : "r"(a));
}

// ---------------- arch probe: static smem size differs by feature ----------------
__global__ void probe_kernel(float* out) {
#if HAS_TC
    __shared__ volatile float s[2048];            // 8192 bytes static smem
    s[threadIdx.x] = 1.f;
    __syncthreads();
    if (out) out[0] = s[threadIdx.x ^ 1];
#else
    if (out) out[0] = 0.f;
#endif
}

// ---------------- tcgen05 helpers (guarded) ----------------
__device__ __forceinline__ uint32_t sw128(uint32_t off) {
    return off ^ ((off >> 3) & 0x70);
}
__device__ __forceinline__ uint32_t sw64(uint32_t off) {
    return off ^ ((off >> 3) & 0x30);
}

__device__ __forceinline__ uint64_t sdesc(uint32_t saddr) {        // SW128 K-major
    return (2ull << 61) | (1ull << 46) | (64ull << 32) | (1ull << 16)
         | ((uint64_t)(saddr >> 4) & 0x3FFF);
}
__device__ __forceinline__ uint64_t sdesc64(uint32_t saddr) {      // SW64 K-major
    return (4ull << 61) | (1ull << 46) | (32ull << 32) | (1ull << 16)
         | ((uint64_t)(saddr >> 4) & 0x3FFF);
}

__device__ __forceinline__ void mbar_init(uint32_t a, uint32_t cnt) {
    asm volatile("mbarrier.init.shared.b64 [%0], %1;" :: "r"(a), "r"(cnt) : "memory");
}

__device__ __forceinline__ void mbar_wait(uint32_t a, int phase) {
    asm volatile(
        "{\n\t.reg .pred P;\n"
        "W_%=:\n\t"
        "mbarrier.try_wait.parity.shared.b64 P, [%0], %1;\n\t"
        "@P bra D_%=;\n\t"
        "bra W_%=;\n"
        "D_%=:\n\t}"
        :: "r"(a), "r"(phase) : "memory");
}

__device__ __forceinline__ void tc_alloc(uint32_t slot, uint32_t ncols) {
#if HAS_TC
    asm volatile("tcgen05.alloc.cta_group::1.sync.aligned.shared::cta.b32 [%0], %1;"
                 :: "r"(slot), "r"(ncols) : "memory");
    asm volatile("tcgen05.relinquish_alloc_permit.cta_group::1.sync.aligned;");
#endif
}

__device__ __forceinline__ void tc_dealloc(uint32_t tmem, uint32_t ncols) {
#if HAS_TC
    asm volatile("tcgen05.dealloc.cta_group::1.sync.aligned.b32 %0, %1;"
                 :: "r"(tmem), "r"(ncols));
#endif
}

__device__ __forceinline__ void tc_mma_f16_ss(uint32_t d, uint64_t a_desc, uint64_t b_desc,
                                              uint32_t idesc, uint32_t en) {
#if HAS_TC
    asm volatile(
        "{\n\t.reg .pred p;\n\t"
        "setp.ne.u32 p, %5, 0;\n\t"
        "tcgen05.mma.cta_group::1.kind::f16 [%0], %1, %2, %3, {%4, %4, %4, %4}, p;\n\t}"
        :: "r"(d), "l"(a_desc), "l"(b_desc), "r"(idesc), "r"(0u), "r"(en) : "memory");
#endif
}

__device__ __forceinline__ void tc_commit(uint32_t mbar) {
#if HAS_TC
    asm volatile("tcgen05.commit.cta_group::1.mbarrier::arrive::one.shared::cluster.b64 [%0];"
                 :: "r"(mbar) : "memory");
#endif
}

__device__ __forceinline__ void tmem_ld32(uint32_t* r, uint32_t a) {
#if HAS_TC
    asm volatile(
        "tcgen05.ld.sync.aligned.32x32b.x32.b32 "
        "{%0, %1, %2, %3, %4, %5, %6, %7, "
        " %8, %9, %10, %11, %12, %13, %14, %15, "
        " %16, %17, %18, %19, %20, %21, %22, %23, "
        " %24, %25, %26, %27, %28, %29, %30, %31}, [%32];"
        : "=r"(r[0]),  "=r"(r[1]),  "=r"(r[2]),  "=r"(r[3]),
          "=r"(r[4]),  "=r"(r[5]),  "=r"(r[6]),  "=r"(r[7]),
          "=r"(r[8]),  "=r"(r[9]),  "=r"(r[10]), "=r"(r[11]),
          "=r"(r[12]), "=r"(r[13]), "=r"(r[14]), "=r"(r[15]),
          "=r"(r[16]), "=r"(r[17]), "=r"(r[18]), "=r"(r[19]),
          "=r"(r[20]), "=r"(r[21]), "=r"(r[22]), "=r"(r[23]),
          "=r"(r[24]), "=r"(r[25]), "=r"(r[26]), "=r"(r[27]),
          "=r"(r[28]), "=r"(r[29]), "=r"(r[30]), "=r"(r[31])
        : "r"(a));
#else
    #pragma unroll
    for (int i = 0; i < 32; i++) r[i] = 0;
    (void)a;
#endif
}

// ---------------- weight split pre-pass ----------------
__global__ void wsplit_kernel(const float4* __restrict__ in,
                              __half2* __restrict__ oh, __half2* __restrict__ ol, int n4) {
    int i = blockIdx.x * blockDim.x + threadIdx.x;
    if (i < n4) {
        float4 v = in[i];
        __half h0, l0, h1, l1, h2, l2, h3, l3;
        hsplit(v.x, h0, l0); hsplit(v.y, h1, l1);
        hsplit(v.z, h2, l2); hsplit(v.w, h3, l3);
        oh[2 * i]     = __halves2half2(h0, h1);
        oh[2 * i + 1] = __halves2half2(h2, h3);
        ol[2 * i]     = __halves2half2(l0, l1);
        ol[2 * i + 1] = __halves2half2(l2, l3);
    }
}

// ---------------- 1) gaussian conv + patchify + LN1 (planes out) ----------------
__device__ __forceinline__ float blockSum256(float v) {
    __shared__ float red[8];
    int lane = threadIdx.x & 31, w = threadIdx.x >> 5;
    __syncthreads();
    #pragma unroll
    for (int o = 16; o; o >>= 1) v += __shfl_down_sync(0xffffffffu, v, o);
    if (!lane) red[w] = v;
    __syncthreads();
    if (w == 0) {
        float r = (lane < 8) ? red[lane] : 0.f;
        #pragma unroll
        for (int o = 4; o; o >>= 1) r += __shfl_down_sync(0xffffffffu, r, o);
        if (!lane) red[0] = r;
    }
    __syncthreads();
    return red[0];
}

__global__ void patch_kernel(const float* __restrict__ in,
                             const float* __restrict__ lg,
                             const float* __restrict__ lb,
                             __half* __restrict__ oh, __half* __restrict__ ol) {
    __shared__ float gk[20];
    if (threadIdx.x == 0) {
        float tmp[20], s = 0.f;
        #pragma unroll
        for (int i = 0; i < 20; i++) {
            float z = ((float)i - 9.5f) * 0.5f;
            tmp[i] = expf(-0.5f * z * z);
            s += tmp[i];
        }
        #pragma unroll
        for (int i = 0; i < 20; i++) gk[i] = tmp[i] / s;
    }
    __syncthreads();

    int row = blockIdx.x;
    int b = row >> 9, n = row & 511;
    int f = threadIdx.x;
    const float* ib = in + (size_t)b * TLEN * PW + f;

    float vals[P1];
    #pragma unroll
    for (int p = 0; p < P1; p++) {
        int t = n * P1 + p;
        float acc = 0.f;
        #pragma unroll
        for (int k = 0; k < 20; k++) {
            int tt = t - 9 + k;
            if (tt >= 0 && tt < TLEN) acc += ib[(size_t)tt * PW] * gk[k];
        }
        vals[p] = acc;
    }
    float s = vals[0] + vals[1] + vals[2] + vals[3];
    float mean = blockSum256(s) * (1.f / 1024.f);
    float sq = 0.f;
    #pragma unroll
    for (int p = 0; p < P1; p++) { float d = vals[p] - mean; sq += d * d; }
    float var = blockSum256(sq) * (1.f / 1024.f);
    float inv = rsqrtf(var + 1e-5f);
    #pragma unroll
    for (int p = 0; p < P1; p++) {
        int e = p * PW + f;
        float o = (vals[p] - mean) * inv * lg[e] + lb[e];
        __half h, l;
        hsplit(o, h, l);
        oh[(size_t)row * DIMM + e] = h;
        ol[(size_t)row * DIMM + e] = l;
    }
}

// ---------------- 2) LayerNorm over D=1024, warp-per-row (8 rows/CTA) ----------------
template <int PACK>
__global__ __launch_bounds__(256)
void ln_kernel(const float* __restrict__ in, void* __restrict__ o1,
               void* __restrict__ o2,
               const float* __restrict__ g, const float* __restrict__ b) {
    int wid = threadIdx.x >> 5, lane = threadIdx.x & 31;
    int row = blockIdx.x * 8 + wid;
    const float* x = in + (size_t)row * DIMM;

    float4 v[8];
    float s = 0.f;
    #pragma unroll
    for (int i = 0; i < 8; i++) {
        v[i] = *(const float4*)(x + lane * 4 + i * 128);
        s += v[i].x + v[i].y + v[i].z + v[i].w;
    }
    #pragma unroll
    for (int o = 16; o; o >>= 1) s += __shfl_xor_sync(0xffffffffu, s, o);
    float mean = s * (1.f / 1024.f);

    float sq = 0.f;
    #pragma unroll
    for (int i = 0; i < 8; i++) {
        v[i].x -= mean; v[i].y -= mean; v[i].z -= mean; v[i].w -= mean;
        sq += v[i].x * v[i].x + v[i].y * v[i].y + v[i].z * v[i].z + v[i].w * v[i].w;
    }
    #pragma unroll
    for (int o = 16; o; o >>= 1) sq += __shfl_xor_sync(0xffffffffu, sq, o);
    float inv = rsqrtf(sq * (1.f / 1024.f) + 1e-5f);

    #pragma unroll
    for (int i = 0; i < 8; i++) {
        int c = lane * 4 + i * 128;
        float4 gv = *(const float4*)(g + c), bv = *(const float4*)(b + c);
        float ox = v[i].x * inv * gv.x + bv.x;
        float oy = v[i].y * inv * gv.y + bv.y;
        float oz = v[i].z * inv * gv.z + bv.z;
        float ow = v[i].w * inv * gv.w + bv.w;
        if (PACK) {
            __half h0, l0, h1, l1, h2, l2, h3, l3;
            hsplit(ox, h0, l0); hsplit(oy, h1, l1);
            hsplit(oz, h2, l2); hsplit(ow, h3, l3);
            size_t idx = ((size_t)row * DIMM + c) >> 1;
            ((__half2*)o1)[idx]     = __halves2half2(h0, h1);
            ((__half2*)o1)[idx + 1] = __halves2half2(h2, h3);
            ((__half2*)o2)[idx]     = __halves2half2(l0, l1);
            ((__half2*)o2)[idx + 1] = __halves2half2(l2, l3);
        } else {
            *(float4*)((float*)o1 + (size_t)row * DIMM + c) = make_float4(ox, oy, oz, ow);
        }
    }
}

// ---------------- 3a) tcgen05 split-FP16 GEMM, narrow (NT=64, K64 chunks, SW128) ----------------
#define ATILE 16384            // 128 rows * 128 B
template <int NT, int MODE>
__global__ __launch_bounds__(128, (NT == 64) ? 2 : 1)
void tgemm_tc(const __half* __restrict__ Ah, const __half* __restrict__ Al,
              const __half* __restrict__ Bh, const __half* __restrict__ Bl,
              const float* __restrict__ bias, const float* __restrict__ R,
              float* __restrict__ Cf, __half* __restrict__ Ch, __half* __restrict__ Cl,
              int M, int N, int K) {
#if HAS_TC
    constexpr int BTILE = NT * 128;
    constexpr int BUF   = 2 * ATILE + 2 * BTILE;
    constexpr uint32_t IDESC = (1u << 4) | ((NT / 8) << 17) | (8u << 24);
    constexpr uint32_t TCOLS = (NT < 64) ? 64 : NT;

    extern __shared__ __align__(1024) uint8_t smraw[];
    uint32_t sbase = (uint32_t)__cvta_generic_to_shared(smraw);
    uint32_t s0 = (sbase + 1023) & ~1023u;
    uint32_t tmem_slot = s0, mb[2] = { s0 + 8, s0 + 16 };
    uint32_t tiles = s0 + 1024;

    int t = threadIdx.x, wid = t >> 5, lid = t & 31;
    int m0 = blockIdx.y * 128, n0 = blockIdx.x * NT;

    if (wid == 0) tc_alloc(tmem_slot, TCOLS);
    if (t == 0) { mbar_init(mb[0], 1); mbar_init(mb[1], 1); }
    __syncthreads();
    uint32_t tmem;
    asm volatile("ld.shared.b32 %0, [%1];" : "=r"(tmem) : "r"(tmem_slot));

    int T = K >> 6;

    auto fill = [&](int c) {
        int b = c & 1;
        int k0 = c * 64;
        uint32_t bb = tiles + b * BUF;
        #pragma unroll 4
        for (int idx = t; idx < 128 * 8; idx += 128) {
            int row = idx >> 3, u = idx & 7;
            uint32_t soff = sw128(row * 128 + u * 16);
            size_t goff = (size_t)(m0 + row) * K + k0 + u * 8;
            cp16s(bb + soff, Ah + goff);
            cp16s(bb + ATILE + soff, Al + goff);
        }
        #pragma unroll 4
        for (int idx = t; idx < NT * 8; idx += 128) {
            int row = idx >> 3, u = idx & 7;
            uint32_t soff = sw128(row * 128 + u * 16);
            size_t goff = (size_t)(n0 + row) * K + k0 + u * 8;
            cp16s(bb + 2 * ATILE + soff, Bh + goff);
            cp16s(bb + 2 * ATILE + BTILE + soff, Bl + goff);
        }
        asm volatile("cp.async.commit_group;\n");
    };

    int ph[2] = { 0, 0 };
    fill(0);
    if (T > 1) fill(1);

    for (int c = 0; c < T; c++) {
        int b = c & 1;
        if (c + 1 < T) asm volatile("cp.async.wait_group 1;\n");
        else           asm volatile("cp.async.wait_group 0;\n");
        __syncthreads();

        if (t == 0) {
            asm volatile("fence.proxy.async.shared::cta;" ::: "memory");
            uint32_t bb = tiles + b * BUF;
            uint64_t dAh = sdesc(bb);
            uint64_t dAl = sdesc(bb + ATILE);
            uint64_t dBh = sdesc(bb + 2 * ATILE);
            uint64_t dBl = sdesc(bb + 2 * ATILE + BTILE);
            #pragma unroll
            for (int k = 0; k < 4; k++) {
                uint32_t en0 = (c == 0 && k == 0) ? 0u : 1u;
                tc_mma_f16_ss(tmem, dAl + k * 2, dBh + k * 2, IDESC, en0);
                tc_mma_f16_ss(tmem, dAh + k * 2, dBl + k * 2, IDESC, 1u);
                tc_mma_f16_ss(tmem, dAh + k * 2, dBh + k * 2, IDESC, 1u);
            }
            tc_commit(mb[b]);
        }

        if (c + 2 < T) {
            mbar_wait(mb[b], ph[b]);
            ph[b] ^= 1;
            fill(c + 2);
        }
    }

    {
        int b2 = (T - 2) & 1, b1 = (T - 1) & 1;
        mbar_wait(mb[b2], ph[b2]); ph[b2] ^= 1;
        mbar_wait(mb[b1], ph[b1]); ph[b1] ^= 1;
    }
    asm volatile("tcgen05.fence::after_thread_sync;" ::: "memory");

    int row = m0 + wid * 32 + lid;
    #pragma unroll 1
    for (int cb = 0; cb < NT / 32; cb++) {
        uint32_t r[32];
        tmem_ld32(r, tmem + cb * 32);
        asm volatile("tcgen05.wait::ld.sync.aligned;" ::: "memory");
        int nb = n0 + cb * 32;
        float v[32];
        #pragma unroll
        for (int c = 0; c < 32; c++)
            v[c] = __uint_as_float(r[c]) + (bias ? bias[nb + c] : 0.f);
        if (MODE == 1) {
            #pragma unroll
            for (int c4 = 0; c4 < 32; c4 += 4) {
                float4 rv = *(const float4*)(R + (size_t)row * N + nb + c4);
                v[c4] += rv.x; v[c4 + 1] += rv.y; v[c4 + 2] += rv.z; v[c4 + 3] += rv.w;
            }
        }
        if (MODE <= 1) {
            #pragma unroll
            for (int c4 = 0; c4 < 32; c4 += 4)
                *(float4*)(Cf + (size_t)row * N + nb + c4) =
                    make_float4(v[c4], v[c4 + 1], v[c4 + 2], v[c4 + 3]);
        } else {
            __align__(16) __half hh[32], hl[32];
            #pragma unroll
            for (int c = 0; c < 32; c++) {
                float gx = gelu_exact(v[c]);
                hsplit(gx, hh[c], hl[c]);
            }
            #pragma unroll
            for (int q = 0; q < 4; q++) {
                *(uint4*)(Ch + (size_t)row * N + nb + q * 8) = *(uint4*)&hh[q * 8];
                *(uint4*)(Cl + (size_t)row * N + nb + q * 8) = *(uint4*)&hl[q * 8];
            }
        }
    }

    __syncthreads();
    if (wid == 0) tc_dealloc(tmem, TCOLS);
#endif
}

// ---------------- 3a') tcgen05 wide GEMM: NT=256, K32 chunks, SW64, 2 CTAs/SM ----------------
#define A32   8192             // 128 rows * 64 B per plane
#define B32   16384            // 256 rows * 64 B per plane
#define BUF32 (2 * A32 + 2 * B32)  // 49152
template <int MODE>
__global__ __launch_bounds__(128, 2)
void tgemm_tcw(const __half* __restrict__ Ah, const __half* __restrict__ Al,
               const __half* __restrict__ Bh, const __half* __restrict__ Bl,
               const float* __restrict__ bias, const float* __restrict__ R,
               float* __restrict__ Cf, __half* __restrict__ Ch, __half* __restrict__ Cl,
               int M, int N, int K) {
#if HAS_TC
    constexpr int NT = 256;
    constexpr uint32_t IDESC = (1u << 4) | ((NT / 8) << 17) | (8u << 24);

    extern __shared__ __align__(1024) uint8_t smraw[];
    uint32_t sbase = (uint32_t)__cvta_generic_to_shared(smraw);
    uint32_t s0 = (sbase + 1023) & ~1023u;
    uint32_t tmem_slot = s0, mb[2] = { s0 + 8, s0 + 16 };
    uint32_t tiles = s0 + 1024;

    int t = threadIdx.x, wid = t >> 5, lid = t & 31;
    int m0 = blockIdx.y * 128, n0 = blockIdx.x * NT;

    if (wid == 0) tc_alloc(tmem_slot, 256);
    if (t == 0) { mbar_init(mb[0], 1); mbar_init(mb[1], 1); }
    __syncthreads();
    uint32_t tmem;
    asm volatile("ld.shared.b32 %0, [%1];" : "=r"(tmem) : "r"(tmem_slot));

    int T = K >> 5;                                 // K/32 chunks

    auto fill = [&](int c) {
        int b = c & 1;
        int k0 = c * 32;
        uint32_t bb = tiles + b * BUF32;
        // A planes: 128 rows x 4 16B-chunks
        #pragma unroll 4
        for (int idx = t; idx < 128 * 4; idx += 128) {
            int row = idx >> 2, u = idx & 3;
            uint32_t soff = sw64(row * 64 + u * 16);
            size_t goff = (size_t)(m0 + row) * K + k0 + u * 8;
            cp16s(bb + soff, Ah + goff);
            cp16s(bb + A32 + soff, Al + goff);
        }
        // B planes: 256 rows x 4 16B-chunks
        #pragma unroll 8
        for (int idx = t; idx < NT * 4; idx += 128) {
            int row = idx >> 2, u = idx & 3;
            uint32_t soff = sw64(row * 64 + u * 16);
            size_t goff = (size_t)(n0 + row) * K + k0 + u * 8;
            cp16s(bb + 2 * A32 + soff, Bh + goff);
            cp16s(bb + 2 * A32 + B32 + soff, Bl + goff);
        }
        asm volatile("cp.async.commit_group;\n");
    };

    int ph[2] = { 0, 0 };
    fill(0);
    if (T > 1) fill(1);

    for (int c = 0; c < T; c++) {
        int b = c & 1;
        if (c + 1 < T) asm volatile("cp.async.wait_group 1;\n");
        else           asm volatile("cp.async.wait_group 0;\n");
        __syncthreads();

        if (t == 0) {
            asm volatile("fence.proxy.async.shared::cta;" ::: "memory");
            uint32_t bb = tiles + b * BUF32;
            uint64_t dAh = sdesc64(bb);
            uint64_t dAl = sdesc64(bb + A32);
            uint64_t dBh = sdesc64(bb + 2 * A32);
            uint64_t dBl = sdesc64(bb + 2 * A32 + B32);
            #pragma unroll
            for (int k = 0; k < 2; k++) {           // two K16 steps per K32 chunk
                uint32_t en0 = (c == 0 && k == 0) ? 0u : 1u;
                tc_mma_f16_ss(tmem, dAl + k * 2, dBh + k * 2, IDESC, en0);
                tc_mma_f16_ss(tmem, dAh + k * 2, dBl + k * 2, IDESC, 1u);
                tc_mma_f16_ss(tmem, dAh + k * 2, dBh + k * 2, IDESC, 1u);
            }
            tc_commit(mb[b]);
        }

        if (c + 2 < T) {
            mbar_wait(mb[b], ph[b]);
            ph[b] ^= 1;
            fill(c + 2);
        }
    }

    {
        int b2 = (T - 2) & 1, b1 = (T - 1) & 1;
        mbar_wait(mb[b2], ph[b2]); ph[b2] ^= 1;
        mbar_wait(mb[b1], ph[b1]); ph[b1] ^= 1;
    }
    asm volatile("tcgen05.fence::after_thread_sync;" ::: "memory");

    int row = m0 + wid * 32 + lid;
    #pragma unroll 1
    for (int cb = 0; cb < NT / 32; cb++) {
        uint32_t r[32];
        tmem_ld32(r, tmem + cb * 32);
        asm volatile("tcgen05.wait::ld.sync.aligned;" ::: "memory");
        int nb = n0 + cb * 32;
        float v[32];
        #pragma unroll
        for (int c = 0; c < 32; c++)
            v[c] = __uint_as_float(r[c]) + (bias ? bias[nb + c] : 0.f);
        if (MODE <= 1) {
            #pragma unroll
            for (int c4 = 0; c4 < 32; c4 += 4)
                *(float4*)(Cf + (size_t)row * N + nb + c4) =
                    make_float4(v[c4], v[c4 + 1], v[c4 + 2], v[c4 + 3]);
        } else {
            __align__(16) __half hh[32], hl[32];
            #pragma unroll
            for (int c = 0; c < 32; c++) {
                float gx = gelu_exact(v[c]);
                hsplit(gx, hh[c], hl[c]);
            }
            #pragma unroll
            for (int q = 0; q < 4; q++) {
                *(uint4*)(Ch + (size_t)row * N + nb + q * 8) = *(uint4*)&hh[q * 8];
                *(uint4*)(Cl + (size_t)row * N + nb + q * 8) = *(uint4*)&hl[q * 8];
            }
        }
    }

    __syncthreads();
    if (wid == 0) tc_dealloc(tmem, 256);
#endif
}

// ---------------- 3b) legacy mma.sync split-FP16 GEMM (fallback) ----------------
__device__ __forceinline__ void mma_f16(float* c, const uint32_t* a, const uint32_t* b) {
    asm volatile(
        "mma.sync.aligned.m16n8k16.row.col.f32.f16.f16.f32 "
        "{%0,%1,%2,%3}, {%4,%5,%6,%7}, {%8,%9}, {%0,%1,%2,%3};"
        : "+f"(c[0]), "+f"(c[1]), "+f"(c[2]), "+f"(c[3])
        : "r"(a[0]), "r"(a[1]), "r"(a[2]), "r"(a[3]), "r"(b[0]), "r"(b[1]));
}

#define LG_PLANE 5120
#define LG_STAGE (4 * LG_PLANE)
#define LG_SMEM  (2 * LG_STAGE * 2)

template <int GELU, int RES, int PACK>
__global__ __launch_bounds__(256)
void tgemm_lg(const __half* __restrict__ Ah, const __half* __restrict__ Al,
              const __half* __restrict__ Bh, const __half* __restrict__ Bl,
              const float* __restrict__ bias, const float* __restrict__ R,
              float* __restrict__ Cf, __half* __restrict__ Ch, __half* __restrict__ Cl,
              int M, int N, int K) {
    extern __shared__ __half smh[];
    uint32_t sbase_u = (uint32_t)__cvta_generic_to_shared(smh);
    int m0 = blockIdx.y * 128, n0 = blockIdx.x * 128;
    int t = threadIdx.x, lane = t & 31, wid = t >> 5;
    int g = lane >> 2, tig = lane & 3;
    int warp_m = wid & 1, warp_n = wid >> 1;

    float acc[4][4][4];
    #pragma unroll
    for (int i = 0; i < 4; i++)
        #pragma unroll
        for (int j = 0; j < 4; j++)
            #pragma unroll
            for (int r = 0; r < 4; r++) acc[i][j][r] = 0.f;

    int T = K >> 5;
    const __half* gsrc[4] = { Ah, Al, Bh, Bl };

    auto fill = [&](int tt) {
        int st = tt & 1;
        int k0 = tt * 32;
        #pragma unroll
        for (int pl = 0; pl < 4; pl++) {
            int rbase = (pl < 2) ? m0 : n0;
            uint32_t dst = sbase_u + (uint32_t)(st * LG_STAGE + pl * LG_PLANE) * 2;
            const __half* src = gsrc[pl] + (size_t)rbase * K + k0;
            #pragma unroll
            for (int q = 0; q < 2; q++) {
                int cidx = t + 256 * q;
                int row = cidx >> 2, seg = cidx & 3;
                cp16s(dst + (uint32_t)(row * 40 + seg * 8) * 2,
                      src + (size_t)row * K + seg * 8);
            }
        }
        asm volatile("cp.async.commit_group;\n");
    };

    fill(0);
    for (int tt = 0; tt < T; tt++) {
        if (tt + 1 < T) { fill(tt + 1); asm volatile("cp.async.wait_group 1;\n"); }
        else            { asm volatile("cp.async.wait_group 0;\n"); }
        __syncthreads();

        const uint32_t* S   = (const uint32_t*)smh + (tt & 1) * (LG_STAGE / 2);
        const uint32_t* SAh = S;
        const uint32_t* SAl = S + LG_PLANE / 2;
        const uint32_t* SWh = S + LG_PLANE;
        const uint32_t* SWl = S + 3 * (LG_PLANE / 2);
        int am = warp_m * 64, bn = warp_n * 32;

        #pragma unroll
        for (int ks = 0; ks < 2; ks++) {
            int kw = ks * 8 + tig;
            uint32_t ah[4][4], al[4][4], bh[4][2], bl[4][2];
            #pragma unroll
            for (int i = 0; i < 4; i++) {
                int r = am + i * 16 + g;
                ah[i][0] = SAh[r * 20 + kw];       ah[i][1] = SAh[(r + 8) * 20 + kw];
                ah[i][2] = SAh[r * 20 + kw + 4];   ah[i][3] = SAh[(r + 8) * 20 + kw + 4];
                al[i][0] = SAl[r * 20 + kw];       al[i][1] = SAl[(r + 8) * 20 + kw];
                al[i][2] = SAl[r * 20 + kw + 4];   al[i][3] = SAl[(r + 8) * 20 + kw + 4];
            }
            #pragma unroll
            for (int j = 0; j < 4; j++) {
                int c = bn + j * 8 + g;
                bh[j][0] = SWh[c * 20 + kw];  bh[j][1] = SWh[c * 20 + kw + 4];
                bl[j][0] = SWl[c * 20 + kw];  bl[j][1] = SWl[c * 20 + kw + 4];
            }
            #pragma unroll
            for (int i = 0; i < 4; i++)
                #pragma unroll
                for (int j = 0; j < 4; j++) {
                    mma_f16(acc[i][j], al[i], bh[j]);
                    mma_f16(acc[i][j], ah[i], bl[j]);
                    mma_f16(acc[i][j], ah[i], bh[j]);
                }
        }
        __syncthreads();
    }

    int m_base = m0 + warp_m * 64;
    int n_base = n0 + warp_n * 32;
    #pragma unroll
    for (int i = 0; i < 4; i++) {
        int r0 = m_base + i * 16 + g;
        int r1 = r0 + 8;
        #pragma unroll
        for (int j = 0; j < 4; j++) {
            int cc = n_base + j * 8 + tig * 2;
            float b0 = bias ? bias[cc] : 0.f;
            float b1 = bias ? bias[cc + 1] : 0.f;
            float v00 = acc[i][j][0] + b0, v01 = acc[i][j][1] + b1;
            float v10 = acc[i][j][2] + b0, v11 = acc[i][j][3] + b1;
            if (GELU) {
                v00 = gelu_exact(v00); v01 = gelu_exact(v01);
                v10 = gelu_exact(v10); v11 = gelu_exact(v11);
            }
            if (RES) {
                const float2 rv0 = *(const float2*)(R + (size_t)r0 * N + cc);
                const float2 rv1 = *(const float2*)(R + (size_t)r1 * N + cc);
                v00 += rv0.x; v01 += rv0.y; v10 += rv1.x; v11 += rv1.y;
            }
            if (PACK) {
                __half h00, l00, h01, l01, h10, l10, h11, l11;
                hsplit(v00, h00, l00); hsplit(v01, h01, l01);
                hsplit(v10, h10, l10); hsplit(v11, h11, l11);
                *(__half2*)(Ch + (size_t)r0 * N + cc) = __halves2half2(h00, h01);
                *(__half2*)(Ch + (size_t)r1 * N + cc) = __halves2half2(h10, h11);
                *(__half2*)(Cl + (size_t)r0 * N + cc) = __halves2half2(l00, l01);
                *(__half2*)(Cl + (size_t)r1 * N + cc) = __halves2half2(l10, l11);
            } else {
                *(float2*)(Cf + (size_t)r0 * N + cc) = make_float2(v00, v01);
                *(float2*)(Cf + (size_t)r1 * N + cc) = make_float2(v10, v11);
            }
        }
    }
}

// ---------------- 4) fused causal attention (flash-style, f32x2 math) ----------------
__global__ __launch_bounds__(128)
void attn_kernel(const float* __restrict__ qkv, const float* __restrict__ rel,
                 __half* __restrict__ oh, __half* __restrict__ ol) {
    __shared__ __align__(16) float ks[32][64];
    __shared__ __align__(16) float vs[32][64];
    __shared__ float relsm[RELN];

    int qt = blockIdx.x, h = blockIdx.y, b = blockIdx.z;
    int i_glob = qt * 128 + threadIdx.x;
    const float* base = qkv + (size_t)b * NPATCH * QKVD;

    uint32_t ks_base = (uint32_t)__cvta_generic_to_shared(ks);
    uint32_t vs_base = (uint32_t)__cvta_generic_to_shared(vs);

    for (int r = threadIdx.x; r < RELN; r += 128) relsm[r] = rel[r];

    uint64_t q2[32];
    {
        const float* qp = base + (size_t)i_glob * QKVD + h * DH;
        #pragma unroll
        for (int d = 0; d < 16; d++) {
            float4 t4 = *(const float4*)(qp + 4 * d);
            q2[2 * d]     = pk2(t4.x, t4.y);
            q2[2 * d + 1] = pk2(t4.z, t4.w);
        }
    }

    uint64_t O2[32];
    #pragma unroll
    for (int d = 0; d < 32; d++) O2[d] = 0ull;
    float mrun = -1e30f, lsum = 0.f;

    int jmax = qt * 128 + 128;
    for (int j0 = 0; j0 < jmax; j0 += 32) {
        __syncthreads();
        #pragma unroll
        for (int i = 0; i < 4; i++) {
            int f = threadIdx.x + 128 * i;
            int jr = f >> 4, dc = (f & 15) * 4;
            const float* kp = base + (size_t)(j0 + jr) * QKVD + INNERD + h * DH + dc;
            const float* vp = base + (size_t)(j0 + jr) * QKVD + 2 * INNERD + h * DH + dc;
            *(float4*)&ks[jr][dc] = *(const float4*)kp;
            *(float4*)&vs[jr][dc] = *(const float4*)vp;
        }
        __syncthreads();

        if (j0 <= i_glob) {
            float s[32];
            #pragma unroll
            for (int j = 0; j < 32; j++) {
                uint64_t acc2 = 0ull;
                uint32_t a = ks_base + j * 256;
                #pragma unroll
                for (int d = 0; d < 16; d++) {
                    uint64_t p0, p1;
                    lds2u64(a + d * 16, p0, p1);
                    acc2 = fma2p(q2[2 * d], p0, acc2);
                    acc2 = fma2p(q2[2 * d + 1], p1, acc2);
                }
                float lo, hi;
                upk2(acc2, lo, hi);
                float sc = lo + hi;
                int delta = i_glob - (j0 + j);
                if (delta < 0) s[j] = -1e30f;
                else           s[j] = sc * 0.125f + relsm[min(delta, 199) + 199];
            }
            float mnew = mrun;
            #pragma unroll
            for (int j = 0; j < 32; j++) mnew = fmaxf(mnew, s[j]);
            float corr = expf(mrun - mnew);
            lsum *= corr;
            uint64_t corr2 = pk2(corr, corr);
            #pragma unroll
            for (int d = 0; d < 32; d++) O2[d] = mul2p(O2[d], corr2);
            #pragma unroll
            for (int j = 0; j < 32; j++) {
                float p = expf(s[j] - mnew);
                lsum += p;
                uint64_t pp = pk2(p, p);
                uint32_t a = vs_base + j * 256;
                #pragma unroll
                for (int d = 0; d < 16; d++) {
                    uint64_t p0, p1;
                    lds2u64(a + d * 16, p0, p1);
                    O2[2 * d]     = fma2p(pp, p0, O2[2 * d]);
                    O2[2 * d + 1] = fma2p(pp, p1, O2[2 * d + 1]);
                }
            }
            mrun = mnew;
        }
    }

    float inv = 1.f / lsum;
    size_t obase = ((size_t)b * NPATCH + i_glob) * DIMM + h * DH;
    #pragma unroll
    for (int d = 0; d < 32; d++) {
        float lo, hi;
        upk2(O2[d], lo, hi);
        float a0 = lo * inv, a1 = hi * inv;
        __half h0, l0, h1, l1;
        hsplit(a0, h0, l0); hsplit(a1, h1, l1);
        *(__half2*)(oh + obase + 2 * d) = __halves2half2(h0, h1);
        *(__half2*)(ol + obase + 2 * d) = __halves2half2(l0, l1);
    }
}

// ---------------- 5) projection head ----------------
__global__ void proj_kernel(const float* __restrict__ x, const float* __restrict__ W,
                            const float* __restrict__ bias, float* __restrict__ out) {
    __shared__ float xs[DIMM];
    int row = blockIdx.x;
    const float* xr = x + (size_t)row * DIMM;
    for (int c = threadIdx.x * 4; c < DIMM; c += 1024)
        *(float4*)&xs[c] = *(const float4*)(xr + c);
    __syncthreads();
    int w = threadIdx.x >> 5, lane = threadIdx.x & 31;
    for (int o = w; o < NCLS; o += 8) {
        const float* wr = W + (size_t)o * DIMM;
        float acc = 0.f;
        for (int d = lane * 4; d < DIMM; d += 128) {
            float4 xv = *(const float4*)&xs[d];
            float4 wv = *(const float4*)(wr + d);
            acc += xv.x * wv.x + xv.y * wv.y + xv.z * wv.z + xv.w * wv.w;
        }
        #pragma unroll
        for (int off = 16; off; off >>= 1) acc += __shfl_down_sync(0xffffffffu, acc, off);
        if (!lane) out[(size_t)row * NCLS + o] = acc + bias[o];
    }
}

// ---------------- launch ----------------
#define SMEM64  (2048 + 2 * (2 * ATILE + 2 * 64 * 128))    // 100352 -> 2 CTAs/SM
#define SMEMW   (2048 + 2 * BUF32)                         // 100352 -> 2 CTAs/SM

extern "C" void kernel_launch(void* const* d_in, const int* in_sizes, int n_in,
                              void* d_out, int out_size) {
    const float* neuralInput  = (const float*)d_in[0];
    const float* patch_ln1_g  = (const float*)d_in[1];
    const float* patch_ln1_b  = (const float*)d_in[2];
    const float* patch_w      = (const float*)d_in[3];
    const float* patch_b      = (const float*)d_in[4];
    const float* patch_ln2_g  = (const float*)d_in[5];
    const float* patch_ln2_b  = (const float*)d_in[6];
    const float* attn_ln_g    = (const float*)d_in[7];
    const float* attn_ln_b    = (const float*)d_in[8];
    const float* qkv_w        = (const float*)d_in[9];
    const float* out_w        = (const float*)d_in[10];
    const float* out_b        = (const float*)d_in[11];
    const float* rel_tab      = (const float*)d_in[12];
    const float* ffn_ln_g     = (const float*)d_in[13];
    const float* ffn_ln_b     = (const float*)d_in[14];
    const float* ffn_w1       = (const float*)d_in[15];
    const float* ffn_b1       = (const float*)d_in[16];
    const float* ffn_w2       = (const float*)d_in[17];
    const float* ffn_b2       = (const float*)d_in[18];
    const float* final_ln_g   = (const float*)d_in[19];
    const float* final_ln_b   = (const float*)d_in[20];
    const float* proj_w       = (const float*)d_in[21];
    const float* proj_b       = (const float*)d_in[22];

    float *px, *pqkv;
    __half *lnh, *lnl, *aoh, *aol, *fh, *fl;
    __half *wph, *wpl, *wqh, *wql, *woh, *wol, *w1h, *w1l, *w2h, *w2l;
    cudaGetSymbolAddress((void**)&px,   g_x);
    cudaGetSymbolAddress((void**)&pqkv, g_qkv);
    cudaGetSymbolAddress((void**)&lnh,  g_lnh);
    cudaGetSymbolAddress((void**)&lnl,  g_lnl);
    cudaGetSymbolAddress((void**)&aoh,  g_aoh);
    cudaGetSymbolAddress((void**)&aol,  g_aol);
    cudaGetSymbolAddress((void**)&fh,   g_fh);
    cudaGetSymbolAddress((void**)&fl,   g_fl);
    cudaGetSymbolAddress((void**)&wph,  g_wph);
    cudaGetSymbolAddress((void**)&wpl,  g_wpl);
    cudaGetSymbolAddress((void**)&wqh,  g_wqh);
    cudaGetSymbolAddress((void**)&wql,  g_wql);
    cudaGetSymbolAddress((void**)&woh,  g_woh);
    cudaGetSymbolAddress((void**)&wol,  g_wol);
    cudaGetSymbolAddress((void**)&w1h,  g_w1h);
    cudaGetSymbolAddress((void**)&w1l,  g_w1l);
    cudaGetSymbolAddress((void**)&w2h,  g_w2h);
    cudaGetSymbolAddress((void**)&w2l,  g_w2l);

    // Which binary variant got loaded? (static smem of probe differs by arch feature)
    bool use_tc = false;
    {
        cudaFuncAttributes a;
        if (cudaFuncGetAttributes(&a, probe_kernel) == cudaSuccess)
            use_tc = (a.sharedSizeBytes >= 8192);
    }

    if (use_tc) {
        cudaFuncSetAttribute(tgemm_tcw<0>, cudaFuncAttributeMaxDynamicSharedMemorySize, SMEMW);
        cudaFuncSetAttribute(tgemm_tcw<2>, cudaFuncAttributeMaxDynamicSharedMemorySize, SMEMW);
        cudaFuncSetAttribute(tgemm_tc<64, 0>, cudaFuncAttributeMaxDynamicSharedMemorySize, SMEM64);
        cudaFuncSetAttribute(tgemm_tc<64, 1>, cudaFuncAttributeMaxDynamicSharedMemorySize, SMEM64);
    } else {
        cudaFuncSetAttribute(tgemm_lg<0, 0, 0>, cudaFuncAttributeMaxDynamicSharedMemorySize, LG_SMEM);
        cudaFuncSetAttribute(tgemm_lg<0, 1, 0>, cudaFuncAttributeMaxDynamicSharedMemorySize, LG_SMEM);
        cudaFuncSetAttribute(tgemm_lg<1, 0, 1>, cudaFuncAttributeMaxDynamicSharedMemorySize, LG_SMEM);
    }

    // weight split pre-pass
    {
        int n;
        n = DIMM * DIMM / 4;
        wsplit_kernel<<<(n + 255) / 256, 256>>>((const float4*)patch_w, (__half2*)wph, (__half2*)wpl, n);
        n = DEPTH * QKVD * DIMM / 4;
        wsplit_kernel<<<(n + 255) / 256, 256>>>((const float4*)qkv_w, (__half2*)wqh, (__half2*)wql, n);
        n = DEPTH * DIMM * INNERD / 4;
        wsplit_kernel<<<(n + 255) / 256, 256>>>((const float4*)out_w, (__half2*)woh, (__half2*)wol, n);
        n = DEPTH * MLPD * DIMM / 4;
        wsplit_kernel<<<(n + 255) / 256, 256>>>((const float4*)ffn_w1, (__half2*)w1h, (__half2*)w1l, n);
        wsplit_kernel<<<(n + 255) / 256, 256>>>((const float4*)ffn_w2, (__half2*)w2h, (__half2*)w2l, n);
    }

    patch_kernel<<<NROWS, 256>>>(neuralInput, patch_ln1_g, patch_ln1_b, lnh, lnl);

    // patch linear -> fp32 temp (g_qkv), then LN2 -> fp32 residual g_x
    if (use_tc)
        tgemm_tc<64, 0><<<dim3(DIMM / 64, NROWS / 128), 128, SMEM64>>>(
            lnh, lnl, wph, wpl, patch_b, nullptr, pqkv, nullptr, nullptr, NROWS, DIMM, DIMM);
    else
        tgemm_lg<0, 0, 0><<<dim3(DIMM / 128, NROWS / 128), 256, LG_SMEM>>>(
            lnh, lnl, wph, wpl, patch_b, nullptr, pqkv, nullptr, nullptr, NROWS, DIMM, DIMM);
    ln_kernel<0><<<NROWS / 8, 256>>>(pqkv, px, nullptr, patch_ln2_g, patch_ln2_b);

    for (int l = 0; l < DEPTH; l++) {
        // attention block
        ln_kernel<1><<<NROWS / 8, 256>>>(px, lnh, lnl, attn_ln_g + l * DIMM, attn_ln_b + l * DIMM);
        if (use_tc)
            tgemm_tcw<0><<<dim3(QKVD / 256, NROWS / 128), 128, SMEMW>>>(
                lnh, lnl, wqh + (size_t)l * QKVD * DIMM, wql + (size_t)l * QKVD * DIMM,
                nullptr, nullptr, pqkv, nullptr, nullptr, NROWS, QKVD, DIMM);
        else
            tgemm_lg<0, 0, 0><<<dim3(QKVD / 128, NROWS / 128), 256, LG_SMEM>>>(
                lnh, lnl, wqh + (size_t)l * QKVD * DIMM, wql + (size_t)l * QKVD * DIMM,
                nullptr, nullptr, pqkv, nullptr, nullptr, NROWS, QKVD, DIMM);
        attn_kernel<<<dim3(NPATCH / 128, HEADS, BATCH), 128>>>(
            pqkv, rel_tab + (size_t)l * RELN, aoh, aol);
        if (use_tc)
            tgemm_tc<64, 1><<<dim3(DIMM / 64, NROWS / 128), 128, SMEM64>>>(
                aoh, aol, woh + (size_t)l * DIMM * INNERD, wol + (size_t)l * DIMM * INNERD,
                out_b + (size_t)l * DIMM, px, px, nullptr, nullptr, NROWS, DIMM, INNERD);
        else
            tgemm_lg<0, 1, 0><<<dim3(DIMM / 128, NROWS / 128), 256, LG_SMEM>>>(
                aoh, aol, woh + (size_t)l * DIMM * INNERD, wol + (size_t)l * DIMM * INNERD,
                out_b + (size_t)l * DIMM, px, px, nullptr, nullptr, NROWS, DIMM, INNERD);
        // ffn block
        ln_kernel<1><<<NROWS / 8, 256>>>(px, lnh, lnl, ffn_ln_g + l * DIMM, ffn_ln_b + l * DIMM);
        if (use_tc)
            tgemm_tcw<2><<<dim3(MLPD / 256, NROWS / 128), 128, SMEMW>>>(
                lnh, lnl, w1h + (size_t)l * MLPD * DIMM, w1l + (size_t)l * MLPD * DIMM,
                ffn_b1 + (size_t)l * MLPD, nullptr, nullptr, fh, fl, NROWS, MLPD, DIMM);
        else
            tgemm_lg<1, 0, 1><<<dim3(MLPD / 128, NROWS / 128), 256, LG_SMEM>>>(
                lnh, lnl, w1h + (size_t)l * MLPD * DIMM, w1l + (size_t)l * MLPD * DIMM,
                ffn_b1 + (size_t)l * MLPD, nullptr, nullptr, fh, fl, NROWS, MLPD, DIMM);
        if (use_tc)
            tgemm_tc<64, 1><<<dim3(DIMM / 64, NROWS / 128), 128, SMEM64>>>(
                fh, fl, w2h + (size_t)l * DIMM * MLPD, w2l + (size_t)l * DIMM * MLPD,
                ffn_b2 + (size_t)l * DIMM, px, px, nullptr, nullptr, NROWS, DIMM, MLPD);
        else
            tgemm_lg<0, 1, 0><<<dim3(DIMM / 128, NROWS / 128), 256, LG_SMEM>>>(
                fh, fl, w2h + (size_t)l * DIMM * MLPD, w2l + (size_t)l * DIMM * MLPD,
                ffn_b2 + (size_t)l * DIMM, px, px, nullptr, nullptr, NROWS, DIMM, MLPD);
    }

    // final LN (fp32 into g_qkv) + projection
    ln_kernel<0><<<NROWS / 8, 256>>>(px, pqkv, nullptr, final_ln_g, final_ln_b);
    proj_kernel<<<NROWS, 256>>>(pqkv, proj_w, proj_b, (float*)d_out);
}

// round 16
// speedup vs baseline: 1.2304x; 1.1031x over previous
#include <cuda_runtime.h>
#include <cuda_fp16.h>
#include <math.h>
#include <stdint.h>

// ---------------- problem constants ----------------
#define BATCH   4
#define TLEN    2048
#define PW      256
#define P1      4
#define NPATCH  512          // TLEN/P1
#define NROWS   2048         // BATCH*NPATCH
#define DIMM    1024
#define HEADS   16
#define DH      64
#define INNERD  1024         // HEADS*DH
#define QKVD    3072
#define MLPD    4096
#define DEPTH   12
#define NCLS    41           // NCLS+1
#define RELN    399          // 2*MAXREL-1

// arch-feature gate: tcgen05 only exists on sm_100a/sm_103a-class targets
#if defined(__CUDA_ARCH_FEAT_SM103_ALL) || defined(__CUDA_ARCH_FEAT_SM100_ALL) || defined(__CUDA_ARCH_FEAT_SM101_ALL)
#define HAS_TC 1
#else
#define HAS_TC 0
#endif

// ---------------- scratch (device globals; allocation-free) ----------------
__device__ float g_x  [(size_t)NROWS*DIMM];     // fp32 residual stream
__device__ float g_qkv[(size_t)NROWS*QKVD];     // fp32 qkv + generic fp32 temp

// activation hi/lo fp16 planes
__device__ __half g_lnh[(size_t)NROWS*DIMM];
__device__ __half g_lnl[(size_t)NROWS*DIMM];
__device__ __half g_aoh[(size_t)NROWS*DIMM];
__device__ __half g_aol[(size_t)NROWS*DIMM];
__device__ __half g_fh [(size_t)NROWS*MLPD];
__device__ __half g_fl [(size_t)NROWS*MLPD];

// weight hi/lo fp16 planes
__device__ __half g_wph[(size_t)DIMM*DIMM];
__device__ __half g_wpl[(size_t)DIMM*DIMM];
__device__ __half g_wqh[(size_t)DEPTH*QKVD*DIMM];
__device__ __half g_wql[(size_t)DEPTH*QKVD*DIMM];
__device__ __half g_woh[(size_t)DEPTH*DIMM*INNERD];
__device__ __half g_wol[(size_t)DEPTH*DIMM*INNERD];
__device__ __half g_w1h[(size_t)DEPTH*MLPD*DIMM];
__device__ __half g_w1l[(size_t)DEPTH*MLPD*DIMM];
__device__ __half g_w2h[(size_t)DEPTH*DIMM*MLPD];
__device__ __half g_w2l[(size_t)DEPTH*DIMM*MLPD];

// ---------------- generic helpers ----------------
__device__ __forceinline__ void hsplit(float x, __half& h, __half& l) {
    h = __float2half_rn(x);
    l = __float2half_rn(x - __half2float(h));
}

__device__ __forceinline__ float gelu_exact(float x) {
    return 0.5f * x * (1.f + erff(x * 0.70710678118654752f));
}

__device__ __forceinline__ void cp16s(uint32_t s, const void* g) {
    asm volatile("cp.async.cg.shared.global [%0], [%1], 16;\n" :: "r"(s), "l"(g));
}

// packed f32x2 helpers (sm_100+)
__device__ __forceinline__ uint64_t pk2(float lo, float hi) {
    uint64_t d;
    asm("mov.b64 %0, {%1, %2};" : "=l"(d) : "f"(lo), "f"(hi));
    return d;
}
__device__ __forceinline__ void upk2(uint64_t v, float& lo, float& hi) {
    asm("mov.b64 {%0, %1}, %2;" : "=f"(lo), "=f"(hi) : "l"(v));
}
__device__ __forceinline__ uint64_t fma2p(uint64_t a, uint64_t b, uint64_t c) {
    uint64_t d;
    asm("fma.rn.f32x2 %0, %1, %2, %3;" : "=l"(d) : "l"(a), "l"(b), "l"(c));
    return d;
}
__device__ __forceinline__ uint64_t mul2p(uint64_t a, uint64_t b) {
    uint64_t d;
    asm("mul.rn.f32x2 %0, %1, %2;" : "=l"(d) : "l"(a), "l"(b));
    return d;
}
__device__ __forceinline__ void lds2u64(uint32_t a, uint64_t& p0, uint64_t& p1) {
    asm("ld.shared.v2.u64 {%0, %1}, [%2];" : "=l"(p0), "=l"(p1) : "r"(a));
}

// ---------------- arch probe: static smem size differs by feature ----------------
__global__ void probe_kernel(float* out) {
#if HAS_TC
    __shared__ volatile float s[2048];            // 8192 bytes static smem
    s[threadIdx.x] = 1.f;
    __syncthreads();
    if (out) out[0] = s[threadIdx.x ^ 1];
#else
    if (out) out[0] = 0.f;
#endif
}

// ---------------- tcgen05 helpers (guarded) ----------------
__device__ __forceinline__ uint32_t sw128(uint32_t off) {
    return off ^ ((off >> 3) & 0x70);
}
__device__ __forceinline__ uint32_t sw64(uint32_t off) {
    return off ^ ((off >> 3) & 0x30);
}

__device__ __forceinline__ uint64_t sdesc(uint32_t saddr) {        // SW128 K-major
    return (2ull << 61) | (1ull << 46) | (64ull << 32) | (1ull << 16)
         | ((uint64_t)(saddr >> 4) & 0x3FFF);
}
__device__ __forceinline__ uint64_t sdesc64(uint32_t saddr) {      // SW64 K-major
    return (4ull << 61) | (1ull << 46) | (32ull << 32) | (1ull << 16)
         | ((uint64_t)(saddr >> 4) & 0x3FFF);
}

__device__ __forceinline__ void mbar_init(uint32_t a, uint32_t cnt) {
    asm volatile("mbarrier.init.shared.b64 [%0], %1;" :: "r"(a), "r"(cnt) : "memory");
}

__device__ __forceinline__ void mbar_wait(uint32_t a, int phase) {
    asm volatile(
        "{\n\t.reg .pred P;\n"
        "W_%=:\n\t"
        "mbarrier.try_wait.parity.shared.b64 P, [%0], %1;\n\t"
        "@P bra D_%=;\n\t"
        "bra W_%=;\n"
        "D_%=:\n\t}"
        :: "r"(a), "r"(phase) : "memory");
}

__device__ __forceinline__ void tc_alloc(uint32_t slot, uint32_t ncols) {
#if HAS_TC
    asm volatile("tcgen05.alloc.cta_group::1.sync.aligned.shared::cta.b32 [%0], %1;"
                 :: "r"(slot), "r"(ncols) : "memory");
    asm volatile("tcgen05.relinquish_alloc_permit.cta_group::1.sync.aligned;");
#endif
}

__device__ __forceinline__ void tc_dealloc(uint32_t tmem, uint32_t ncols) {
#if HAS_TC
    asm volatile("tcgen05.dealloc.cta_group::1.sync.aligned.b32 %0, %1;"
                 :: "r"(tmem), "r"(ncols));
#endif
}

__device__ __forceinline__ void tc_mma_f16_ss(uint32_t d, uint64_t a_desc, uint64_t b_desc,
                                              uint32_t idesc, uint32_t en) {
#if HAS_TC
    asm volatile(
        "{\n\t.reg .pred p;\n\t"
        "setp.ne.u32 p, %5, 0;\n\t"
        "tcgen05.mma.cta_group::1.kind::f16 [%0], %1, %2, %3, {%4, %4, %4, %4}, p;\n\t}"
        :: "r"(d), "l"(a_desc), "l"(b_desc), "r"(idesc), "r"(0u), "r"(en) : "memory");
#endif
}

__device__ __forceinline__ void tc_commit(uint32_t mbar) {
#if HAS_TC
    asm volatile("tcgen05.commit.cta_group::1.mbarrier::arrive::one.shared::cluster.b64 [%0];"
                 :: "r"(mbar) : "memory");
#endif
}

__device__ __forceinline__ void tmem_ld32(uint32_t* r, uint32_t a) {
#if HAS_TC
    asm volatile(
        "tcgen05.ld.sync.aligned.32x32b.x32.b32 "
        "{%0, %1, %2, %3, %4, %5, %6, %7, "
        " %8, %9, %10, %11, %12, %13, %14, %15, "
        " %16, %17, %18, %19, %20, %21, %22, %23, "
        " %24, %25, %26, %27, %28, %29, %30, %31}, [%32];"
        : "=r"(r[0]),  "=r"(r[1]),  "=r"(r[2]),  "=r"(r[3]),
          "=r"(r[4]),  "=r"(r[5]),  "=r"(r[6]),  "=r"(r[7]),
          "=r"(r[8]),  "=r"(r[9]),  "=r"(r[10]), "=r"(r[11]),
          "=r"(r[12]), "=r"(r[13]), "=r"(r[14]), "=r"(r[15]),
          "=r"(r[16]), "=r"(r[17]), "=r"(r[18]), "=r"(r[19]),
          "=r"(r[20]), "=r"(r[21]), "=r"(r[22]), "=r"(r[23]),
          "=r"(r[24]), "=r"(r[25]), "=r"(r[26]), "=r"(r[27]),
          "=r"(r[28]), "=r"(r[29]), "=r"(r[30]), "=r"(r[31])
        : "r"(a));
#else
    #pragma unroll
    for (int i = 0; i < 32; i++) r[i] = 0;
    (void)a;
#endif
}

// ---------------- weight split pre-pass ----------------
__global__ void wsplit_kernel(const float4* __restrict__ in,
                              __half2* __restrict__ oh, __half2* __restrict__ ol, int n4) {
    int i = blockIdx.x * blockDim.x + threadIdx.x;
    if (i < n4) {
        float4 v = in[i];
        __half h0, l0, h1, l1, h2, l2, h3, l3;
        hsplit(v.x, h0, l0); hsplit(v.y, h1, l1);
        hsplit(v.z, h2, l2); hsplit(v.w, h3, l3);
        oh[2 * i]     = __halves2half2(h0, h1);
        oh[2 * i + 1] = __halves2half2(h2, h3);
        ol[2 * i]     = __halves2half2(l0, l1);
        ol[2 * i + 1] = __halves2half2(l2, l3);
    }
}

// ---------------- 1) gaussian conv + patchify + LN1 (planes out) ----------------
__device__ __forceinline__ float blockSum256(float v) {
    __shared__ float red[8];
    int lane = threadIdx.x & 31, w = threadIdx.x >> 5;
    __syncthreads();
    #pragma unroll
    for (int o = 16; o; o >>= 1) v += __shfl_down_sync(0xffffffffu, v, o);
    if (!lane) red[w] = v;
    __syncthreads();
    if (w == 0) {
        float r = (lane < 8) ? red[lane] : 0.f;
        #pragma unroll
        for (int o = 4; o; o >>= 1) r += __shfl_down_sync(0xffffffffu, r, o);
        if (!lane) red[0] = r;
    }
    __syncthreads();
    return red[0];
}

__global__ void patch_kernel(const float* __restrict__ in,
                             const float* __restrict__ lg,
                             const float* __restrict__ lb,
                             __half* __restrict__ oh, __half* __restrict__ ol) {
    __shared__ float gk[20];
    if (threadIdx.x == 0) {
        float tmp[20], s = 0.f;
        #pragma unroll
        for (int i = 0; i < 20; i++) {
            float z = ((float)i - 9.5f) * 0.5f;
            tmp[i] = expf(-0.5f * z * z);
            s += tmp[i];
        }
        #pragma unroll
        for (int i = 0; i < 20; i++) gk[i] = tmp[i] / s;
    }
    __syncthreads();

    int row = blockIdx.x;
    int b = row >> 9, n = row & 511;
    int f = threadIdx.x;
    const float* ib = in + (size_t)b * TLEN * PW + f;

    float vals[P1];
    #pragma unroll
    for (int p = 0; p < P1; p++) {
        int t = n * P1 + p;
        float acc = 0.f;
        #pragma unroll
        for (int k = 0; k < 20; k++) {
            int tt = t - 9 + k;
            if (tt >= 0 && tt < TLEN) acc += ib[(size_t)tt * PW] * gk[k];
        }
        vals[p] = acc;
    }
    float s = vals[0] + vals[1] + vals[2] + vals[3];
    float mean = blockSum256(s) * (1.f / 1024.f);
    float sq = 0.f;
    #pragma unroll
    for (int p = 0; p < P1; p++) { float d = vals[p] - mean; sq += d * d; }
    float var = blockSum256(sq) * (1.f / 1024.f);
    float inv = rsqrtf(var + 1e-5f);
    #pragma unroll
    for (int p = 0; p < P1; p++) {
        int e = p * PW + f;
        float o = (vals[p] - mean) * inv * lg[e] + lb[e];
        __half h, l;
        hsplit(o, h, l);
        oh[(size_t)row * DIMM + e] = h;
        ol[(size_t)row * DIMM + e] = l;
    }
}

// ---------------- 2) LayerNorm over D=1024, warp-per-row (8 rows/CTA) ----------------
template <int PACK>
__global__ __launch_bounds__(256)
void ln_kernel(const float* __restrict__ in, void* __restrict__ o1,
               void* __restrict__ o2,
               const float* __restrict__ g, const float* __restrict__ b) {
    int wid = threadIdx.x >> 5, lane = threadIdx.x & 31;
    int row = blockIdx.x * 8 + wid;
    const float* x = in + (size_t)row * DIMM;

    float4 v[8];
    float s = 0.f;
    #pragma unroll
    for (int i = 0; i < 8; i++) {
        v[i] = *(const float4*)(x + lane * 4 + i * 128);
        s += v[i].x + v[i].y + v[i].z + v[i].w;
    }
    #pragma unroll
    for (int o = 16; o; o >>= 1) s += __shfl_xor_sync(0xffffffffu, s, o);
    float mean = s * (1.f / 1024.f);

    float sq = 0.f;
    #pragma unroll
    for (int i = 0; i < 8; i++) {
        v[i].x -= mean; v[i].y -= mean; v[i].z -= mean; v[i].w -= mean;
        sq += v[i].x * v[i].x + v[i].y * v[i].y + v[i].z * v[i].z + v[i].w * v[i].w;
    }
    #pragma unroll
    for (int o = 16; o; o >>= 1) sq += __shfl_xor_sync(0xffffffffu, sq, o);
    float inv = rsqrtf(sq * (1.f / 1024.f) + 1e-5f);

    #pragma unroll
    for (int i = 0; i < 8; i++) {
        int c = lane * 4 + i * 128;
        float4 gv = *(const float4*)(g + c), bv = *(const float4*)(b + c);
        float ox = v[i].x * inv * gv.x + bv.x;
        float oy = v[i].y * inv * gv.y + bv.y;
        float oz = v[i].z * inv * gv.z + bv.z;
        float ow = v[i].w * inv * gv.w + bv.w;
        if (PACK) {
            __half h0, l0, h1, l1, h2, l2, h3, l3;
            hsplit(ox, h0, l0); hsplit(oy, h1, l1);
            hsplit(oz, h2, l2); hsplit(ow, h3, l3);
            size_t idx = ((size_t)row * DIMM + c) >> 1;
            ((__half2*)o1)[idx]     = __halves2half2(h0, h1);
            ((__half2*)o1)[idx + 1] = __halves2half2(h2, h3);
            ((__half2*)o2)[idx]     = __halves2half2(l0, l1);
            ((__half2*)o2)[idx + 1] = __halves2half2(l2, l3);
        } else {
            *(float4*)((float*)o1 + (size_t)row * DIMM + c) = make_float4(ox, oy, oz, ow);
        }
    }
}

// ---------------- 3a) tcgen05 split-FP16 GEMM, narrow (NT=64, K64 chunks, SW128) ----------------
// SA = number of A planes (2 = hi/lo split, 1 = hi only).
#define ATILE 16384            // 128 rows * 128 B
template <int NT, int MODE, int SA>
__global__ __launch_bounds__(128, 2)
void tgemm_tc(const __half* __restrict__ Ah, const __half* __restrict__ Al,
              const __half* __restrict__ Bh, const __half* __restrict__ Bl,
              const float* __restrict__ bias, const float* __restrict__ R,
              float* __restrict__ Cf, __half* __restrict__ Ch, __half* __restrict__ Cl,
              int M, int N, int K) {
#if HAS_TC
    constexpr int BTILE = NT * 128;
    constexpr int ABYTES = SA * ATILE;
    constexpr int BUF   = ABYTES + 2 * BTILE;
    constexpr uint32_t IDESC = (1u << 4) | ((NT / 8) << 17) | (8u << 24);
    constexpr uint32_t TCOLS = (NT < 64) ? 64 : NT;

    extern __shared__ __align__(1024) uint8_t smraw[];
    uint32_t sbase = (uint32_t)__cvta_generic_to_shared(smraw);
    uint32_t s0 = (sbase + 1023) & ~1023u;
    uint32_t tmem_slot = s0, mb[2] = { s0 + 8, s0 + 16 };
    uint32_t tiles = s0 + 1024;

    int t = threadIdx.x, wid = t >> 5, lid = t & 31;
    int m0 = blockIdx.y * 128, n0 = blockIdx.x * NT;

    if (wid == 0) tc_alloc(tmem_slot, TCOLS);
    if (t == 0) { mbar_init(mb[0], 1); mbar_init(mb[1], 1); }
    __syncthreads();
    uint32_t tmem;
    asm volatile("ld.shared.b32 %0, [%1];" : "=r"(tmem) : "r"(tmem_slot));

    int T = K >> 6;

    auto fill = [&](int c) {
        int b = c & 1;
        int k0 = c * 64;
        uint32_t bb = tiles + b * BUF;
        #pragma unroll 4
        for (int idx = t; idx < 128 * 8; idx += 128) {
            int row = idx >> 3, u = idx & 7;
            uint32_t soff = sw128(row * 128 + u * 16);
            size_t goff = (size_t)(m0 + row) * K + k0 + u * 8;
            cp16s(bb + soff, Ah + goff);
            if (SA == 2) cp16s(bb + ATILE + soff, Al + goff);
        }
        #pragma unroll 4
        for (int idx = t; idx < NT * 8; idx += 128) {
            int row = idx >> 3, u = idx & 7;
            uint32_t soff = sw128(row * 128 + u * 16);
            size_t goff = (size_t)(n0 + row) * K + k0 + u * 8;
            cp16s(bb + ABYTES + soff, Bh + goff);
            cp16s(bb + ABYTES + BTILE + soff, Bl + goff);
        }
        asm volatile("cp.async.commit_group;\n");
    };

    int ph[2] = { 0, 0 };
    fill(0);
    if (T > 1) fill(1);

    for (int c = 0; c < T; c++) {
        int b = c & 1;
        if (c + 1 < T) asm volatile("cp.async.wait_group 1;\n");
        else           asm volatile("cp.async.wait_group 0;\n");
        __syncthreads();

        if (t == 0) {
            asm volatile("fence.proxy.async.shared::cta;" ::: "memory");
            uint32_t bb = tiles + b * BUF;
            uint64_t dAh = sdesc(bb);
            uint64_t dAl = sdesc(bb + ATILE);
            uint64_t dBh = sdesc(bb + ABYTES);
            uint64_t dBl = sdesc(bb + ABYTES + BTILE);
            #pragma unroll
            for (int k = 0; k < 4; k++) {
                uint32_t en0 = (c == 0 && k == 0) ? 0u : 1u;
                if (SA == 2) {
                    tc_mma_f16_ss(tmem, dAl + k * 2, dBh + k * 2, IDESC, en0);
                    tc_mma_f16_ss(tmem, dAh + k * 2, dBl + k * 2, IDESC, 1u);
                } else {
                    tc_mma_f16_ss(tmem, dAh + k * 2, dBl + k * 2, IDESC, en0);
                }
                tc_mma_f16_ss(tmem, dAh + k * 2, dBh + k * 2, IDESC, 1u);
            }
            tc_commit(mb[b]);
        }

        if (c + 2 < T) {
            mbar_wait(mb[b], ph[b]);
            ph[b] ^= 1;
            fill(c + 2);
        }
    }

    {
        int b2 = (T - 2) & 1, b1 = (T - 1) & 1;
        mbar_wait(mb[b2], ph[b2]); ph[b2] ^= 1;
        mbar_wait(mb[b1], ph[b1]); ph[b1] ^= 1;
    }
    asm volatile("tcgen05.fence::after_thread_sync;" ::: "memory");

    int row = m0 + wid * 32 + lid;
    #pragma unroll 1
    for (int cb = 0; cb < NT / 32; cb++) {
        uint32_t r[32];
        tmem_ld32(r, tmem + cb * 32);
        asm volatile("tcgen05.wait::ld.sync.aligned;" ::: "memory");
        int nb = n0 + cb * 32;
        float v[32];
        #pragma unroll
        for (int c = 0; c < 32; c++)
            v[c] = __uint_as_float(r[c]) + (bias ? bias[nb + c] : 0.f);
        if (MODE == 1) {
            #pragma unroll
            for (int c4 = 0; c4 < 32; c4 += 4) {
                float4 rv = *(const float4*)(R + (size_t)row * N + nb + c4);
                v[c4] += rv.x; v[c4 + 1] += rv.y; v[c4 + 2] += rv.z; v[c4 + 3] += rv.w;
            }
        }
        if (MODE <= 1) {
            #pragma unroll
            for (int c4 = 0; c4 < 32; c4 += 4)
                *(float4*)(Cf + (size_t)row * N + nb + c4) =
                    make_float4(v[c4], v[c4 + 1], v[c4 + 2], v[c4 + 3]);
        } else {
            __align__(16) __half hh[32];
            #pragma unroll
            for (int c = 0; c < 32; c++)
                hh[c] = __float2half_rn(gelu_exact(v[c]));
            #pragma unroll
            for (int q = 0; q < 4; q++)
                *(uint4*)(Ch + (size_t)row * N + nb + q * 8) = *(uint4*)&hh[q * 8];
        }
    }

    __syncthreads();
    if (wid == 0) tc_dealloc(tmem, TCOLS);
#endif
}

// ---------------- 3a') tcgen05 wide GEMM: NT=256, K32 chunks, SW64, 2 CTAs/SM ----------------
#define A32   8192             // 128 rows * 64 B per plane
#define B32   16384            // 256 rows * 64 B per plane
#define BUF32 (2 * A32 + 2 * B32)  // 49152
template <int MODE>
__global__ __launch_bounds__(128, 2)
void tgemm_tcw(const __half* __restrict__ Ah, const __half* __restrict__ Al,
               const __half* __restrict__ Bh, const __half* __restrict__ Bl,
               const float* __restrict__ bias, const float* __restrict__ R,
               float* __restrict__ Cf, __half* __restrict__ Ch, __half* __restrict__ Cl,
               int M, int N, int K) {
#if HAS_TC
    constexpr int NT = 256;
    constexpr uint32_t IDESC = (1u << 4) | ((NT / 8) << 17) | (8u << 24);

    extern __shared__ __align__(1024) uint8_t smraw[];
    uint32_t sbase = (uint32_t)__cvta_generic_to_shared(smraw);
    uint32_t s0 = (sbase + 1023) & ~1023u;
    uint32_t tmem_slot = s0, mb[2] = { s0 + 8, s0 + 16 };
    uint32_t tiles = s0 + 1024;

    int t = threadIdx.x, wid = t >> 5, lid = t & 31;
    int m0 = blockIdx.y * 128, n0 = blockIdx.x * NT;

    if (wid == 0) tc_alloc(tmem_slot, 256);
    if (t == 0) { mbar_init(mb[0], 1); mbar_init(mb[1], 1); }
    __syncthreads();
    uint32_t tmem;
    asm volatile("ld.shared.b32 %0, [%1];" : "=r"(tmem) : "r"(tmem_slot));

    int T = K >> 5;                                 // K/32 chunks

    auto fill = [&](int c) {
        int b = c & 1;
        int k0 = c * 32;
        uint32_t bb = tiles + b * BUF32;
        #pragma unroll 4
        for (int idx = t; idx < 128 * 4; idx += 128) {
            int row = idx >> 2, u = idx & 3;
            uint32_t soff = sw64(row * 64 + u * 16);
            size_t goff = (size_t)(m0 + row) * K + k0 + u * 8;
            cp16s(bb + soff, Ah + goff);
            cp16s(bb + A32 + soff, Al + goff);
        }
        #pragma unroll 8
        for (int idx = t; idx < NT * 4; idx += 128) {
            int row = idx >> 2, u = idx & 3;
            uint32_t soff = sw64(row * 64 + u * 16);
            size_t goff = (size_t)(n0 + row) * K + k0 + u * 8;
            cp16s(bb + 2 * A32 + soff, Bh + goff);
            cp16s(bb + 2 * A32 + B32 + soff, Bl + goff);
        }
        asm volatile("cp.async.commit_group;\n");
    };

    int ph[2] = { 0, 0 };
    fill(0);
    if (T > 1) fill(1);

    for (int c = 0; c < T; c++) {
        int b = c & 1;
        if (c + 1 < T) asm volatile("cp.async.wait_group 1;\n");
        else           asm volatile("cp.async.wait_group 0;\n");
        __syncthreads();

        if (t == 0) {
            asm volatile("fence.proxy.async.shared::cta;" ::: "memory");
            uint32_t bb = tiles + b * BUF32;
            uint64_t dAh = sdesc64(bb);
            uint64_t dAl = sdesc64(bb + A32);
            uint64_t dBh = sdesc64(bb + 2 * A32);
            uint64_t dBl = sdesc64(bb + 2 * A32 + B32);
            #pragma unroll
            for (int k = 0; k < 2; k++) {
                uint32_t en0 = (c == 0 && k == 0) ? 0u : 1u;
                tc_mma_f16_ss(tmem, dAl + k * 2, dBh + k * 2, IDESC, en0);
                tc_mma_f16_ss(tmem, dAh + k * 2, dBl + k * 2, IDESC, 1u);
                tc_mma_f16_ss(tmem, dAh + k * 2, dBh + k * 2, IDESC, 1u);
            }
            tc_commit(mb[b]);
        }

        if (c + 2 < T) {
            mbar_wait(mb[b], ph[b]);
            ph[b] ^= 1;
            fill(c + 2);
        }
    }

    {
        int b2 = (T - 2) & 1, b1 = (T - 1) & 1;
        mbar_wait(mb[b2], ph[b2]); ph[b2] ^= 1;
        mbar_wait(mb[b1], ph[b1]); ph[b1] ^= 1;
    }
    asm volatile("tcgen05.fence::after_thread_sync;" ::: "memory");

    int row = m0 + wid * 32 + lid;
    #pragma unroll 1
    for (int cb = 0; cb < NT / 32; cb++) {
        uint32_t r[32];
        tmem_ld32(r, tmem + cb * 32);
        asm volatile("tcgen05.wait::ld.sync.aligned;" ::: "memory");
        int nb = n0 + cb * 32;
        float v[32];
        #pragma unroll
        for (int c = 0; c < 32; c++)
            v[c] = __uint_as_float(r[c]) + (bias ? bias[nb + c] : 0.f);
        if (MODE <= 1) {
            #pragma unroll
            for (int c4 = 0; c4 < 32; c4 += 4)
                *(float4*)(Cf + (size_t)row * N + nb + c4) =
                    make_float4(v[c4], v[c4 + 1], v[c4 + 2], v[c4 + 3]);
        } else {
            __align__(16) __half hh[32];
            #pragma unroll
            for (int c = 0; c < 32; c++)
                hh[c] = __float2half_rn(gelu_exact(v[c]));
            #pragma unroll
            for (int q = 0; q < 4; q++)
                *(uint4*)(Ch + (size_t)row * N + nb + q * 8) = *(uint4*)&hh[q * 8];
        }
    }

    __syncthreads();
    if (wid == 0) tc_dealloc(tmem, 256);
#endif
}

// ---------------- 3b) legacy mma.sync split-FP16 GEMM (fallback) ----------------
__device__ __forceinline__ void mma_f16(float* c, const uint32_t* a, const uint32_t* b) {
    asm volatile(
        "mma.sync.aligned.m16n8k16.row.col.f32.f16.f16.f32 "
        "{%0,%1,%2,%3}, {%4,%5,%6,%7}, {%8,%9}, {%0,%1,%2,%3};"
        : "+f"(c[0]), "+f"(c[1]), "+f"(c[2]), "+f"(c[3])
        : "r"(a[0]), "r"(a[1]), "r"(a[2]), "r"(a[3]), "r"(b[0]), "r"(b[1]));
}

#define LG_PLANE 5120
#define LG_STAGE (4 * LG_PLANE)
#define LG_SMEM  (2 * LG_STAGE * 2)

template <int GELU, int RES, int PACK>
__global__ __launch_bounds__(256)
void tgemm_lg(const __half* __restrict__ Ah, const __half* __restrict__ Al,
              const __half* __restrict__ Bh, const __half* __restrict__ Bl,
              const float* __restrict__ bias, const float* __restrict__ R,
              float* __restrict__ Cf, __half* __restrict__ Ch, __half* __restrict__ Cl,
              int M, int N, int K) {
    extern __shared__ __half smh[];
    uint32_t sbase_u = (uint32_t)__cvta_generic_to_shared(smh);
    int m0 = blockIdx.y * 128, n0 = blockIdx.x * 128;
    int t = threadIdx.x, lane = t & 31, wid = t >> 5;
    int g = lane >> 2, tig = lane & 3;
    int warp_m = wid & 1, warp_n = wid >> 1;

    float acc[4][4][4];
    #pragma unroll
    for (int i = 0; i < 4; i++)
        #pragma unroll
        for (int j = 0; j < 4; j++)
            #pragma unroll
            for (int r = 0; r < 4; r++) acc[i][j][r] = 0.f;

    int T = K >> 5;
    const __half* gsrc[4] = { Ah, Al, Bh, Bl };

    auto fill = [&](int tt) {
        int st = tt & 1;
        int k0 = tt * 32;
        #pragma unroll
        for (int pl = 0; pl < 4; pl++) {
            int rbase = (pl < 2) ? m0 : n0;
            uint32_t dst = sbase_u + (uint32_t)(st * LG_STAGE + pl * LG_PLANE) * 2;
            const __half* src = gsrc[pl] + (size_t)rbase * K + k0;
            #pragma unroll
            for (int q = 0; q < 2; q++) {
                int cidx = t + 256 * q;
                int row = cidx >> 2, seg = cidx & 3;
                cp16s(dst + (uint32_t)(row * 40 + seg * 8) * 2,
                      src + (size_t)row * K + seg * 8);
            }
        }
        asm volatile("cp.async.commit_group;\n");
    };

    fill(0);
    for (int tt = 0; tt < T; tt++) {
        if (tt + 1 < T) { fill(tt + 1); asm volatile("cp.async.wait_group 1;\n"); }
        else            { asm volatile("cp.async.wait_group 0;\n"); }
        __syncthreads();

        const uint32_t* S   = (const uint32_t*)smh + (tt & 1) * (LG_STAGE / 2);
        const uint32_t* SAh = S;
        const uint32_t* SAl = S + LG_PLANE / 2;
        const uint32_t* SWh = S + LG_PLANE;
        const uint32_t* SWl = S + 3 * (LG_PLANE / 2);
        int am = warp_m * 64, bn = warp_n * 32;

        #pragma unroll
        for (int ks = 0; ks < 2; ks++) {
            int kw = ks * 8 + tig;
            uint32_t ah[4][4], al[4][4], bh[4][2], bl[4][2];
            #pragma unroll
            for (int i = 0; i < 4; i++) {
                int r = am + i * 16 + g;
                ah[i][0] = SAh[r * 20 + kw];       ah[i][1] = SAh[(r + 8) * 20 + kw];
                ah[i][2] = SAh[r * 20 + kw + 4];   ah[i][3] = SAh[(r + 8) * 20 + kw + 4];
                al[i][0] = SAl[r * 20 + kw];       al[i][1] = SAl[(r + 8) * 20 + kw];
                al[i][2] = SAl[r * 20 + kw + 4];   al[i][3] = SAl[(r + 8) * 20 + kw + 4];
            }
            #pragma unroll
            for (int j = 0; j < 4; j++) {
                int c = bn + j * 8 + g;
                bh[j][0] = SWh[c * 20 + kw];  bh[j][1] = SWh[c * 20 + kw + 4];
                bl[j][0] = SWl[c * 20 + kw];  bl[j][1] = SWl[c * 20 + kw + 4];
            }
            #pragma unroll
            for (int i = 0; i < 4; i++)
                #pragma unroll
                for (int j = 0; j < 4; j++) {
                    mma_f16(acc[i][j], al[i], bh[j]);
                    mma_f16(acc[i][j], ah[i], bl[j]);
                    mma_f16(acc[i][j], ah[i], bh[j]);
                }
        }
        __syncthreads();
    }

    int m_base = m0 + warp_m * 64;
    int n_base = n0 + warp_n * 32;
    #pragma unroll
    for (int i = 0; i < 4; i++) {
        int r0 = m_base + i * 16 + g;
        int r1 = r0 + 8;
        #pragma unroll
        for (int j = 0; j < 4; j++) {
            int cc = n_base + j * 8 + tig * 2;
            float b0 = bias ? bias[cc] : 0.f;
            float b1 = bias ? bias[cc + 1] : 0.f;
            float v00 = acc[i][j][0] + b0, v01 = acc[i][j][1] + b1;
            float v10 = acc[i][j][2] + b0, v11 = acc[i][j][3] + b1;
            if (GELU) {
                v00 = gelu_exact(v00); v01 = gelu_exact(v01);
                v10 = gelu_exact(v10); v11 = gelu_exact(v11);
            }
            if (RES) {
                const float2 rv0 = *(const float2*)(R + (size_t)r0 * N + cc);
                const float2 rv1 = *(const float2*)(R + (size_t)r1 * N + cc);
                v00 += rv0.x; v01 += rv0.y; v10 += rv1.x; v11 += rv1.y;
            }
            if (PACK) {
                __half h00, l00, h01, l01, h10, l10, h11, l11;
                hsplit(v00, h00, l00); hsplit(v01, h01, l01);
                hsplit(v10, h10, l10); hsplit(v11, h11, l11);
                *(__half2*)(Ch + (size_t)r0 * N + cc) = __halves2half2(h00, h01);
                *(__half2*)(Ch + (size_t)r1 * N + cc) = __halves2half2(h10, h11);
                *(__half2*)(Cl + (size_t)r0 * N + cc) = __halves2half2(l00, l01);
                *(__half2*)(Cl + (size_t)r1 * N + cc) = __halves2half2(l10, l11);
            } else {
                *(float2*)(Cf + (size_t)r0 * N + cc) = make_float2(v00, v01);
                *(float2*)(Cf + (size_t)r1 * N + cc) = make_float2(v10, v11);
            }
        }
    }
}

// ---------------- 4) fused causal attention (flash-style, f32x2 math) ----------------
__global__ __launch_bounds__(128)
void attn_kernel(const float* __restrict__ qkv, const float* __restrict__ rel,
                 __half* __restrict__ oh, __half* __restrict__ ol) {
    __shared__ __align__(16) float ks[32][64];
    __shared__ __align__(16) float vs[32][64];
    __shared__ float relsm[RELN];

    int qt = blockIdx.x, h = blockIdx.y, b = blockIdx.z;
    int i_glob = qt * 128 + threadIdx.x;
    const float* base = qkv + (size_t)b * NPATCH * QKVD;

    uint32_t ks_base = (uint32_t)__cvta_generic_to_shared(ks);
    uint32_t vs_base = (uint32_t)__cvta_generic_to_shared(vs);

    for (int r = threadIdx.x; r < RELN; r += 128) relsm[r] = rel[r];

    uint64_t q2[32];
    {
        const float* qp = base + (size_t)i_glob * QKVD + h * DH;
        #pragma unroll
        for (int d = 0; d < 16; d++) {
            float4 t4 = *(const float4*)(qp + 4 * d);
            q2[2 * d]     = pk2(t4.x, t4.y);
            q2[2 * d + 1] = pk2(t4.z, t4.w);
        }
    }

    uint64_t O2[32];
    #pragma unroll
    for (int d = 0; d < 32; d++) O2[d] = 0ull;
    float mrun = -1e30f, lsum = 0.f;

    int jmax = qt * 128 + 128;
    for (int j0 = 0; j0 < jmax; j0 += 32) {
        __syncthreads();
        #pragma unroll
        for (int i = 0; i < 4; i++) {
            int f = threadIdx.x + 128 * i;
            int jr = f >> 4, dc = (f & 15) * 4;
            const float* kp = base + (size_t)(j0 + jr) * QKVD + INNERD + h * DH + dc;
            const float* vp = base + (size_t)(j0 + jr) * QKVD + 2 * INNERD + h * DH + dc;
            *(float4*)&ks[jr][dc] = *(const float4*)kp;
            *(float4*)&vs[jr][dc] = *(const float4*)vp;
        }
        __syncthreads();

        if (j0 <= i_glob) {
            float s[32];
            #pragma unroll
            for (int j = 0; j < 32; j++) {
                uint64_t acc2 = 0ull;
                uint32_t a = ks_base + j * 256;
                #pragma unroll
                for (int d = 0; d < 16; d++) {
                    uint64_t p0, p1;
                    lds2u64(a + d * 16, p0, p1);
                    acc2 = fma2p(q2[2 * d], p0, acc2);
                    acc2 = fma2p(q2[2 * d + 1], p1, acc2);
                }
                float lo, hi;
                upk2(acc2, lo, hi);
                float sc = lo + hi;
                int delta = i_glob - (j0 + j);
                if (delta < 0) s[j] = -1e30f;
                else           s[j] = sc * 0.125f + relsm[min(delta, 199) + 199];
            }
            float mnew = mrun;
            #pragma unroll
            for (int j = 0; j < 32; j++) mnew = fmaxf(mnew, s[j]);
            float corr = expf(mrun - mnew);
            lsum *= corr;
            uint64_t corr2 = pk2(corr, corr);
            #pragma unroll
            for (int d = 0; d < 32; d++) O2[d] = mul2p(O2[d], corr2);
            #pragma unroll
            for (int j = 0; j < 32; j++) {
                float p = expf(s[j] - mnew);
                lsum += p;
                uint64_t pp = pk2(p, p);
                uint32_t a = vs_base + j * 256;
                #pragma unroll
                for (int d = 0; d < 16; d++) {
                    uint64_t p0, p1;
                    lds2u64(a + d * 16, p0, p1);
                    O2[2 * d]     = fma2p(pp, p0, O2[2 * d]);
                    O2[2 * d + 1] = fma2p(pp, p1, O2[2 * d + 1]);
                }
            }
            mrun = mnew;
        }
    }

    float inv = 1.f / lsum;
    size_t obase = ((size_t)b * NPATCH + i_glob) * DIMM + h * DH;
    #pragma unroll
    for (int d = 0; d < 32; d++) {
        float lo, hi;
        upk2(O2[d], lo, hi);
        float a0 = lo * inv, a1 = hi * inv;
        __half h0, l0, h1, l1;
        hsplit(a0, h0, l0); hsplit(a1, h1, l1);
        *(__half2*)(oh + obase + 2 * d) = __halves2half2(h0, h1);
        *(__half2*)(ol + obase + 2 * d) = __halves2half2(l0, l1);
    }
}

// ---------------- 5) projection head ----------------
__global__ void proj_kernel(const float* __restrict__ x, const float* __restrict__ W,
                            const float* __restrict__ bias, float* __restrict__ out) {
    __shared__ float xs[DIMM];
    int row = blockIdx.x;
    const float* xr = x + (size_t)row * DIMM;
    for (int c = threadIdx.x * 4; c < DIMM; c += 1024)
        *(float4*)&xs[c] = *(const float4*)(xr + c);
    __syncthreads();
    int w = threadIdx.x >> 5, lane = threadIdx.x & 31;
    for (int o = w; o < NCLS; o += 8) {
        const float* wr = W + (size_t)o * DIMM;
        float acc = 0.f;
        for (int d = lane * 4; d < DIMM; d += 128) {
            float4 xv = *(const float4*)&xs[d];
            float4 wv = *(const float4*)(wr + d);
            acc += xv.x * wv.x + xv.y * wv.y + xv.z * wv.z + xv.w * wv.w;
        }
        #pragma unroll
        for (int off = 16; off; off >>= 1) acc += __shfl_down_sync(0xffffffffu, acc, off);
        if (!lane) out[(size_t)row * NCLS + o] = acc + bias[o];
    }
}

// ---------------- launch ----------------
#define SMEM64A2 (2048 + 2 * (2 * ATILE + 2 * 64 * 128))   // 100352
#define SMEM64A1 (2048 + 2 * (1 * ATILE + 2 * 64 * 128))   // 67584
#define SMEMW    (2048 + 2 * BUF32)                        // 100352

extern "C" void kernel_launch(void* const* d_in, const int* in_sizes, int n_in,
                              void* d_out, int out_size) {
    const float* neuralInput  = (const float*)d_in[0];
    const float* patch_ln1_g  = (const float*)d_in[1];
    const float* patch_ln1_b  = (const float*)d_in[2];
    const float* patch_w      = (const float*)d_in[3];
    const float* patch_b      = (const float*)d_in[4];
    const float* patch_ln2_g  = (const float*)d_in[5];
    const float* patch_ln2_b  = (const float*)d_in[6];
    const float* attn_ln_g    = (const float*)d_in[7];
    const float* attn_ln_b    = (const float*)d_in[8];
    const float* qkv_w        = (const float*)d_in[9];
    const float* out_w        = (const float*)d_in[10];
    const float* out_b        = (const float*)d_in[11];
    const float* rel_tab      = (const float*)d_in[12];
    const float* ffn_ln_g     = (const float*)d_in[13];
    const float* ffn_ln_b     = (const float*)d_in[14];
    const float* ffn_w1       = (const float*)d_in[15];
    const float* ffn_b1       = (const float*)d_in[16];
    const float* ffn_w2       = (const float*)d_in[17];
    const float* ffn_b2       = (const float*)d_in[18];
    const float* final_ln_g   = (const float*)d_in[19];
    const float* final_ln_b   = (const float*)d_in[20];
    const float* proj_w       = (const float*)d_in[21];
    const float* proj_b       = (const float*)d_in[22];

    float *px, *pqkv;
    __half *lnh, *lnl, *aoh, *aol, *fh, *fl;
    __half *wph, *wpl, *wqh, *wql, *woh, *wol, *w1h, *w1l, *w2h, *w2l;
    cudaGetSymbolAddress((void**)&px,   g_x);
    cudaGetSymbolAddress((void**)&pqkv, g_qkv);
    cudaGetSymbolAddress((void**)&lnh,  g_lnh);
    cudaGetSymbolAddress((void**)&lnl,  g_lnl);
    cudaGetSymbolAddress((void**)&aoh,  g_aoh);
    cudaGetSymbolAddress((void**)&aol,  g_aol);
    cudaGetSymbolAddress((void**)&fh,   g_fh);
    cudaGetSymbolAddress((void**)&fl,   g_fl);
    cudaGetSymbolAddress((void**)&wph,  g_wph);
    cudaGetSymbolAddress((void**)&wpl,  g_wpl);
    cudaGetSymbolAddress((void**)&wqh,  g_wqh);
    cudaGetSymbolAddress((void**)&wql,  g_wql);
    cudaGetSymbolAddress((void**)&woh,  g_woh);
    cudaGetSymbolAddress((void**)&wol,  g_wol);
    cudaGetSymbolAddress((void**)&w1h,  g_w1h);
    cudaGetSymbolAddress((void**)&w1l,  g_w1l);
    cudaGetSymbolAddress((void**)&w2h,  g_w2h);
    cudaGetSymbolAddress((void**)&w2l,  g_w2l);

    // Which binary variant got loaded? (static smem of probe differs by arch feature)
    bool use_tc = false;
    {
        cudaFuncAttributes a;
        if (cudaFuncGetAttributes(&a, probe_kernel) == cudaSuccess)
            use_tc = (a.sharedSizeBytes >= 8192);
    }

    if (use_tc) {
        cudaFuncSetAttribute(tgemm_tcw<0>, cudaFuncAttributeMaxDynamicSharedMemorySize, SMEMW);
        cudaFuncSetAttribute(tgemm_tcw<2>, cudaFuncAttributeMaxDynamicSharedMemorySize, SMEMW);
        cudaFuncSetAttribute(tgemm_tc<64, 0, 2>, cudaFuncAttributeMaxDynamicSharedMemorySize, SMEM64A2);
        cudaFuncSetAttribute(tgemm_tc<64, 1, 1>, cudaFuncAttributeMaxDynamicSharedMemorySize, SMEM64A1);
    } else {
        cudaFuncSetAttribute(tgemm_lg<0, 0, 0>, cudaFuncAttributeMaxDynamicSharedMemorySize, LG_SMEM);
        cudaFuncSetAttribute(tgemm_lg<0, 1, 0>, cudaFuncAttributeMaxDynamicSharedMemorySize, LG_SMEM);
        cudaFuncSetAttribute(tgemm_lg<1, 0, 1>, cudaFuncAttributeMaxDynamicSharedMemorySize, LG_SMEM);
    }

    // weight split pre-pass
    {
        int n;
        n = DIMM * DIMM / 4;
        wsplit_kernel<<<(n + 255) / 256, 256>>>((const float4*)patch_w, (__half2*)wph, (__half2*)wpl, n);
        n = DEPTH * QKVD * DIMM / 4;
        wsplit_kernel<<<(n + 255) / 256, 256>>>((const float4*)qkv_w, (__half2*)wqh, (__half2*)wql, n);
        n = DEPTH * DIMM * INNERD / 4;
        wsplit_kernel<<<(n + 255) / 256, 256>>>((const float4*)out_w, (__half2*)woh, (__half2*)wol, n);
        n = DEPTH * MLPD * DIMM / 4;
        wsplit_kernel<<<(n + 255) / 256, 256>>>((const float4*)ffn_w1, (__half2*)w1h, (__half2*)w1l, n);
        wsplit_kernel<<<(n + 255) / 256, 256>>>((const float4*)ffn_w2, (__half2*)w2h, (__half2*)w2l, n);
    }

    patch_kernel<<<NROWS, 256>>>(neuralInput, patch_ln1_g, patch_ln1_b, lnh, lnl);

    // patch linear -> fp32 temp (g_qkv), then LN2 -> fp32 residual g_x
    if (use_tc)
        tgemm_tc<64, 0, 2><<<dim3(DIMM / 64, NROWS / 128), 128, SMEM64A2>>>(
            lnh, lnl, wph, wpl, patch_b, nullptr, pqkv, nullptr, nullptr, NROWS, DIMM, DIMM);
    else
        tgemm_lg<0, 0, 0><<<dim3(DIMM / 128, NROWS / 128), 256, LG_SMEM>>>(
            lnh, lnl, wph, wpl, patch_b, nullptr, pqkv, nullptr, nullptr, NROWS, DIMM, DIMM);
    ln_kernel<0><<<NROWS / 8, 256>>>(pqkv, px, nullptr, patch_ln2_g, patch_ln2_b);

    for (int l = 0; l < DEPTH; l++) {
        // attention block
        ln_kernel<1><<<NROWS / 8, 256>>>(px, lnh, lnl, attn_ln_g + l * DIMM, attn_ln_b + l * DIMM);
        if (use_tc)
            tgemm_tcw<0><<<dim3(QKVD / 256, NROWS / 128), 128, SMEMW>>>(
                lnh, lnl, wqh + (size_t)l * QKVD * DIMM, wql + (size_t)l * QKVD * DIMM,
                nullptr, nullptr, pqkv, nullptr, nullptr, NROWS, QKVD, DIMM);
        else
            tgemm_lg<0, 0, 0><<<dim3(QKVD / 128, NROWS / 128), 256, LG_SMEM>>>(
                lnh, lnl, wqh + (size_t)l * QKVD * DIMM, wql + (size_t)l * QKVD * DIMM,
                nullptr, nullptr, pqkv, nullptr, nullptr, NROWS, QKVD, DIMM);
        attn_kernel<<<dim3(NPATCH / 128, HEADS, BATCH), 128>>>(
            pqkv, rel_tab + (size_t)l * RELN, aoh, aol);
        if (use_tc)
            tgemm_tc<64, 1, 1><<<dim3(DIMM / 64, NROWS / 128), 128, SMEM64A1>>>(
                aoh, nullptr, woh + (size_t)l * DIMM * INNERD, wol + (size_t)l * DIMM * INNERD,
                out_b + (size_t)l * DIMM, px, px, nullptr, nullptr, NROWS, DIMM, INNERD);
        else
            tgemm_lg<0, 1, 0><<<dim3(DIMM / 128, NROWS / 128), 256, LG_SMEM>>>(
                aoh, aol, woh + (size_t)l * DIMM * INNERD, wol + (size_t)l * DIMM * INNERD,
                out_b + (size_t)l * DIMM, px, px, nullptr, nullptr, NROWS, DIMM, INNERD);
        // ffn block
        ln_kernel<1><<<NROWS / 8, 256>>>(px, lnh, lnl, ffn_ln_g + l * DIMM, ffn_ln_b + l * DIMM);
        if (use_tc)
            tgemm_tcw<2><<<dim3(MLPD / 256, NROWS / 128), 128, SMEMW>>>(
                lnh, lnl, w1h + (size_t)l * MLPD * DIMM, w1l + (size_t)l * MLPD * DIMM,
                ffn_b1 + (size_t)l * MLPD, nullptr, nullptr, fh, nullptr, NROWS, MLPD, DIMM);
        else
            tgemm_lg<1, 0, 1><<<dim3(MLPD / 128, NROWS / 128), 256, LG_SMEM>>>(
                lnh, lnl, w1h + (size_t)l * MLPD * DIMM, w1l + (size_t)l * MLPD * DIMM,
                ffn_b1 + (size_t)l * MLPD, nullptr, nullptr, fh, fl, NROWS, MLPD, DIMM);
        if (use_tc)
            tgemm_tc<64, 1, 1><<<dim3(DIMM / 64, NROWS / 128), 128, SMEM64A1>>>(
                fh, nullptr, w2h + (size_t)l * DIMM * MLPD, w2l + (size_t)l * DIMM * MLPD,
                ffn_b2 + (size_t)l * DIMM, px, px, nullptr, nullptr, NROWS, DIMM, MLPD);
        else
            tgemm_lg<0, 1, 0><<<dim3(DIMM / 128, NROWS / 128), 256, LG_SMEM>>>(
                fh, fl, w2h + (size_t)l * DIMM * MLPD, w2l + (size_t)l * DIMM * MLPD,
                ffn_b2 + (size_t)l * DIMM, px, px, nullptr, nullptr, NROWS, DIMM, MLPD);
    }

    // final LN (fp32 into g_qkv) + projection
    ln_kernel<0><<<NROWS / 8, 256>>>(px, pqkv, nullptr, final_ln_g, final_ln_b);
    proj_kernel<<<NROWS, 256>>>(pqkv, proj_w, proj_b, (float*)d_out);
}

// round 17
// speedup vs baseline: 1.2934x; 1.0512x over previous
#include <cuda_runtime.h>
#include <cuda_fp16.h>
#include <math.h>
#include <stdint.h>

// ---------------- problem constants ----------------
#define BATCH   4
#define TLEN    2048
#define PW      256
#define P1      4
#define NPATCH  512          // TLEN/P1
#define NROWS   2048         // BATCH*NPATCH
#define DIMM    1024
#define HEADS   16
#define DH      64
#define INNERD  1024         // HEADS*DH
#define QKVD    3072
#define MLPD    4096
#define DEPTH   12
#define NCLS    41           // NCLS+1
#define RELN    399          // 2*MAXREL-1

// arch-feature gate: tcgen05 only exists on sm_100a/sm_103a-class targets
#if defined(__CUDA_ARCH_FEAT_SM103_ALL) || defined(__CUDA_ARCH_FEAT_SM100_ALL) || defined(__CUDA_ARCH_FEAT_SM101_ALL)
#define HAS_TC 1
#else
#define HAS_TC 0
#endif

// ---------------- scratch (device globals; allocation-free) ----------------
__device__ float g_x  [(size_t)NROWS*DIMM];     // fp32 residual stream
__device__ float g_qkv[(size_t)NROWS*QKVD];     // fp32 qkv + generic fp32 temp

// activation hi/lo fp16 planes
__device__ __half g_lnh[(size_t)NROWS*DIMM];
__device__ __half g_lnl[(size_t)NROWS*DIMM];
__device__ __half g_aoh[(size_t)NROWS*DIMM];
__device__ __half g_aol[(size_t)NROWS*DIMM];
__device__ __half g_fh [(size_t)NROWS*MLPD];
__device__ __half g_fl [(size_t)NROWS*MLPD];

// weight hi/lo fp16 planes
__device__ __half g_wph[(size_t)DIMM*DIMM];
__device__ __half g_wpl[(size_t)DIMM*DIMM];
__device__ __half g_wqh[(size_t)DEPTH*QKVD*DIMM];
__device__ __half g_wql[(size_t)DEPTH*QKVD*DIMM];
__device__ __half g_woh[(size_t)DEPTH*DIMM*INNERD];
__device__ __half g_wol[(size_t)DEPTH*DIMM*INNERD];
__device__ __half g_w1h[(size_t)DEPTH*MLPD*DIMM];
__device__ __half g_w1l[(size_t)DEPTH*MLPD*DIMM];
__device__ __half g_w2h[(size_t)DEPTH*DIMM*MLPD];
__device__ __half g_w2l[(size_t)DEPTH*DIMM*MLPD];

// ---------------- generic helpers ----------------
__device__ __forceinline__ void hsplit(float x, __half& h, __half& l) {
    h = __float2half_rn(x);
    l = __float2half_rn(x - __half2float(h));
}

__device__ __forceinline__ float gelu_exact(float x) {
    return 0.5f * x * (1.f + erff(x * 0.70710678118654752f));
}

__device__ __forceinline__ void cp16s(uint32_t s, const void* g) {
    asm volatile("cp.async.cg.shared.global [%0], [%1], 16;\n" :: "r"(s), "l"(g));
}

// packed f32x2 helpers (sm_100+)
__device__ __forceinline__ uint64_t pk2(float lo, float hi) {
    uint64_t d;
    asm("mov.b64 %0, {%1, %2};" : "=l"(d) : "f"(lo), "f"(hi));
    return d;
}
__device__ __forceinline__ void upk2(uint64_t v, float& lo, float& hi) {
    asm("mov.b64 {%0, %1}, %2;" : "=f"(lo), "=f"(hi) : "l"(v));
}
__device__ __forceinline__ uint64_t fma2p(uint64_t a, uint64_t b, uint64_t c) {
    uint64_t d;
    asm("fma.rn.f32x2 %0, %1, %2, %3;" : "=l"(d) : "l"(a), "l"(b), "l"(c));
    return d;
}
__device__ __forceinline__ uint64_t mul2p(uint64_t a, uint64_t b) {
    uint64_t d;
    asm("mul.rn.f32x2 %0, %1, %2;" : "=l"(d) : "l"(a), "l"(b));
    return d;
}
__device__ __forceinline__ void lds2u64(uint32_t a, uint64_t& p0, uint64_t& p1) {
    asm("ld.shared.v2.u64 {%0, %1}, [%2];" : "=l"(p0), "=l"(p1) : "r"(a));
}

// ---------------- arch probe: static smem size differs by feature ----------------
__global__ void probe_kernel(float* out) {
#if HAS_TC
    __shared__ volatile float s[2048];            // 8192 bytes static smem
    s[threadIdx.x] = 1.f;
    __syncthreads();
    if (out) out[0] = s[threadIdx.x ^ 1];
#else
    if (out) out[0] = 0.f;
#endif
}

// ---------------- tcgen05 helpers (guarded) ----------------
__device__ __forceinline__ uint32_t sw128(uint32_t off) {
    return off ^ ((off >> 3) & 0x70);
}
__device__ __forceinline__ uint32_t sw64(uint32_t off) {
    return off ^ ((off >> 3) & 0x30);
}

__device__ __forceinline__ uint64_t sdesc(uint32_t saddr) {        // SW128 K-major
    return (2ull << 61) | (1ull << 46) | (64ull << 32) | (1ull << 16)
         | ((uint64_t)(saddr >> 4) & 0x3FFF);
}
__device__ __forceinline__ uint64_t sdesc64(uint32_t saddr) {      // SW64 K-major
    return (4ull << 61) | (1ull << 46) | (32ull << 32) | (1ull << 16)
         | ((uint64_t)(saddr >> 4) & 0x3FFF);
}

__device__ __forceinline__ void mbar_init(uint32_t a, uint32_t cnt) {
    asm volatile("mbarrier.init.shared.b64 [%0], %1;" :: "r"(a), "r"(cnt) : "memory");
}

__device__ __forceinline__ void mbar_wait(uint32_t a, int phase) {
    asm volatile(
        "{\n\t.reg .pred P;\n"
        "W_%=:\n\t"
        "mbarrier.try_wait.parity.shared.b64 P, [%0], %1;\n\t"
        "@P bra D_%=;\n\t"
        "bra W_%=;\n"
        "D_%=:\n\t}"
        :: "r"(a), "r"(phase) : "memory");
}

__device__ __forceinline__ void tc_alloc(uint32_t slot, uint32_t ncols) {
#if HAS_TC
    asm volatile("tcgen05.alloc.cta_group::1.sync.aligned.shared::cta.b32 [%0], %1;"
                 :: "r"(slot), "r"(ncols) : "memory");
    asm volatile("tcgen05.relinquish_alloc_permit.cta_group::1.sync.aligned;");
#endif
}

__device__ __forceinline__ void tc_dealloc(uint32_t tmem, uint32_t ncols) {
#if HAS_TC
    asm volatile("tcgen05.dealloc.cta_group::1.sync.aligned.b32 %0, %1;"
                 :: "r"(tmem), "r"(ncols));
#endif
}

__device__ __forceinline__ void tc_mma_f16_ss(uint32_t d, uint64_t a_desc, uint64_t b_desc,
                                              uint32_t idesc, uint32_t en) {
#if HAS_TC
    asm volatile(
        "{\n\t.reg .pred p;\n\t"
        "setp.ne.u32 p, %5, 0;\n\t"
        "tcgen05.mma.cta_group::1.kind::f16 [%0], %1, %2, %3, {%4, %4, %4, %4}, p;\n\t}"
        :: "r"(d), "l"(a_desc), "l"(b_desc), "r"(idesc), "r"(0u), "r"(en) : "memory");
#endif
}

__device__ __forceinline__ void tc_commit(uint32_t mbar) {
#if HAS_TC
    asm volatile("tcgen05.commit.cta_group::1.mbarrier::arrive::one.shared::cluster.b64 [%0];"
                 :: "r"(mbar) : "memory");
#endif
}

__device__ __forceinline__ void tmem_ld32(uint32_t* r, uint32_t a) {
#if HAS_TC
    asm volatile(
        "tcgen05.ld.sync.aligned.32x32b.x32.b32 "
        "{%0, %1, %2, %3, %4, %5, %6, %7, "
        " %8, %9, %10, %11, %12, %13, %14, %15, "
        " %16, %17, %18, %19, %20, %21, %22, %23, "
        " %24, %25, %26, %27, %28, %29, %30, %31}, [%32];"
        : "=r"(r[0]),  "=r"(r[1]),  "=r"(r[2]),  "=r"(r[3]),
          "=r"(r[4]),  "=r"(r[5]),  "=r"(r[6]),  "=r"(r[7]),
          "=r"(r[8]),  "=r"(r[9]),  "=r"(r[10]), "=r"(r[11]),
          "=r"(r[12]), "=r"(r[13]), "=r"(r[14]), "=r"(r[15]),
          "=r"(r[16]), "=r"(r[17]), "=r"(r[18]), "=r"(r[19]),
          "=r"(r[20]), "=r"(r[21]), "=r"(r[22]), "=r"(r[23]),
          "=r"(r[24]), "=r"(r[25]), "=r"(r[26]), "=r"(r[27]),
          "=r"(r[28]), "=r"(r[29]), "=r"(r[30]), "=r"(r[31])
        : "r"(a));
#else
    #pragma unroll
    for (int i = 0; i < 32; i++) r[i] = 0;
    (void)a;
#endif
}

// ---------------- weight split pre-pass ----------------
__global__ void wsplit_kernel(const float4* __restrict__ in,
                              __half2* __restrict__ oh, __half2* __restrict__ ol, int n4) {
    int i = blockIdx.x * blockDim.x + threadIdx.x;
    if (i < n4) {
        float4 v = in[i];
        __half h0, l0, h1, l1, h2, l2, h3, l3;
        hsplit(v.x, h0, l0); hsplit(v.y, h1, l1);
        hsplit(v.z, h2, l2); hsplit(v.w, h3, l3);
        oh[2 * i]     = __halves2half2(h0, h1);
        oh[2 * i + 1] = __halves2half2(h2, h3);
        ol[2 * i]     = __halves2half2(l0, l1);
        ol[2 * i + 1] = __halves2half2(l2, l3);
    }
}

// hi-plane only (for single-plane-B GEMM weights on the tc path)
__global__ void wsplit_h_kernel(const float4* __restrict__ in,
                                __half2* __restrict__ oh, int n4) {
    int i = blockIdx.x * blockDim.x + threadIdx.x;
    if (i < n4) {
        float4 v = in[i];
        oh[2 * i]     = __halves2half2(__float2half_rn(v.x), __float2half_rn(v.y));
        oh[2 * i + 1] = __halves2half2(__float2half_rn(v.z), __float2half_rn(v.w));
    }
}

// ---------------- 1) gaussian conv + patchify + LN1 (planes out) ----------------
__device__ __forceinline__ float blockSum256(float v) {
    __shared__ float red[8];
    int lane = threadIdx.x & 31, w = threadIdx.x >> 5;
    __syncthreads();
    #pragma unroll
    for (int o = 16; o; o >>= 1) v += __shfl_down_sync(0xffffffffu, v, o);
    if (!lane) red[w] = v;
    __syncthreads();
    if (w == 0) {
        float r = (lane < 8) ? red[lane] : 0.f;
        #pragma unroll
        for (int o = 4; o; o >>= 1) r += __shfl_down_sync(0xffffffffu, r, o);
        if (!lane) red[0] = r;
    }
    __syncthreads();
    return red[0];
}

__global__ void patch_kernel(const float* __restrict__ in,
                             const float* __restrict__ lg,
                             const float* __restrict__ lb,
                             __half* __restrict__ oh, __half* __restrict__ ol) {
    __shared__ float gk[20];
    if (threadIdx.x == 0) {
        float tmp[20], s = 0.f;
        #pragma unroll
        for (int i = 0; i < 20; i++) {
            float z = ((float)i - 9.5f) * 0.5f;
            tmp[i] = expf(-0.5f * z * z);
            s += tmp[i];
        }
        #pragma unroll
        for (int i = 0; i < 20; i++) gk[i] = tmp[i] / s;
    }
    __syncthreads();

    int row = blockIdx.x;
    int b = row >> 9, n = row & 511;
    int f = threadIdx.x;
    const float* ib = in + (size_t)b * TLEN * PW + f;

    float vals[P1];
    #pragma unroll
    for (int p = 0; p < P1; p++) {
        int t = n * P1 + p;
        float acc = 0.f;
        #pragma unroll
        for (int k = 0; k < 20; k++) {
            int tt = t - 9 + k;
            if (tt >= 0 && tt < TLEN) acc += ib[(size_t)tt * PW] * gk[k];
        }
        vals[p] = acc;
    }
    float s = vals[0] + vals[1] + vals[2] + vals[3];
    float mean = blockSum256(s) * (1.f / 1024.f);
    float sq = 0.f;
    #pragma unroll
    for (int p = 0; p < P1; p++) { float d = vals[p] - mean; sq += d * d; }
    float var = blockSum256(sq) * (1.f / 1024.f);
    float inv = rsqrtf(var + 1e-5f);
    #pragma unroll
    for (int p = 0; p < P1; p++) {
        int e = p * PW + f;
        float o = (vals[p] - mean) * inv * lg[e] + lb[e];
        __half h, l;
        hsplit(o, h, l);
        oh[(size_t)row * DIMM + e] = h;
        ol[(size_t)row * DIMM + e] = l;
    }
}

// ---------------- 2) LayerNorm over D=1024, warp-per-row (8 rows/CTA) ----------------
template <int PACK>
__global__ __launch_bounds__(256)
void ln_kernel(const float* __restrict__ in, void* __restrict__ o1,
               void* __restrict__ o2,
               const float* __restrict__ g, const float* __restrict__ b) {
    int wid = threadIdx.x >> 5, lane = threadIdx.x & 31;
    int row = blockIdx.x * 8 + wid;
    const float* x = in + (size_t)row * DIMM;

    float4 v[8];
    float s = 0.f;
    #pragma unroll
    for (int i = 0; i < 8; i++) {
        v[i] = *(const float4*)(x + lane * 4 + i * 128);
        s += v[i].x + v[i].y + v[i].z + v[i].w;
    }
    #pragma unroll
    for (int o = 16; o; o >>= 1) s += __shfl_xor_sync(0xffffffffu, s, o);
    float mean = s * (1.f / 1024.f);

    float sq = 0.f;
    #pragma unroll
    for (int i = 0; i < 8; i++) {
        v[i].x -= mean; v[i].y -= mean; v[i].z -= mean; v[i].w -= mean;
        sq += v[i].x * v[i].x + v[i].y * v[i].y + v[i].z * v[i].z + v[i].w * v[i].w;
    }
    #pragma unroll
    for (int o = 16; o; o >>= 1) sq += __shfl_xor_sync(0xffffffffu, sq, o);
    float inv = rsqrtf(sq * (1.f / 1024.f) + 1e-5f);

    #pragma unroll
    for (int i = 0; i < 8; i++) {
        int c = lane * 4 + i * 128;
        float4 gv = *(const float4*)(g + c), bv = *(const float4*)(b + c);
        float ox = v[i].x * inv * gv.x + bv.x;
        float oy = v[i].y * inv * gv.y + bv.y;
        float oz = v[i].z * inv * gv.z + bv.z;
        float ow = v[i].w * inv * gv.w + bv.w;
        if (PACK) {
            __half h0, l0, h1, l1, h2, l2, h3, l3;
            hsplit(ox, h0, l0); hsplit(oy, h1, l1);
            hsplit(oz, h2, l2); hsplit(ow, h3, l3);
            size_t idx = ((size_t)row * DIMM + c) >> 1;
            ((__half2*)o1)[idx]     = __halves2half2(h0, h1);
            ((__half2*)o1)[idx + 1] = __halves2half2(h2, h3);
            ((__half2*)o2)[idx]     = __halves2half2(l0, l1);
            ((__half2*)o2)[idx + 1] = __halves2half2(l2, l3);
        } else {
            *(float4*)((float*)o1 + (size_t)row * DIMM + c) = make_float4(ox, oy, oz, ow);
        }
    }
}

// ---------------- 3a) tcgen05 split-FP16 GEMM, narrow (NT=64, K64 chunks, SW128) ----------------
// SA/SB = number of A/B planes (2 = hi/lo split, 1 = hi only).
#define ATILE 16384            // 128 rows * 128 B
template <int NT, int MODE, int SA, int SB>
__global__ __launch_bounds__(128, (SA == 1 && SB == 1) ? 4 : 2)
void tgemm_tc(const __half* __restrict__ Ah, const __half* __restrict__ Al,
              const __half* __restrict__ Bh, const __half* __restrict__ Bl,
              const float* __restrict__ bias, const float* __restrict__ R,
              float* __restrict__ Cf, __half* __restrict__ Ch, __half* __restrict__ Cl,
              int M, int N, int K) {
#if HAS_TC
    constexpr int BTILE = NT * 128;
    constexpr int ABYTES = SA * ATILE;
    constexpr int BBYTES = SB * BTILE;
    constexpr int BUF   = ABYTES + BBYTES;
    constexpr uint32_t IDESC = (1u << 4) | ((NT / 8) << 17) | (8u << 24);
    constexpr uint32_t TCOLS = (NT < 64) ? 64 : NT;

    extern __shared__ __align__(1024) uint8_t smraw[];
    uint32_t sbase = (uint32_t)__cvta_generic_to_shared(smraw);
    uint32_t s0 = (sbase + 1023) & ~1023u;
    uint32_t tmem_slot = s0, mb[2] = { s0 + 8, s0 + 16 };
    uint32_t tiles = s0 + 1024;

    int t = threadIdx.x, wid = t >> 5, lid = t & 31;
    int m0 = blockIdx.y * 128, n0 = blockIdx.x * NT;

    if (wid == 0) tc_alloc(tmem_slot, TCOLS);
    if (t == 0) { mbar_init(mb[0], 1); mbar_init(mb[1], 1); }
    __syncthreads();
    uint32_t tmem;
    asm volatile("ld.shared.b32 %0, [%1];" : "=r"(tmem) : "r"(tmem_slot));

    int T = K >> 6;

    auto fill = [&](int c) {
        int b = c & 1;
        int k0 = c * 64;
        uint32_t bb = tiles + b * BUF;
        #pragma unroll 4
        for (int idx = t; idx < 128 * 8; idx += 128) {
            int row = idx >> 3, u = idx & 7;
            uint32_t soff = sw128(row * 128 + u * 16);
            size_t goff = (size_t)(m0 + row) * K + k0 + u * 8;
            cp16s(bb + soff, Ah + goff);
            if (SA == 2) cp16s(bb + ATILE + soff, Al + goff);
        }
        #pragma unroll 4
        for (int idx = t; idx < NT * 8; idx += 128) {
            int row = idx >> 3, u = idx & 7;
            uint32_t soff = sw128(row * 128 + u * 16);
            size_t goff = (size_t)(n0 + row) * K + k0 + u * 8;
            cp16s(bb + ABYTES + soff, Bh + goff);
            if (SB == 2) cp16s(bb + ABYTES + BTILE + soff, Bl + goff);
        }
        asm volatile("cp.async.commit_group;\n");
    };

    int ph[2] = { 0, 0 };
    fill(0);
    if (T > 1) fill(1);

    for (int c = 0; c < T; c++) {
        int b = c & 1;
        if (c + 1 < T) asm volatile("cp.async.wait_group 1;\n");
        else           asm volatile("cp.async.wait_group 0;\n");
        __syncthreads();

        if (t == 0) {
            asm volatile("fence.proxy.async.shared::cta;" ::: "memory");
            uint32_t bb = tiles + b * BUF;
            uint64_t dAh = sdesc(bb);
            uint64_t dAl = sdesc(bb + ATILE);
            uint64_t dBh = sdesc(bb + ABYTES);
            uint64_t dBl = sdesc(bb + ABYTES + BTILE);
            #pragma unroll
            for (int k = 0; k < 4; k++) {
                uint32_t en0 = (c == 0 && k == 0) ? 0u : 1u;
                if (SA == 2) {
                    tc_mma_f16_ss(tmem, dAl + k * 2, dBh + k * 2, IDESC, en0);
                    tc_mma_f16_ss(tmem, dAh + k * 2, dBl + k * 2, IDESC, 1u);
                    tc_mma_f16_ss(tmem, dAh + k * 2, dBh + k * 2, IDESC, 1u);
                } else if (SB == 2) {
                    tc_mma_f16_ss(tmem, dAh + k * 2, dBl + k * 2, IDESC, en0);
                    tc_mma_f16_ss(tmem, dAh + k * 2, dBh + k * 2, IDESC, 1u);
                } else {
                    tc_mma_f16_ss(tmem, dAh + k * 2, dBh + k * 2, IDESC, en0);
                }
            }
            tc_commit(mb[b]);
        }

        if (c + 2 < T) {
            mbar_wait(mb[b], ph[b]);
            ph[b] ^= 1;
            fill(c + 2);
        }
    }

    {
        int b2 = (T - 2) & 1, b1 = (T - 1) & 1;
        mbar_wait(mb[b2], ph[b2]); ph[b2] ^= 1;
        mbar_wait(mb[b1], ph[b1]); ph[b1] ^= 1;
    }
    asm volatile("tcgen05.fence::after_thread_sync;" ::: "memory");

    int row = m0 + wid * 32 + lid;
    #pragma unroll 1
    for (int cb = 0; cb < NT / 32; cb++) {
        uint32_t r[32];
        tmem_ld32(r, tmem + cb * 32);
        asm volatile("tcgen05.wait::ld.sync.aligned;" ::: "memory");
        int nb = n0 + cb * 32;
        float v[32];
        #pragma unroll
        for (int c = 0; c < 32; c++)
            v[c] = __uint_as_float(r[c]) + (bias ? bias[nb + c] : 0.f);
        if (MODE == 1) {
            #pragma unroll
            for (int c4 = 0; c4 < 32; c4 += 4) {
                float4 rv = *(const float4*)(R + (size_t)row * N + nb + c4);
                v[c4] += rv.x; v[c4 + 1] += rv.y; v[c4 + 2] += rv.z; v[c4 + 3] += rv.w;
            }
        }
        if (MODE <= 1) {
            #pragma unroll
            for (int c4 = 0; c4 < 32; c4 += 4)
                *(float4*)(Cf + (size_t)row * N + nb + c4) =
                    make_float4(v[c4], v[c4 + 1], v[c4 + 2], v[c4 + 3]);
        } else {
            __align__(16) __half hh[32];
            #pragma unroll
            for (int c = 0; c < 32; c++)
                hh[c] = __float2half_rn(gelu_exact(v[c]));
            #pragma unroll
            for (int q = 0; q < 4; q++)
                *(uint4*)(Ch + (size_t)row * N + nb + q * 8) = *(uint4*)&hh[q * 8];
        }
    }

    __syncthreads();
    if (wid == 0) tc_dealloc(tmem, TCOLS);
#endif
}

// ---------------- 3a') tcgen05 wide GEMM: NT=256, K32 chunks, SW64, 2 CTAs/SM ----------------
#define A32   8192             // 128 rows * 64 B per plane
#define B32   16384            // 256 rows * 64 B per plane
#define BUF32 (2 * A32 + 2 * B32)  // 49152
template <int MODE>
__global__ __launch_bounds__(128, 2)
void tgemm_tcw(const __half* __restrict__ Ah, const __half* __restrict__ Al,
               const __half* __restrict__ Bh, const __half* __restrict__ Bl,
               const float* __restrict__ bias, const float* __restrict__ R,
               float* __restrict__ Cf, __half* __restrict__ Ch, __half* __restrict__ Cl,
               int M, int N, int K) {
#if HAS_TC
    constexpr int NT = 256;
    constexpr uint32_t IDESC = (1u << 4) | ((NT / 8) << 17) | (8u << 24);

    extern __shared__ __align__(1024) uint8_t smraw[];
    uint32_t sbase = (uint32_t)__cvta_generic_to_shared(smraw);
    uint32_t s0 = (sbase + 1023) & ~1023u;
    uint32_t tmem_slot = s0, mb[2] = { s0 + 8, s0 + 16 };
    uint32_t tiles = s0 + 1024;

    int t = threadIdx.x, wid = t >> 5, lid = t & 31;
    int m0 = blockIdx.y * 128, n0 = blockIdx.x * NT;

    if (wid == 0) tc_alloc(tmem_slot, 256);
    if (t == 0) { mbar_init(mb[0], 1); mbar_init(mb[1], 1); }
    __syncthreads();
    uint32_t tmem;
    asm volatile("ld.shared.b32 %0, [%1];" : "=r"(tmem) : "r"(tmem_slot));

    int T = K >> 5;                                 // K/32 chunks

    auto fill = [&](int c) {
        int b = c & 1;
        int k0 = c * 32;
        uint32_t bb = tiles + b * BUF32;
        #pragma unroll 4
        for (int idx = t; idx < 128 * 4; idx += 128) {
            int row = idx >> 2, u = idx & 3;
            uint32_t soff = sw64(row * 64 + u * 16);
            size_t goff = (size_t)(m0 + row) * K + k0 + u * 8;
            cp16s(bb + soff, Ah + goff);
            cp16s(bb + A32 + soff, Al + goff);
        }
        #pragma unroll 8
        for (int idx = t; idx < NT * 4; idx += 128) {
            int row = idx >> 2, u = idx & 3;
            uint32_t soff = sw64(row * 64 + u * 16);
            size_t goff = (size_t)(n0 + row) * K + k0 + u * 8;
            cp16s(bb + 2 * A32 + soff, Bh + goff);
            cp16s(bb + 2 * A32 + B32 + soff, Bl + goff);
        }
        asm volatile("cp.async.commit_group;\n");
    };

    int ph[2] = { 0, 0 };
    fill(0);
    if (T > 1) fill(1);

    for (int c = 0; c < T; c++) {
        int b = c & 1;
        if (c + 1 < T) asm volatile("cp.async.wait_group 1;\n");
        else           asm volatile("cp.async.wait_group 0;\n");
        __syncthreads();

        if (t == 0) {
            asm volatile("fence.proxy.async.shared::cta;" ::: "memory");
            uint32_t bb = tiles + b * BUF32;
            uint64_t dAh = sdesc64(bb);
            uint64_t dAl = sdesc64(bb + A32);
            uint64_t dBh = sdesc64(bb + 2 * A32);
            uint64_t dBl = sdesc64(bb + 2 * A32 + B32);
            #pragma unroll
            for (int k = 0; k < 2; k++) {
                uint32_t en0 = (c == 0 && k == 0) ? 0u : 1u;
                tc_mma_f16_ss(tmem, dAl + k * 2, dBh + k * 2, IDESC, en0);
                tc_mma_f16_ss(tmem, dAh + k * 2, dBl + k * 2, IDESC, 1u);
                tc_mma_f16_ss(tmem, dAh + k * 2, dBh + k * 2, IDESC, 1u);
            }
            tc_commit(mb[b]);
        }

        if (c + 2 < T) {
            mbar_wait(mb[b], ph[b]);
            ph[b] ^= 1;
            fill(c + 2);
        }
    }

    {
        int b2 = (T - 2) & 1, b1 = (T - 1) & 1;
        mbar_wait(mb[b2], ph[b2]); ph[b2] ^= 1;
        mbar_wait(mb[b1], ph[b1]); ph[b1] ^= 1;
    }
    asm volatile("tcgen05.fence::after_thread_sync;" ::: "memory");

    int row = m0 + wid * 32 + lid;
    #pragma unroll 1
    for (int cb = 0; cb < NT / 32; cb++) {
        uint32_t r[32];
        tmem_ld32(r, tmem + cb * 32);
        asm volatile("tcgen05.wait::ld.sync.aligned;" ::: "memory");
        int nb = n0 + cb * 32;
        float v[32];
        #pragma unroll
        for (int c = 0; c < 32; c++)
            v[c] = __uint_as_float(r[c]) + (bias ? bias[nb + c] : 0.f);
        if (MODE <= 1) {
            #pragma unroll
            for (int c4 = 0; c4 < 32; c4 += 4)
                *(float4*)(Cf + (size_t)row * N + nb + c4) =
                    make_float4(v[c4], v[c4 + 1], v[c4 + 2], v[c4 + 3]);
        } else {
            __align__(16) __half hh[32];
            #pragma unroll
            for (int c = 0; c < 32; c++)
                hh[c] = __float2half_rn(gelu_exact(v[c]));
            #pragma unroll
            for (int q = 0; q < 4; q++)
                *(uint4*)(Ch + (size_t)row * N + nb + q * 8) = *(uint4*)&hh[q * 8];
        }
    }

    __syncthreads();
    if (wid == 0) tc_dealloc(tmem, 256);
#endif
}

// ---------------- 3b) legacy mma.sync split-FP16 GEMM (fallback) ----------------
__device__ __forceinline__ void mma_f16(float* c, const uint32_t* a, const uint32_t* b) {
    asm volatile(
        "mma.sync.aligned.m16n8k16.row.col.f32.f16.f16.f32 "
        "{%0,%1,%2,%3}, {%4,%5,%6,%7}, {%8,%9}, {%0,%1,%2,%3};"
        : "+f"(c[0]), "+f"(c[1]), "+f"(c[2]), "+f"(c[3])
        : "r"(a[0]), "r"(a[1]), "r"(a[2]), "r"(a[3]), "r"(b[0]), "r"(b[1]));
}

#define LG_PLANE 5120
#define LG_STAGE (4 * LG_PLANE)
#define LG_SMEM  (2 * LG_STAGE * 2)

template <int GELU, int RES, int PACK>
__global__ __launch_bounds__(256)
void tgemm_lg(const __half* __restrict__ Ah, const __half* __restrict__ Al,
              const __half* __restrict__ Bh, const __half* __restrict__ Bl,
              const float* __restrict__ bias, const float* __restrict__ R,
              float* __restrict__ Cf, __half* __restrict__ Ch, __half* __restrict__ Cl,
              int M, int N, int K) {
    extern __shared__ __half smh[];
    uint32_t sbase_u = (uint32_t)__cvta_generic_to_shared(smh);
    int m0 = blockIdx.y * 128, n0 = blockIdx.x * 128;
    int t = threadIdx.x, lane = t & 31, wid = t >> 5;
    int g = lane >> 2, tig = lane & 3;
    int warp_m = wid & 1, warp_n = wid >> 1;

    float acc[4][4][4];
    #pragma unroll
    for (int i = 0; i < 4; i++)
        #pragma unroll
        for (int j = 0; j < 4; j++)
            #pragma unroll
            for (int r = 0; r < 4; r++) acc[i][j][r] = 0.f;

    int T = K >> 5;
    const __half* gsrc[4] = { Ah, Al, Bh, Bl };

    auto fill = [&](int tt) {
        int st = tt & 1;
        int k0 = tt * 32;
        #pragma unroll
        for (int pl = 0; pl < 4; pl++) {
            int rbase = (pl < 2) ? m0 : n0;
            uint32_t dst = sbase_u + (uint32_t)(st * LG_STAGE + pl * LG_PLANE) * 2;
            const __half* src = gsrc[pl] + (size_t)rbase * K + k0;
            #pragma unroll
            for (int q = 0; q < 2; q++) {
                int cidx = t + 256 * q;
                int row = cidx >> 2, seg = cidx & 3;
                cp16s(dst + (uint32_t)(row * 40 + seg * 8) * 2,
                      src + (size_t)row * K + seg * 8);
            }
        }
        asm volatile("cp.async.commit_group;\n");
    };

    fill(0);
    for (int tt = 0; tt < T; tt++) {
        if (tt + 1 < T) { fill(tt + 1); asm volatile("cp.async.wait_group 1;\n"); }
        else            { asm volatile("cp.async.wait_group 0;\n"); }
        __syncthreads();

        const uint32_t* S   = (const uint32_t*)smh + (tt & 1) * (LG_STAGE / 2);
        const uint32_t* SAh = S;
        const uint32_t* SAl = S + LG_PLANE / 2;
        const uint32_t* SWh = S + LG_PLANE;
        const uint32_t* SWl = S + 3 * (LG_PLANE / 2);
        int am = warp_m * 64, bn = warp_n * 32;

        #pragma unroll
        for (int ks = 0; ks < 2; ks++) {
            int kw = ks * 8 + tig;
            uint32_t ah[4][4], al[4][4], bh[4][2], bl[4][2];
            #pragma unroll
            for (int i = 0; i < 4; i++) {
                int r = am + i * 16 + g;
                ah[i][0] = SAh[r * 20 + kw];       ah[i][1] = SAh[(r + 8) * 20 + kw];
                ah[i][2] = SAh[r * 20 + kw + 4];   ah[i][3] = SAh[(r + 8) * 20 + kw + 4];
                al[i][0] = SAl[r * 20 + kw];       al[i][1] = SAl[(r + 8) * 20 + kw];
                al[i][2] = SAl[r * 20 + kw + 4];   al[i][3] = SAl[(r + 8) * 20 + kw + 4];
            }
            #pragma unroll
            for (int j = 0; j < 4; j++) {
                int c = bn + j * 8 + g;
                bh[j][0] = SWh[c * 20 + kw];  bh[j][1] = SWh[c * 20 + kw + 4];
                bl[j][0] = SWl[c * 20 + kw];  bl[j][1] = SWl[c * 20 + kw + 4];
            }
            #pragma unroll
            for (int i = 0; i < 4; i++)
                #pragma unroll
                for (int j = 0; j < 4; j++) {
                    mma_f16(acc[i][j], al[i], bh[j]);
                    mma_f16(acc[i][j], ah[i], bl[j]);
                    mma_f16(acc[i][j], ah[i], bh[j]);
                }
        }
        __syncthreads();
    }

    int m_base = m0 + warp_m * 64;
    int n_base = n0 + warp_n * 32;
    #pragma unroll
    for (int i = 0; i < 4; i++) {
        int r0 = m_base + i * 16 + g;
        int r1 = r0 + 8;
        #pragma unroll
        for (int j = 0; j < 4; j++) {
            int cc = n_base + j * 8 + tig * 2;
            float b0 = bias ? bias[cc] : 0.f;
            float b1 = bias ? bias[cc + 1] : 0.f;
            float v00 = acc[i][j][0] + b0, v01 = acc[i][j][1] + b1;
            float v10 = acc[i][j][2] + b0, v11 = acc[i][j][3] + b1;
            if (GELU) {
                v00 = gelu_exact(v00); v01 = gelu_exact(v01);
                v10 = gelu_exact(v10); v11 = gelu_exact(v11);
            }
            if (RES) {
                const float2 rv0 = *(const float2*)(R + (size_t)r0 * N + cc);
                const float2 rv1 = *(const float2*)(R + (size_t)r1 * N + cc);
                v00 += rv0.x; v01 += rv0.y; v10 += rv1.x; v11 += rv1.y;
            }
            if (PACK) {
                __half h00, l00, h01, l01, h10, l10, h11, l11;
                hsplit(v00, h00, l00); hsplit(v01, h01, l01);
                hsplit(v10, h10, l10); hsplit(v11, h11, l11);
                *(__half2*)(Ch + (size_t)r0 * N + cc) = __halves2half2(h00, h01);
                *(__half2*)(Ch + (size_t)r1 * N + cc) = __halves2half2(h10, h11);
                *(__half2*)(Cl + (size_t)r0 * N + cc) = __halves2half2(l00, l01);
                *(__half2*)(Cl + (size_t)r1 * N + cc) = __halves2half2(l10, l11);
            } else {
                *(float2*)(Cf + (size_t)r0 * N + cc) = make_float2(v00, v01);
                *(float2*)(Cf + (size_t)r1 * N + cc) = make_float2(v10, v11);
            }
        }
    }
}

// ---------------- 4) fused causal attention (flash-style, f32x2 math) ----------------
__global__ __launch_bounds__(128)
void attn_kernel(const float* __restrict__ qkv, const float* __restrict__ rel,
                 __half* __restrict__ oh, __half* __restrict__ ol) {
    __shared__ __align__(16) float ks[32][64];
    __shared__ __align__(16) float vs[32][64];
    __shared__ float relsm[RELN];

    int qt = blockIdx.x, h = blockIdx.y, b = blockIdx.z;
    int i_glob = qt * 128 + threadIdx.x;
    const float* base = qkv + (size_t)b * NPATCH * QKVD;

    uint32_t ks_base = (uint32_t)__cvta_generic_to_shared(ks);
    uint32_t vs_base = (uint32_t)__cvta_generic_to_shared(vs);

    for (int r = threadIdx.x; r < RELN; r += 128) relsm[r] = rel[r];

    uint64_t q2[32];
    {
        const float* qp = base + (size_t)i_glob * QKVD + h * DH;
        #pragma unroll
        for (int d = 0; d < 16; d++) {
            float4 t4 = *(const float4*)(qp + 4 * d);
            q2[2 * d]     = pk2(t4.x, t4.y);
            q2[2 * d + 1] = pk2(t4.z, t4.w);
        }
    }

    uint64_t O2[32];
    #pragma unroll
    for (int d = 0; d < 32; d++) O2[d] = 0ull;
    float mrun = -1e30f, lsum = 0.f;

    int jmax = qt * 128 + 128;
    for (int j0 = 0; j0 < jmax; j0 += 32) {
        __syncthreads();
        #pragma unroll
        for (int i = 0; i < 4; i++) {
            int f = threadIdx.x + 128 * i;
            int jr = f >> 4, dc = (f & 15) * 4;
            const float* kp = base + (size_t)(j0 + jr) * QKVD + INNERD + h * DH + dc;
            const float* vp = base + (size_t)(j0 + jr) * QKVD + 2 * INNERD + h * DH + dc;
            *(float4*)&ks[jr][dc] = *(const float4*)kp;
            *(float4*)&vs[jr][dc] = *(const float4*)vp;
        }
        __syncthreads();

        if (j0 <= i_glob) {
            float s[32];
            #pragma unroll
            for (int j = 0; j < 32; j++) {
                uint64_t acc2 = 0ull;
                uint32_t a = ks_base + j * 256;
                #pragma unroll
                for (int d = 0; d < 16; d++) {
                    uint64_t p0, p1;
                    lds2u64(a + d * 16, p0, p1);
                    acc2 = fma2p(q2[2 * d], p0, acc2);
                    acc2 = fma2p(q2[2 * d + 1], p1, acc2);
                }
                float lo, hi;
                upk2(acc2, lo, hi);
                float sc = lo + hi;
                int delta = i_glob - (j0 + j);
                if (delta < 0) s[j] = -1e30f;
                else           s[j] = sc * 0.125f + relsm[min(delta, 199) + 199];
            }
            float mnew = mrun;
            #pragma unroll
            for (int j = 0; j < 32; j++) mnew = fmaxf(mnew, s[j]);
            float corr = expf(mrun - mnew);
            lsum *= corr;
            uint64_t corr2 = pk2(corr, corr);
            #pragma unroll
            for (int d = 0; d < 32; d++) O2[d] = mul2p(O2[d], corr2);
            #pragma unroll
            for (int j = 0; j < 32; j++) {
                float p = expf(s[j] - mnew);
                lsum += p;
                uint64_t pp = pk2(p, p);
                uint32_t a = vs_base + j * 256;
                #pragma unroll
                for (int d = 0; d < 16; d++) {
                    uint64_t p0, p1;
                    lds2u64(a + d * 16, p0, p1);
                    O2[2 * d]     = fma2p(pp, p0, O2[2 * d]);
                    O2[2 * d + 1] = fma2p(pp, p1, O2[2 * d + 1]);
                }
            }
            mrun = mnew;
        }
    }

    float inv = 1.f / lsum;
    size_t obase = ((size_t)b * NPATCH + i_glob) * DIMM + h * DH;
    #pragma unroll
    for (int d = 0; d < 32; d++) {
        float lo, hi;
        upk2(O2[d], lo, hi);
        float a0 = lo * inv, a1 = hi * inv;
        __half h0, l0, h1, l1;
        hsplit(a0, h0, l0); hsplit(a1, h1, l1);
        *(__half2*)(oh + obase + 2 * d) = __halves2half2(h0, h1);
        *(__half2*)(ol + obase + 2 * d) = __halves2half2(l0, l1);
    }
}

// ---------------- 5) projection head ----------------
__global__ void proj_kernel(const float* __restrict__ x, const float* __restrict__ W,
                            const float* __restrict__ bias, float* __restrict__ out) {
    __shared__ float xs[DIMM];
    int row = blockIdx.x;
    const float* xr = x + (size_t)row * DIMM;
    for (int c = threadIdx.x * 4; c < DIMM; c += 1024)
        *(float4*)&xs[c] = *(const float4*)(xr + c);
    __syncthreads();
    int w = threadIdx.x >> 5, lane = threadIdx.x & 31;
    for (int o = w; o < NCLS; o += 8) {
        const float* wr = W + (size_t)o * DIMM;
        float acc = 0.f;
        for (int d = lane * 4; d < DIMM; d += 128) {
            float4 xv = *(const float4*)&xs[d];
            float4 wv = *(const float4*)(wr + d);
            acc += xv.x * wv.x + xv.y * wv.y + xv.z * wv.z + xv.w * wv.w;
        }
        #pragma unroll
        for (int off = 16; off; off >>= 1) acc += __shfl_down_sync(0xffffffffu, acc, off);
        if (!lane) out[(size_t)row * NCLS + o] = acc + bias[o];
    }
}

// ---------------- launch ----------------
#define SMEM64A2 (2048 + 2 * (2 * ATILE + 2 * 64 * 128))   // 100352
#define SMEM64S1 (2048 + 2 * (1 * ATILE + 1 * 64 * 128))   // 51200 -> 4 CTAs/SM
#define SMEMW    (2048 + 2 * BUF32)                        // 100352

extern "C" void kernel_launch(void* const* d_in, const int* in_sizes, int n_in,
                              void* d_out, int out_size) {
    const float* neuralInput  = (const float*)d_in[0];
    const float* patch_ln1_g  = (const float*)d_in[1];
    const float* patch_ln1_b  = (const float*)d_in[2];
    const float* patch_w      = (const float*)d_in[3];
    const float* patch_b      = (const float*)d_in[4];
    const float* patch_ln2_g  = (const float*)d_in[5];
    const float* patch_ln2_b  = (const float*)d_in[6];
    const float* attn_ln_g    = (const float*)d_in[7];
    const float* attn_ln_b    = (const float*)d_in[8];
    const float* qkv_w        = (const float*)d_in[9];
    const float* out_w        = (const float*)d_in[10];
    const float* out_b        = (const float*)d_in[11];
    const float* rel_tab      = (const float*)d_in[12];
    const float* ffn_ln_g     = (const float*)d_in[13];
    const float* ffn_ln_b     = (const float*)d_in[14];
    const float* ffn_w1       = (const float*)d_in[15];
    const float* ffn_b1       = (const float*)d_in[16];
    const float* ffn_w2       = (const float*)d_in[17];
    const float* ffn_b2       = (const float*)d_in[18];
    const float* final_ln_g   = (const float*)d_in[19];
    const float* final_ln_b   = (const float*)d_in[20];
    const float* proj_w       = (const float*)d_in[21];
    const float* proj_b       = (const float*)d_in[22];

    float *px, *pqkv;
    __half *lnh, *lnl, *aoh, *aol, *fh, *fl;
    __half *wph, *wpl, *wqh, *wql, *woh, *wol, *w1h, *w1l, *w2h, *w2l;
    cudaGetSymbolAddress((void**)&px,   g_x);
    cudaGetSymbolAddress((void**)&pqkv, g_qkv);
    cudaGetSymbolAddress((void**)&lnh,  g_lnh);
    cudaGetSymbolAddress((void**)&lnl,  g_lnl);
    cudaGetSymbolAddress((void**)&aoh,  g_aoh);
    cudaGetSymbolAddress((void**)&aol,  g_aol);
    cudaGetSymbolAddress((void**)&fh,   g_fh);
    cudaGetSymbolAddress((void**)&fl,   g_fl);
    cudaGetSymbolAddress((void**)&wph,  g_wph);
    cudaGetSymbolAddress((void**)&wpl,  g_wpl);
    cudaGetSymbolAddress((void**)&wqh,  g_wqh);
    cudaGetSymbolAddress((void**)&wql,  g_wql);
    cudaGetSymbolAddress((void**)&woh,  g_woh);
    cudaGetSymbolAddress((void**)&wol,  g_wol);
    cudaGetSymbolAddress((void**)&w1h,  g_w1h);
    cudaGetSymbolAddress((void**)&w1l,  g_w1l);
    cudaGetSymbolAddress((void**)&w2h,  g_w2h);
    cudaGetSymbolAddress((void**)&w2l,  g_w2l);

    // Which binary variant got loaded? (static smem of probe differs by arch feature)
    bool use_tc = false;
    {
        cudaFuncAttributes a;
        if (cudaFuncGetAttributes(&a, probe_kernel) == cudaSuccess)
            use_tc = (a.sharedSizeBytes >= 8192);
    }

    if (use_tc) {
        cudaFuncSetAttribute(tgemm_tcw<0>, cudaFuncAttributeMaxDynamicSharedMemorySize, SMEMW);
        cudaFuncSetAttribute(tgemm_tcw<2>, cudaFuncAttributeMaxDynamicSharedMemorySize, SMEMW);
        cudaFuncSetAttribute(tgemm_tc<64, 0, 2, 2>, cudaFuncAttributeMaxDynamicSharedMemorySize, SMEM64A2);
        cudaFuncSetAttribute(tgemm_tc<64, 1, 1, 1>, cudaFuncAttributeMaxDynamicSharedMemorySize, SMEM64S1);
    } else {
        cudaFuncSetAttribute(tgemm_lg<0, 0, 0>, cudaFuncAttributeMaxDynamicSharedMemorySize, LG_SMEM);
        cudaFuncSetAttribute(tgemm_lg<0, 1, 0>, cudaFuncAttributeMaxDynamicSharedMemorySize, LG_SMEM);
        cudaFuncSetAttribute(tgemm_lg<1, 0, 1>, cudaFuncAttributeMaxDynamicSharedMemorySize, LG_SMEM);
    }

    // weight split pre-pass
    {
        int n;
        n = DIMM * DIMM / 4;
        wsplit_kernel<<<(n + 255) / 256, 256>>>((const float4*)patch_w, (__half2*)wph, (__half2*)wpl, n);
        n = DEPTH * QKVD * DIMM / 4;
        wsplit_kernel<<<(n + 255) / 256, 256>>>((const float4*)qkv_w, (__half2*)wqh, (__half2*)wql, n);
        n = DEPTH * DIMM * INNERD / 4;
        if (use_tc)
            wsplit_h_kernel<<<(n + 255) / 256, 256>>>((const float4*)out_w, (__half2*)woh, n);
        else
            wsplit_kernel<<<(n + 255) / 256, 256>>>((const float4*)out_w, (__half2*)woh, (__half2*)wol, n);
        n = DEPTH * MLPD * DIMM / 4;
        wsplit_kernel<<<(n + 255) / 256, 256>>>((const float4*)ffn_w1, (__half2*)w1h, (__half2*)w1l, n);
        if (use_tc)
            wsplit_h_kernel<<<(n + 255) / 256, 256>>>((const float4*)ffn_w2, (__half2*)w2h, n);
        else
            wsplit_kernel<<<(n + 255) / 256, 256>>>((const float4*)ffn_w2, (__half2*)w2h, (__half2*)w2l, n);
    }

    patch_kernel<<<NROWS, 256>>>(neuralInput, patch_ln1_g, patch_ln1_b, lnh, lnl);

    // patch linear -> fp32 temp (g_qkv), then LN2 -> fp32 residual g_x
    if (use_tc)
        tgemm_tc<64, 0, 2, 2><<<dim3(DIMM / 64, NROWS / 128), 128, SMEM64A2>>>(
            lnh, lnl, wph, wpl, patch_b, nullptr, pqkv, nullptr, nullptr, NROWS, DIMM, DIMM);
    else
        tgemm_lg<0, 0, 0><<<dim3(DIMM / 128, NROWS / 128), 256, LG_SMEM>>>(
            lnh, lnl, wph, wpl, patch_b, nullptr, pqkv, nullptr, nullptr, NROWS, DIMM, DIMM);
    ln_kernel<0><<<NROWS / 8, 256>>>(pqkv, px, nullptr, patch_ln2_g, patch_ln2_b);

    for (int l = 0; l < DEPTH; l++) {
        // attention block
        ln_kernel<1><<<NROWS / 8, 256>>>(px, lnh, lnl, attn_ln_g + l * DIMM, attn_ln_b + l * DIMM);
        if (use_tc)
            tgemm_tcw<0><<<dim3(QKVD / 256, NROWS / 128), 128, SMEMW>>>(
                lnh, lnl, wqh + (size_t)l * QKVD * DIMM, wql + (size_t)l * QKVD * DIMM,
                nullptr, nullptr, pqkv, nullptr, nullptr, NROWS, QKVD, DIMM);
        else
            tgemm_lg<0, 0, 0><<<dim3(QKVD / 128, NROWS / 128), 256, LG_SMEM>>>(
                lnh, lnl, wqh + (size_t)l * QKVD * DIMM, wql + (size_t)l * QKVD * DIMM,
                nullptr, nullptr, pqkv, nullptr, nullptr, NROWS, QKVD, DIMM);
        attn_kernel<<<dim3(NPATCH / 128, HEADS, BATCH), 128>>>(
            pqkv, rel_tab + (size_t)l * RELN, aoh, aol);
        if (use_tc)
            tgemm_tc<64, 1, 1, 1><<<dim3(DIMM / 64, NROWS / 128), 128, SMEM64S1>>>(
                aoh, nullptr, woh + (size_t)l * DIMM * INNERD, nullptr,
                out_b + (size_t)l * DIMM, px, px, nullptr, nullptr, NROWS, DIMM, INNERD);
        else
            tgemm_lg<0, 1, 0><<<dim3(DIMM / 128, NROWS / 128), 256, LG_SMEM>>>(
                aoh, aol, woh + (size_t)l * DIMM * INNERD, wol + (size_t)l * DIMM * INNERD,
                out_b + (size_t)l * DIMM, px, px, nullptr, nullptr, NROWS, DIMM, INNERD);
        // ffn block
        ln_kernel<1><<<NROWS / 8, 256>>>(px, lnh, lnl, ffn_ln_g + l * DIMM, ffn_ln_b + l * DIMM);
        if (use_tc)
            tgemm_tcw<2><<<dim3(MLPD / 256, NROWS / 128), 128, SMEMW>>>(
                lnh, lnl, w1h + (size_t)l * MLPD * DIMM, w1l + (size_t)l * MLPD * DIMM,
                ffn_b1 + (size_t)l * MLPD, nullptr, nullptr, fh, nullptr, NROWS, MLPD, DIMM);
        else
            tgemm_lg<1, 0, 1><<<dim3(MLPD / 128, NROWS / 128), 256, LG_SMEM>>>(
                lnh, lnl, w1h + (size_t)l * MLPD * DIMM, w1l + (size_t)l * MLPD * DIMM,
                ffn_b1 + (size_t)l * MLPD, nullptr, nullptr, fh, fl, NROWS, MLPD, DIMM);
        if (use_tc)
            tgemm_tc<64, 1, 1, 1><<<dim3(DIMM / 64, NROWS / 128), 128, SMEM64S1>>>(
                fh, nullptr, w2h + (size_t)l * DIMM * MLPD, nullptr,
                ffn_b2 + (size_t)l * DIMM, px, px, nullptr, nullptr, NROWS, DIMM, MLPD);
        else
            tgemm_lg<0, 1, 0><<<dim3(DIMM / 128, NROWS / 128), 256, LG_SMEM>>>(
                fh, fl, w2h + (size_t)l * DIMM * MLPD, w2l + (size_t)l * DIMM * MLPD,
                ffn_b2 + (size_t)l * DIMM, px, px, nullptr, nullptr, NROWS, DIMM, MLPD);
    }

    // final LN (fp32 into g_qkv) + projection
    ln_kernel<0><<<NROWS / 8, 256>>>(px, pqkv, nullptr, final_ln_g, final_ln_b);
    proj_kernel<<<NROWS, 256>>>(pqkv, proj_w, proj_b, (float*)d_out);
}